// round 1
// baseline (speedup 1.0000x reference)
#include <cuda_runtime.h>
#include <math.h>

// ---------------------------------------------------------------------------
// Problem constants
//   q   : (64, 128, 512)    -> A1 (8192 x 512)
//   kv  : (64, 512, 256)    -> A2 (32768 x 256)
//   Wq  : (512, 1024)
//   Wkv : (256, 2048)        k = cols [0,1024), v = cols [1024,2048)
//   Wo  : (1024, 512)
//   bo  : (512)
//   out : (64, 128, 512)
// ---------------------------------------------------------------------------

#define B_ASSETS 64
#define I_LAT    128
#define J_WIN    512
#define QD       512
#define KVD      256
#define HID      1024
#define NH       16
#define HD       64

// Scratch (no cudaMalloc allowed)
__device__ float g_query [8192u * 1024u];            // 32 MB
__device__ float g_kvproj[32768u * 2048u];           // 256 MB
__device__ float g_attn  [8192u * 1024u];            // 32 MB

// ---------------------------------------------------------------------------
// Tiled FP32 SGEMM: C = A(MxK) * B(KxN) (+bias), row-major, all dims
// divisible by tile sizes. 128x128 block tile, BK=16, 8x8 per thread,
// 256 threads.
// ---------------------------------------------------------------------------
#define BM 128
#define BN 128
#define BK 16
#define TM 8
#define TN 8

__global__ __launch_bounds__(256) void sgemm_kernel(
    const float* __restrict__ A, const float* __restrict__ B,
    float* __restrict__ C, int M, int N, int K,
    const float* __restrict__ bias)
{
    __shared__ float As[BK][BM];
    __shared__ float Bs[BK][BN];

    const int tid  = threadIdx.x;
    const int row0 = blockIdx.y * BM;
    const int col0 = blockIdx.x * BN;
    const int tx = tid & 15;   // column group
    const int ty = tid >> 4;   // row group

    float acc[TM][TN];
    #pragma unroll
    for (int i = 0; i < TM; i++)
        #pragma unroll
        for (int j = 0; j < TN; j++) acc[i][j] = 0.f;

    for (int k0 = 0; k0 < K; k0 += BK) {
        // ---- load A tile (128 x 16) transposed into As[k][m] ----
        #pragma unroll
        for (int it = 0; it < 2; it++) {
            int idx = tid + it * 256;          // 0..511 float4 slots
            int r   = idx >> 2;                // 0..127
            int c4  = idx & 3;                 // float4 within the 16-col row
            float4 a = *reinterpret_cast<const float4*>(
                A + (size_t)(row0 + r) * K + k0 + c4 * 4);
            As[c4 * 4 + 0][r] = a.x;
            As[c4 * 4 + 1][r] = a.y;
            As[c4 * 4 + 2][r] = a.z;
            As[c4 * 4 + 3][r] = a.w;
        }
        // ---- load B tile (16 x 128) ----
        #pragma unroll
        for (int it = 0; it < 2; it++) {
            int idx = tid + it * 256;          // 0..511 float4 slots
            int r   = idx >> 5;                // 0..15
            int c4  = idx & 31;                // 0..31
            float4 bv = *reinterpret_cast<const float4*>(
                B + (size_t)(k0 + r) * N + col0 + c4 * 4);
            *reinterpret_cast<float4*>(&Bs[r][c4 * 4]) = bv;
        }
        __syncthreads();

        #pragma unroll
        for (int k = 0; k < BK; k++) {
            float av[TM], bv[TN];
            #pragma unroll
            for (int i = 0; i < TM; i++) av[i] = As[k][ty * TM + i];
            #pragma unroll
            for (int j = 0; j < TN; j++) bv[j] = Bs[k][tx * TN + j];
            #pragma unroll
            for (int i = 0; i < TM; i++)
                #pragma unroll
                for (int j = 0; j < TN; j++)
                    acc[i][j] = fmaf(av[i], bv[j], acc[i][j]);
        }
        __syncthreads();
    }

    // ---- write back ----
    #pragma unroll
    for (int i = 0; i < TM; i++) {
        int r = row0 + ty * TM + i;
        #pragma unroll
        for (int j = 0; j < TN; j += 4) {
            int c = col0 + tx * TN + j;
            float4 v;
            v.x = acc[i][j + 0];
            v.y = acc[i][j + 1];
            v.z = acc[i][j + 2];
            v.w = acc[i][j + 3];
            if (bias != nullptr) {
                v.x += bias[c + 0];
                v.y += bias[c + 1];
                v.z += bias[c + 2];
                v.w += bias[c + 3];
            }
            *reinterpret_cast<float4*>(C + (size_t)r * N + c) = v;
        }
    }
}

// ---------------------------------------------------------------------------
// Fused attention: one CTA per (b, h). 128 threads; thread i owns query
// row i. Online (flash) softmax over J=512 in 8 tiles of 64. K/V rows are
// staged in shared as float4; inner-loop reads are warp-broadcasts.
// ---------------------------------------------------------------------------
__global__ __launch_bounds__(128) void attn_kernel(
    const float* __restrict__ query,    // (8192, 1024)
    const float* __restrict__ kvproj,   // (32768, 2048)
    float* __restrict__ out)            // (8192, 1024)
{
    const int b = blockIdx.x >> 4;
    const int h = blockIdx.x & 15;
    const int i = threadIdx.x;
    const float scale = 0.125f;  // 1/sqrt(64)

    __shared__ float4 Ks[64][16];
    __shared__ float4 Vs[64][16];

    // load this thread's q row (64 floats)
    float4 qv[16];
    const float4* qrow = reinterpret_cast<const float4*>(
        query + (size_t)(b * I_LAT + i) * HID + h * HD);
    #pragma unroll
    for (int d = 0; d < 16; d++) qv[d] = qrow[d];

    float acc[HD];
    #pragma unroll
    for (int d = 0; d < HD; d++) acc[d] = 0.f;
    float m = -INFINITY, l = 0.f;

    for (int jt = 0; jt < J_WIN / 64; jt++) {
        __syncthreads();
        // stage 64 K rows + 64 V rows (each 16 float4)
        for (int t = threadIdx.x; t < 64 * 16; t += 128) {
            int r = t >> 4, c = t & 15;
            size_t rowbase = (size_t)(b * J_WIN + jt * 64 + r) * 2048;
            Ks[r][c] = reinterpret_cast<const float4*>(
                kvproj + rowbase + h * HD)[c];
            Vs[r][c] = reinterpret_cast<const float4*>(
                kvproj + rowbase + HID + h * HD)[c];
        }
        __syncthreads();

        #pragma unroll 4
        for (int j = 0; j < 64; j++) {
            float s = 0.f;
            #pragma unroll
            for (int d = 0; d < 16; d++) {
                float4 k4 = Ks[j][d];
                s = fmaf(qv[d].x, k4.x, s);
                s = fmaf(qv[d].y, k4.y, s);
                s = fmaf(qv[d].z, k4.z, s);
                s = fmaf(qv[d].w, k4.w, s);
            }
            s *= scale;
            float mnew = fmaxf(m, s);
            float f = __expf(m - mnew);   // 0 on first iter (m = -inf)
            float p = __expf(s - mnew);
            m = mnew;
            l = l * f + p;
            #pragma unroll
            for (int d = 0; d < 16; d++) {
                float4 v4 = Vs[j][d];
                acc[4 * d + 0] = fmaf(acc[4 * d + 0], f, p * v4.x);
                acc[4 * d + 1] = fmaf(acc[4 * d + 1], f, p * v4.y);
                acc[4 * d + 2] = fmaf(acc[4 * d + 2], f, p * v4.z);
                acc[4 * d + 3] = fmaf(acc[4 * d + 3], f, p * v4.w);
            }
        }
    }

    const float inv = 1.f / l;
    float* orow = out + (size_t)(b * I_LAT + i) * HID + h * HD;
    #pragma unroll
    for (int d = 0; d < 16; d++) {
        float4 v;
        v.x = acc[4 * d + 0] * inv;
        v.y = acc[4 * d + 1] * inv;
        v.z = acc[4 * d + 2] * inv;
        v.w = acc[4 * d + 3] * inv;
        reinterpret_cast<float4*>(orow)[d] = v;
    }
}

// ---------------------------------------------------------------------------
// Launch
// ---------------------------------------------------------------------------
extern "C" void kernel_launch(void* const* d_in, const int* in_sizes, int n_in,
                              void* d_out, int out_size)
{
    const float* q   = (const float*)d_in[0];
    const float* kv  = (const float*)d_in[1];
    const float* Wq  = (const float*)d_in[2];
    const float* Wkv = (const float*)d_in[3];
    const float* Wo  = (const float*)d_in[4];
    const float* bo  = (const float*)d_in[5];
    float* out = (float*)d_out;

    float *query = nullptr, *kvproj = nullptr, *attn = nullptr;
    cudaGetSymbolAddress((void**)&query,  g_query);
    cudaGetSymbolAddress((void**)&kvproj, g_kvproj);
    cudaGetSymbolAddress((void**)&attn,   g_attn);

    // 1) query = q @ Wq : (8192 x 512) * (512 x 1024)
    sgemm_kernel<<<dim3(HID / BN, (B_ASSETS * I_LAT) / BM), 256>>>(
        q, Wq, query, B_ASSETS * I_LAT, HID, QD, nullptr);

    // 2) kvproj = kv @ Wkv : (32768 x 256) * (256 x 2048)
    sgemm_kernel<<<dim3((2 * HID) / BN, (B_ASSETS * J_WIN) / BM), 256>>>(
        kv, Wkv, kvproj, B_ASSETS * J_WIN, 2 * HID, KVD, nullptr);

    // 3) fused multi-head attention
    attn_kernel<<<B_ASSETS * NH, 128>>>(query, kvproj, attn);

    // 4) out = attn @ Wo + bo : (8192 x 1024) * (1024 x 512)
    sgemm_kernel<<<dim3(QD / BN, (B_ASSETS * I_LAT) / BM), 256>>>(
        attn, Wo, out, B_ASSETS * I_LAT, QD, HID, bo);
}

// round 3
// speedup vs baseline: 1.5220x; 1.5220x over previous
#include <cuda_runtime.h>
#include <cuda_bf16.h>
#include <cstdint>
#include <math.h>

// ---------------------------------------------------------------------------
// Problem:
//   q   : (64, 128, 512)   A1 (8192 x 512)
//   kv  : (64, 512, 256)   A2 (32768 x 256)
//   Wq  : (512, 1024)   Wkv : (256, 2048)   Wo : (1024, 512)   bo : (512)
//   out : (64, 128, 512)
// GEMMs on tensor cores via mma.sync.m16n8k16 bf16 (base sm_103 PTX —
// tcgen05 is rejected because the harness compiles for sm_103, not sm_103a).
// fp32 emulated as bf16 hi/lo x3-split with fp32 accumulation.
// ---------------------------------------------------------------------------

#define B_ASSETS 64
#define I_LAT    128
#define J_WIN    512
#define QD       512
#define KVD      256
#define HID      1024
#define NH       16
#define HD       64

// ------------------------- scratch (no cudaMalloc) -------------------------
__device__ float          g_query [8192u  * 1024u];
__device__ float          g_kvproj[32768u * 2048u];
__device__ __nv_bfloat16  g_qhi [8192u  * 512u],  g_qlo [8192u  * 512u];
__device__ __nv_bfloat16  g_kvhi[32768u * 256u],  g_kvlo[32768u * 256u];
__device__ __nv_bfloat16  g_ahi [8192u  * 1024u], g_alo [8192u  * 1024u];
__device__ __nv_bfloat16  g_wqthi [1024u * 512u], g_wqtlo [1024u * 512u];
__device__ __nv_bfloat16  g_wkvthi[2048u * 256u], g_wkvtlo[2048u * 256u];
__device__ __nv_bfloat16  g_wothi [512u * 1024u], g_wotlo [512u * 1024u];

// ------------------------------ PTX helpers --------------------------------
__device__ __forceinline__ uint32_t smem_u32(const void* p) {
    uint32_t a;
    asm("{ .reg .u64 t; cvta.to.shared.u64 t, %1; cvt.u32.u64 %0, t; }"
        : "=r"(a) : "l"(p));
    return a;
}
__device__ __forceinline__ void cp16(uint32_t dst, const void* src) {
    asm volatile("cp.async.cg.shared.global [%0], [%1], 16;"
                 :: "r"(dst), "l"(src));
}
#define CP_COMMIT() asm volatile("cp.async.commit_group;" ::: "memory")
#define CP_WAIT(n)  asm volatile("cp.async.wait_group %0;" :: "n"(n) : "memory")

__device__ __forceinline__ void ldsm_x4(uint32_t (&r)[4], uint32_t addr) {
    asm volatile("ldmatrix.sync.aligned.m8n8.x4.shared.b16 {%0,%1,%2,%3}, [%4];"
                 : "=r"(r[0]), "=r"(r[1]), "=r"(r[2]), "=r"(r[3]) : "r"(addr));
}
__device__ __forceinline__ void mma_bf16(float (&d)[4],
                                         const uint32_t (&a)[4],
                                         uint32_t b0, uint32_t b1) {
    asm volatile(
        "mma.sync.aligned.m16n8k16.row.col.f32.bf16.bf16.f32 "
        "{%0,%1,%2,%3}, {%4,%5,%6,%7}, {%8,%9}, {%0,%1,%2,%3};"
        : "+f"(d[0]), "+f"(d[1]), "+f"(d[2]), "+f"(d[3])
        : "r"(a[0]), "r"(a[1]), "r"(a[2]), "r"(a[3]), "r"(b0), "r"(b1));
}

// ---------------------------------------------------------------------------
// HMMA GEMM: C(MxN fp32) = (Ahi+Alo)(MxK) * (Bthi+Btlo)^T (+bias)
// A row-major M x K bf16; Bt row-major N x K bf16 (== B col-major).
// CTA tile 128x128, BK=32, 8 warps (4x2), warp tile 32x64,
// cp.async double buffer. Rows padded to 40 bf16 (80B) in smem.
// ---------------------------------------------------------------------------
#define BM 128
#define BN 128
#define BK 32
#define RPAD 40                 // padded row length (bf16 elems)
#define ARR_E (128 * RPAD)      // elems per array (5120)
#define STG_E (4 * ARR_E)       // elems per stage  (20480)
#define SMEM_BYTES (2 * STG_E * 2)  // 81920 B

__global__ __launch_bounds__(256) void mma_gemm_kernel(
    const __nv_bfloat16* __restrict__ Ahi, const __nv_bfloat16* __restrict__ Alo,
    const __nv_bfloat16* __restrict__ Bthi, const __nv_bfloat16* __restrict__ Btlo,
    float* __restrict__ C, int M, int N, int K,
    const float* __restrict__ bias)
{
    extern __shared__ __nv_bfloat16 smem[];
    const uint32_t sbase = smem_u32(smem);
    const int tid  = threadIdx.x;
    const int wid  = tid >> 5;
    const int lane = tid & 31;
    const int m0 = blockIdx.y * BM;
    const int n0 = blockIdx.x * BN;
    const int wm = (wid >> 1) * 32;   // warp row offset in tile
    const int wn = (wid & 1) * 64;    // warp col offset in tile

    // ------- cp.async stage loader: 2048 16B chunks, 8 per thread -------
    auto load_stage = [&](int s, int kbase) {
        const int cc  = tid;                 // base chunk id within array (0..255)
        #pragma unroll
        for (int half = 0; half < 2; half++) {
            int c   = cc + half * 256;       // 0..511
            int row = c >> 2;
            int ch  = c & 3;
            uint32_t so = sbase + (uint32_t)(s * STG_E + row * RPAD) * 2 + ch * 16;
            size_t goa = (size_t)(m0 + row) * K + kbase + ch * 8;
            size_t gob = (size_t)(n0 + row) * K + kbase + ch * 8;
            cp16(so + 0 * ARR_E * 2, Ahi  + goa);
            cp16(so + 1 * ARR_E * 2, Alo  + goa);
            cp16(so + 2 * ARR_E * 2, Bthi + gob);
            cp16(so + 3 * ARR_E * 2, Btlo + gob);
        }
    };

    float acc[2][8][4];
    #pragma unroll
    for (int i = 0; i < 2; i++)
        #pragma unroll
        for (int j = 0; j < 8; j++)
            #pragma unroll
            for (int v = 0; v < 4; v++) acc[i][j][v] = 0.f;

    const int nk = K / BK;
    load_stage(0, 0);
    CP_COMMIT();

    // precomputed ldmatrix lane addressing
    const int a_row = lane & 15;                       // A: row within 16
    const int a_k8  = (lane >> 4) * 8;                 // A: k half
    const int b_row = (lane & 7) + ((lane >> 4) << 3); // B: n row within 16
    const int b_k8  = ((lane >> 3) & 1) * 8;           // B: k half

    for (int kc = 0; kc < nk; kc++) {
        if (kc + 1 < nk) {
            load_stage((kc + 1) & 1, (kc + 1) * BK);
            CP_COMMIT();
            CP_WAIT(1);
        } else {
            CP_WAIT(0);
        }
        __syncthreads();

        const uint32_t stg = sbase + (uint32_t)(((kc & 1) ? STG_E : 0)) * 2;

        #pragma unroll
        for (int k16 = 0; k16 < BK; k16 += 16) {
            // ---- A fragments (hi & lo), 2 m16 tiles ----
            uint32_t ah[2][4], al[2][4];
            #pragma unroll
            for (int mt = 0; mt < 2; mt++) {
                uint32_t off = (uint32_t)((wm + mt * 16 + a_row) * RPAD) * 2
                             + (k16 + a_k8) * 2;
                ldsm_x4(ah[mt], stg + off);
                ldsm_x4(al[mt], stg + ARR_E * 2 + off);
            }
            // ---- B pairs: 4 pairs of n8 tiles ----
            #pragma unroll
            for (int p = 0; p < 4; p++) {
                uint32_t bh[4], bl[4];
                uint32_t off = (uint32_t)((wn + p * 16 + b_row) * RPAD) * 2
                             + (k16 + b_k8) * 2;
                ldsm_x4(bh, stg + 2 * ARR_E * 2 + off);
                ldsm_x4(bl, stg + 3 * ARR_E * 2 + off);
                #pragma unroll
                for (int mt = 0; mt < 2; mt++) {
                    mma_bf16(acc[mt][2 * p + 0], ah[mt], bh[0], bh[1]);
                    mma_bf16(acc[mt][2 * p + 0], ah[mt], bl[0], bl[1]);
                    mma_bf16(acc[mt][2 * p + 0], al[mt], bh[0], bh[1]);
                    mma_bf16(acc[mt][2 * p + 1], ah[mt], bh[2], bh[3]);
                    mma_bf16(acc[mt][2 * p + 1], ah[mt], bl[2], bl[3]);
                    mma_bf16(acc[mt][2 * p + 1], al[mt], bh[2], bh[3]);
                }
            }
        }
        __syncthreads();
    }

    // ------------------------------ epilogue -------------------------------
    const int er = lane >> 2;          // row group 0..7
    const int ec = (lane & 3) * 2;     // col pair
    #pragma unroll
    for (int mt = 0; mt < 2; mt++) {
        int r0 = m0 + wm + mt * 16 + er;
        #pragma unroll
        for (int nt = 0; nt < 8; nt++) {
            int c = n0 + wn + nt * 8 + ec;
            float bx = 0.f, by = 0.f;
            if (bias != nullptr) { bx = bias[c]; by = bias[c + 1]; }
            float2 v0 = make_float2(acc[mt][nt][0] + bx, acc[mt][nt][1] + by);
            float2 v1 = make_float2(acc[mt][nt][2] + bx, acc[mt][nt][3] + by);
            *reinterpret_cast<float2*>(C + (size_t)r0 * N + c) = v0;
            *reinterpret_cast<float2*>(C + (size_t)(r0 + 8) * N + c) = v1;
        }
    }
}

// ---------------------------------------------------------------------------
// fp32 -> (bf16 hi, bf16 lo) split, vectorized
// ---------------------------------------------------------------------------
__global__ void split_kernel(const float* __restrict__ x,
                             __nv_bfloat16* __restrict__ hi,
                             __nv_bfloat16* __restrict__ lo, int n4)
{
    int i = blockIdx.x * blockDim.x + threadIdx.x;
    if (i >= n4) return;
    float4 v = reinterpret_cast<const float4*>(x)[i];
    __nv_bfloat16 h0 = __float2bfloat16_rn(v.x);
    __nv_bfloat16 h1 = __float2bfloat16_rn(v.y);
    __nv_bfloat16 h2 = __float2bfloat16_rn(v.z);
    __nv_bfloat16 h3 = __float2bfloat16_rn(v.w);
    __nv_bfloat162 hp0; hp0.x = h0; hp0.y = h1;
    __nv_bfloat162 hp1; hp1.x = h2; hp1.y = h3;
    __nv_bfloat162 lp0, lp1;
    lp0.x = __float2bfloat16_rn(v.x - __bfloat162float(h0));
    lp0.y = __float2bfloat16_rn(v.y - __bfloat162float(h1));
    lp1.x = __float2bfloat16_rn(v.z - __bfloat162float(h2));
    lp1.y = __float2bfloat16_rn(v.w - __bfloat162float(h3));
    reinterpret_cast<__nv_bfloat162*>(hi)[2 * i + 0] = hp0;
    reinterpret_cast<__nv_bfloat162*>(hi)[2 * i + 1] = hp1;
    reinterpret_cast<__nv_bfloat162*>(lo)[2 * i + 0] = lp0;
    reinterpret_cast<__nv_bfloat162*>(lo)[2 * i + 1] = lp1;
}

// W (K x N) -> Wt hi/lo (N x K) transpose + split
__global__ void tsplit_kernel(const float* __restrict__ W,
                              __nv_bfloat16* __restrict__ Whi,
                              __nv_bfloat16* __restrict__ Wlo, int K, int N)
{
    int idx = blockIdx.x * blockDim.x + threadIdx.x;
    if (idx >= K * N) return;
    int k = idx / N, n = idx - k * N;
    float v = W[idx];
    __nv_bfloat16 h = __float2bfloat16_rn(v);
    Whi[(size_t)n * K + k] = h;
    Wlo[(size_t)n * K + k] = __float2bfloat16_rn(v - __bfloat162float(h));
}

// ---------------------------------------------------------------------------
// Fused attention (fp32): one CTA per (b, h); thread i owns query row i.
// Epilogue writes bf16 hi/lo split for GEMM3's A operand.
// ---------------------------------------------------------------------------
__global__ __launch_bounds__(128) void attn_kernel(
    const float* __restrict__ query,
    const float* __restrict__ kvproj,
    __nv_bfloat16* __restrict__ ohi,
    __nv_bfloat16* __restrict__ olo)
{
    const int b = blockIdx.x >> 4;
    const int h = blockIdx.x & 15;
    const int i = threadIdx.x;
    const float scale = 0.125f;

    __shared__ float4 Ks[64][16];
    __shared__ float4 Vs[64][16];

    float4 qv[16];
    const float4* qrow = reinterpret_cast<const float4*>(
        query + (size_t)(b * I_LAT + i) * HID + h * HD);
    #pragma unroll
    for (int d = 0; d < 16; d++) qv[d] = qrow[d];

    float acc[HD];
    #pragma unroll
    for (int d = 0; d < HD; d++) acc[d] = 0.f;
    float m = -INFINITY, l = 0.f;

    for (int jt = 0; jt < J_WIN / 64; jt++) {
        __syncthreads();
        for (int t = threadIdx.x; t < 64 * 16; t += 128) {
            int r = t >> 4, c = t & 15;
            size_t rowbase = (size_t)(b * J_WIN + jt * 64 + r) * 2048;
            Ks[r][c] = reinterpret_cast<const float4*>(kvproj + rowbase + h * HD)[c];
            Vs[r][c] = reinterpret_cast<const float4*>(kvproj + rowbase + HID + h * HD)[c];
        }
        __syncthreads();

        #pragma unroll 4
        for (int j = 0; j < 64; j++) {
            float s = 0.f;
            #pragma unroll
            for (int d = 0; d < 16; d++) {
                float4 k4 = Ks[j][d];
                s = fmaf(qv[d].x, k4.x, s);
                s = fmaf(qv[d].y, k4.y, s);
                s = fmaf(qv[d].z, k4.z, s);
                s = fmaf(qv[d].w, k4.w, s);
            }
            s *= scale;
            float mnew = fmaxf(m, s);
            float f = __expf(m - mnew);
            float p = __expf(s - mnew);
            m = mnew;
            l = l * f + p;
            #pragma unroll
            for (int d = 0; d < 16; d++) {
                float4 v4 = Vs[j][d];
                acc[4 * d + 0] = fmaf(acc[4 * d + 0], f, p * v4.x);
                acc[4 * d + 1] = fmaf(acc[4 * d + 1], f, p * v4.y);
                acc[4 * d + 2] = fmaf(acc[4 * d + 2], f, p * v4.z);
                acc[4 * d + 3] = fmaf(acc[4 * d + 3], f, p * v4.w);
            }
        }
    }

    const float inv = 1.f / l;
    const size_t obase = (size_t)(b * I_LAT + i) * HID + h * HD;
    __nv_bfloat162* hb = reinterpret_cast<__nv_bfloat162*>(ohi + obase);
    __nv_bfloat162* lb = reinterpret_cast<__nv_bfloat162*>(olo + obase);
    #pragma unroll
    for (int d = 0; d < 16; d++) {
        float x0 = acc[4 * d + 0] * inv, x1 = acc[4 * d + 1] * inv;
        float x2 = acc[4 * d + 2] * inv, x3 = acc[4 * d + 3] * inv;
        __nv_bfloat162 hp0, hp1, lp0, lp1;
        hp0.x = __float2bfloat16_rn(x0); hp0.y = __float2bfloat16_rn(x1);
        hp1.x = __float2bfloat16_rn(x2); hp1.y = __float2bfloat16_rn(x3);
        lp0.x = __float2bfloat16_rn(x0 - __bfloat162float(hp0.x));
        lp0.y = __float2bfloat16_rn(x1 - __bfloat162float(hp0.y));
        lp1.x = __float2bfloat16_rn(x2 - __bfloat162float(hp1.x));
        lp1.y = __float2bfloat16_rn(x3 - __bfloat162float(hp1.y));
        hb[2 * d + 0] = hp0; hb[2 * d + 1] = hp1;
        lb[2 * d + 0] = lp0; lb[2 * d + 1] = lp1;
    }
}

// ---------------------------------------------------------------------------
// Launch
// ---------------------------------------------------------------------------
extern "C" void kernel_launch(void* const* d_in, const int* in_sizes, int n_in,
                              void* d_out, int out_size)
{
    const float* q   = (const float*)d_in[0];
    const float* kv  = (const float*)d_in[1];
    const float* Wq  = (const float*)d_in[2];
    const float* Wkv = (const float*)d_in[3];
    const float* Wo  = (const float*)d_in[4];
    const float* bo  = (const float*)d_in[5];
    float* out = (float*)d_out;

    float *query, *kvproj;
    __nv_bfloat16 *qhi, *qlo, *kvhi, *kvlo, *ahi, *alo;
    __nv_bfloat16 *wqthi, *wqtlo, *wkvthi, *wkvtlo, *wothi, *wotlo;
    cudaGetSymbolAddress((void**)&query,  g_query);
    cudaGetSymbolAddress((void**)&kvproj, g_kvproj);
    cudaGetSymbolAddress((void**)&qhi,  g_qhi);   cudaGetSymbolAddress((void**)&qlo,  g_qlo);
    cudaGetSymbolAddress((void**)&kvhi, g_kvhi);  cudaGetSymbolAddress((void**)&kvlo, g_kvlo);
    cudaGetSymbolAddress((void**)&ahi,  g_ahi);   cudaGetSymbolAddress((void**)&alo,  g_alo);
    cudaGetSymbolAddress((void**)&wqthi, g_wqthi);   cudaGetSymbolAddress((void**)&wqtlo, g_wqtlo);
    cudaGetSymbolAddress((void**)&wkvthi, g_wkvthi); cudaGetSymbolAddress((void**)&wkvtlo, g_wkvtlo);
    cudaGetSymbolAddress((void**)&wothi, g_wothi);   cudaGetSymbolAddress((void**)&wotlo, g_wotlo);

    cudaFuncSetAttribute(mma_gemm_kernel,
                         cudaFuncAttributeMaxDynamicSharedMemorySize, SMEM_BYTES);

    // prep: splits + weight transpose-splits
    {
        int n4 = 8192 * 512 / 4;
        split_kernel<<<(n4 + 255) / 256, 256>>>(q, qhi, qlo, n4);
        n4 = 32768 * 256 / 4;
        split_kernel<<<(n4 + 255) / 256, 256>>>(kv, kvhi, kvlo, n4);
        int ne = QD * HID;
        tsplit_kernel<<<(ne + 255) / 256, 256>>>(Wq, wqthi, wqtlo, QD, HID);
        ne = KVD * 2 * HID;
        tsplit_kernel<<<(ne + 255) / 256, 256>>>(Wkv, wkvthi, wkvtlo, KVD, 2 * HID);
        ne = HID * QD;
        tsplit_kernel<<<(ne + 255) / 256, 256>>>(Wo, wothi, wotlo, HID, QD);
    }

    // 1) query = q @ Wq : (8192 x 1024), K=512
    mma_gemm_kernel<<<dim3(HID / BN, 8192 / BM), 256, SMEM_BYTES>>>(
        qhi, qlo, wqthi, wqtlo, query, 8192, HID, QD, nullptr);

    // 2) kvproj = kv @ Wkv : (32768 x 2048), K=256
    mma_gemm_kernel<<<dim3(2 * HID / BN, 32768 / BM), 256, SMEM_BYTES>>>(
        kvhi, kvlo, wkvthi, wkvtlo, kvproj, 32768, 2 * HID, KVD, nullptr);

    // 3) attention (fp32) -> bf16 hi/lo split output
    attn_kernel<<<B_ASSETS * NH, 128>>>(query, kvproj, ahi, alo);

    // 4) out = attn @ Wo + bo : (8192 x 512), K=1024
    mma_gemm_kernel<<<dim3(QD / BN, 8192 / BM), 256, SMEM_BYTES>>>(
        ahi, alo, wothi, wotlo, out, 8192, QD, HID, bo);
}

// round 4
// speedup vs baseline: 2.9670x; 1.9495x over previous
#include <cuda_runtime.h>
#include <cuda_bf16.h>
#include <cstdint>
#include <math.h>

// ---------------------------------------------------------------------------
//   q   : (64, 128, 512)   kv : (64, 512, 256)
//   Wq  : (512, 1024)  Wkv : (256, 2048)  Wo : (1024, 512)  bo : (512)
//   out : (64, 128, 512)
// Everything on HMMA (mma.sync m16n8k16 bf16) with fp32 emulation via
// bf16 hi/lo 3-split. Flash attention also on HMMA.
// ---------------------------------------------------------------------------

#define B_ASSETS 64
#define I_LAT    128
#define J_WIN    512
#define QD       512
#define KVD      256
#define HID      1024
#define NH       16
#define HD       64

// ------------------------- scratch (no cudaMalloc) -------------------------
__device__ __nv_bfloat16  g_qhi  [8192u  * 512u],  g_qlo  [8192u  * 512u];
__device__ __nv_bfloat16  g_kvhi [32768u * 256u],  g_kvlo [32768u * 256u];
__device__ __nv_bfloat16  g_qphi [8192u  * 1024u], g_qplo [8192u  * 1024u];
__device__ __nv_bfloat16  g_kvphi[32768u * 2048u], g_kvplo[32768u * 2048u];
__device__ __nv_bfloat16  g_athi [8192u  * 1024u], g_atlo [8192u  * 1024u];
__device__ __nv_bfloat16  g_wqthi [1024u * 512u],  g_wqtlo [1024u * 512u];
__device__ __nv_bfloat16  g_wkvthi[2048u * 256u],  g_wkvtlo[2048u * 256u];
__device__ __nv_bfloat16  g_wothi [512u * 1024u],  g_wotlo [512u * 1024u];

// ------------------------------ PTX helpers --------------------------------
__device__ __forceinline__ uint32_t smem_u32(const void* p) {
    uint32_t a;
    asm("{ .reg .u64 t; cvta.to.shared.u64 t, %1; cvt.u32.u64 %0, t; }"
        : "=r"(a) : "l"(p));
    return a;
}
__device__ __forceinline__ void cp16(uint32_t dst, const void* src) {
    asm volatile("cp.async.cg.shared.global [%0], [%1], 16;"
                 :: "r"(dst), "l"(src));
}
#define CP_COMMIT() asm volatile("cp.async.commit_group;" ::: "memory")
#define CP_WAIT(n)  asm volatile("cp.async.wait_group %0;" :: "n"(n) : "memory")

__device__ __forceinline__ void ldsm_x4(uint32_t (&r)[4], uint32_t addr) {
    asm volatile("ldmatrix.sync.aligned.m8n8.x4.shared.b16 {%0,%1,%2,%3}, [%4];"
                 : "=r"(r[0]), "=r"(r[1]), "=r"(r[2]), "=r"(r[3]) : "r"(addr));
}
__device__ __forceinline__ void ldsm_x4t(uint32_t (&r)[4], uint32_t addr) {
    asm volatile("ldmatrix.sync.aligned.m8n8.x4.trans.shared.b16 {%0,%1,%2,%3}, [%4];"
                 : "=r"(r[0]), "=r"(r[1]), "=r"(r[2]), "=r"(r[3]) : "r"(addr));
}
__device__ __forceinline__ void mma_bf16(float (&d)[4],
                                         const uint32_t (&a)[4],
                                         uint32_t b0, uint32_t b1) {
    asm volatile(
        "mma.sync.aligned.m16n8k16.row.col.f32.bf16.bf16.f32 "
        "{%0,%1,%2,%3}, {%4,%5,%6,%7}, {%8,%9}, {%0,%1,%2,%3};"
        : "+f"(d[0]), "+f"(d[1]), "+f"(d[2]), "+f"(d[3])
        : "r"(a[0]), "r"(a[1]), "r"(a[2]), "r"(a[3]), "r"(b0), "r"(b1));
}
__device__ __forceinline__ uint32_t pack_bf16(float lo, float hi) {
    __nv_bfloat162 h = __floats2bfloat162_rn(lo, hi);   // .x = lo half
    return *reinterpret_cast<uint32_t*>(&h);
}

// ---------------------------------------------------------------------------
// HMMA GEMM: (Ahi+Alo)(MxK) * (Bthi+Btlo)^T ; out either fp32 C (+bias) or
// bf16 hi/lo split (Chi/Clo). CTA 128x128, BK=32, 8 warps, cp.async dbuf.
// ---------------------------------------------------------------------------
#define BM 128
#define BN 128
#define BK 32
#define RPAD 40
#define ARR_E (128 * RPAD)
#define STG_E (4 * ARR_E)
#define GEMM_SMEM (2 * STG_E * 2)

__global__ __launch_bounds__(256) void mma_gemm_kernel(
    const __nv_bfloat16* __restrict__ Ahi, const __nv_bfloat16* __restrict__ Alo,
    const __nv_bfloat16* __restrict__ Bthi, const __nv_bfloat16* __restrict__ Btlo,
    float* __restrict__ C,
    __nv_bfloat16* __restrict__ Chi, __nv_bfloat16* __restrict__ Clo,
    int M, int N, int K, const float* __restrict__ bias)
{
    extern __shared__ __nv_bfloat16 smem[];
    const uint32_t sbase = smem_u32(smem);
    const int tid  = threadIdx.x;
    const int wid  = tid >> 5;
    const int lane = tid & 31;
    const int m0 = blockIdx.y * BM;
    const int n0 = blockIdx.x * BN;
    const int wm = (wid >> 1) * 32;
    const int wn = (wid & 1) * 64;

    auto load_stage = [&](int s, int kbase) {
        #pragma unroll
        for (int half = 0; half < 2; half++) {
            int c   = tid + half * 256;
            int row = c >> 2;
            int ch  = c & 3;
            uint32_t so = sbase + (uint32_t)(s * STG_E + row * RPAD) * 2 + ch * 16;
            size_t goa = (size_t)(m0 + row) * K + kbase + ch * 8;
            size_t gob = (size_t)(n0 + row) * K + kbase + ch * 8;
            cp16(so + 0 * ARR_E * 2, Ahi  + goa);
            cp16(so + 1 * ARR_E * 2, Alo  + goa);
            cp16(so + 2 * ARR_E * 2, Bthi + gob);
            cp16(so + 3 * ARR_E * 2, Btlo + gob);
        }
    };

    float acc[2][8][4];
    #pragma unroll
    for (int i = 0; i < 2; i++)
        #pragma unroll
        for (int j = 0; j < 8; j++)
            #pragma unroll
            for (int v = 0; v < 4; v++) acc[i][j][v] = 0.f;

    const int nk = K / BK;
    load_stage(0, 0);
    CP_COMMIT();

    const int a_row = lane & 15;
    const int a_k8  = (lane >> 4) * 8;
    const int b_row = (lane & 7) + ((lane >> 4) << 3);
    const int b_k8  = ((lane >> 3) & 1) * 8;

    for (int kc = 0; kc < nk; kc++) {
        if (kc + 1 < nk) {
            load_stage((kc + 1) & 1, (kc + 1) * BK);
            CP_COMMIT();
            CP_WAIT(1);
        } else {
            CP_WAIT(0);
        }
        __syncthreads();

        const uint32_t stg = sbase + (uint32_t)(((kc & 1) ? STG_E : 0)) * 2;

        #pragma unroll
        for (int k16 = 0; k16 < BK; k16 += 16) {
            uint32_t ah[2][4], al[2][4];
            #pragma unroll
            for (int mt = 0; mt < 2; mt++) {
                uint32_t off = (uint32_t)((wm + mt * 16 + a_row) * RPAD) * 2
                             + (k16 + a_k8) * 2;
                ldsm_x4(ah[mt], stg + off);
                ldsm_x4(al[mt], stg + ARR_E * 2 + off);
            }
            #pragma unroll
            for (int p = 0; p < 4; p++) {
                uint32_t bh[4], bl[4];
                uint32_t off = (uint32_t)((wn + p * 16 + b_row) * RPAD) * 2
                             + (k16 + b_k8) * 2;
                ldsm_x4(bh, stg + 2 * ARR_E * 2 + off);
                ldsm_x4(bl, stg + 3 * ARR_E * 2 + off);
                #pragma unroll
                for (int mt = 0; mt < 2; mt++) {
                    mma_bf16(acc[mt][2 * p + 0], ah[mt], bh[0], bh[1]);
                    mma_bf16(acc[mt][2 * p + 0], ah[mt], bl[0], bl[1]);
                    mma_bf16(acc[mt][2 * p + 0], al[mt], bh[0], bh[1]);
                    mma_bf16(acc[mt][2 * p + 1], ah[mt], bh[2], bh[3]);
                    mma_bf16(acc[mt][2 * p + 1], ah[mt], bl[2], bl[3]);
                    mma_bf16(acc[mt][2 * p + 1], al[mt], bh[2], bh[3]);
                }
            }
        }
        __syncthreads();
    }

    const int er = lane >> 2;
    const int ec = (lane & 3) * 2;
    #pragma unroll
    for (int mt = 0; mt < 2; mt++) {
        int r0 = m0 + wm + mt * 16 + er;
        #pragma unroll
        for (int nt = 0; nt < 8; nt++) {
            int c = n0 + wn + nt * 8 + ec;
            if (Chi != nullptr) {
                #pragma unroll
                for (int half = 0; half < 2; half++) {
                    int r = r0 + half * 8;
                    float v0 = acc[mt][nt][2 * half + 0];
                    float v1 = acc[mt][nt][2 * half + 1];
                    uint32_t hp = pack_bf16(v0, v1);
                    __nv_bfloat162 hb = *reinterpret_cast<__nv_bfloat162*>(&hp);
                    uint32_t lp = pack_bf16(v0 - __bfloat162float(hb.x),
                                            v1 - __bfloat162float(hb.y));
                    *reinterpret_cast<uint32_t*>(Chi + (size_t)r * N + c) = hp;
                    *reinterpret_cast<uint32_t*>(Clo + (size_t)r * N + c) = lp;
                }
            } else {
                float bx = 0.f, by = 0.f;
                if (bias != nullptr) { bx = bias[c]; by = bias[c + 1]; }
                float2 v0 = make_float2(acc[mt][nt][0] + bx, acc[mt][nt][1] + by);
                float2 v1 = make_float2(acc[mt][nt][2] + bx, acc[mt][nt][3] + by);
                *reinterpret_cast<float2*>(C + (size_t)r0 * N + c) = v0;
                *reinterpret_cast<float2*>(C + (size_t)(r0 + 8) * N + c) = v1;
            }
        }
    }
}

// ---------------------------------------------------------------------------
// Prep: input splits (q then kv) in one kernel; weight transpose-splits in one.
// ---------------------------------------------------------------------------
__global__ void split_all_kernel(const float* __restrict__ q,
                                 const float* __restrict__ kv)
{
    int i = blockIdx.x * blockDim.x + threadIdx.x;
    const float* src; __nv_bfloat16 *hi, *lo; int base;
    if (i < 1048576) { src = q;  hi = g_qhi;  lo = g_qlo;  base = i; }
    else             { src = kv; hi = g_kvhi; lo = g_kvlo; base = i - 1048576; }
    float4 v = reinterpret_cast<const float4*>(src)[base];
    __nv_bfloat162 hp0 = __floats2bfloat162_rn(v.x, v.y);
    __nv_bfloat162 hp1 = __floats2bfloat162_rn(v.z, v.w);
    __nv_bfloat162 lp0 = __floats2bfloat162_rn(v.x - __bfloat162float(hp0.x),
                                               v.y - __bfloat162float(hp0.y));
    __nv_bfloat162 lp1 = __floats2bfloat162_rn(v.z - __bfloat162float(hp1.x),
                                               v.w - __bfloat162float(hp1.y));
    reinterpret_cast<__nv_bfloat162*>(hi)[2 * base + 0] = hp0;
    reinterpret_cast<__nv_bfloat162*>(hi)[2 * base + 1] = hp1;
    reinterpret_cast<__nv_bfloat162*>(lo)[2 * base + 0] = lp0;
    reinterpret_cast<__nv_bfloat162*>(lo)[2 * base + 1] = lp1;
}

__global__ void tsplit_all_kernel(const float* __restrict__ Wq,
                                  const float* __restrict__ Wkv,
                                  const float* __restrict__ Wo)
{
    int i = blockIdx.x * blockDim.x + threadIdx.x;
    const float* W; __nv_bfloat16 *Whi, *Wlo; int K, N, idx;
    if (i < 524288)       { W = Wq;  Whi = g_wqthi;  Wlo = g_wqtlo;  K = 512;  N = 1024; idx = i; }
    else if (i < 1048576) { W = Wkv; Whi = g_wkvthi; Wlo = g_wkvtlo; K = 256;  N = 2048; idx = i - 524288; }
    else                  { W = Wo;  Whi = g_wothi;  Wlo = g_wotlo;  K = 1024; N = 512;  idx = i - 1048576; }
    int k = idx / N, n = idx - k * N;
    float v = W[idx];
    __nv_bfloat16 h = __float2bfloat16_rn(v);
    Whi[(size_t)n * K + k] = h;
    Wlo[(size_t)n * K + k] = __float2bfloat16_rn(v - __bfloat162float(h));
}

// ---------------------------------------------------------------------------
// HMMA flash attention: CTA = (b, h), 8 warps x 16 q-rows.
// S = QK^T and O = PV via 3-split bf16 MMAs; K/V tiles cp.async dbuf.
// ---------------------------------------------------------------------------
#define RP 72
#define AQ_HI 0
#define AQ_LO (128 * RP * 2)
#define ASTG  (2 * 128 * RP * 2)       // 36864: start of K/V stages
#define AST_SZ (4 * 64 * RP * 2)       // 36864 per stage
#define AK_HI 0
#define AK_LO (64 * RP * 2)
#define AV_HI (2 * 64 * RP * 2)
#define AV_LO (3 * 64 * RP * 2)
#define ATT_SMEM (ASTG + 2 * AST_SZ)   // 110592

__global__ __launch_bounds__(256) void attn_mma_kernel()
{
    extern __shared__ char asm_smem[];
    const uint32_t sbase = smem_u32(asm_smem);
    const int b = blockIdx.x >> 4;
    const int h = blockIdx.x & 15;
    const int tid  = threadIdx.x;
    const int wid  = tid >> 5;
    const int lane = tid & 31;
    const float scale = 0.125f;

    // ---- load Q tile (128 x 64 hi/lo) into smem ----
    {
        __nv_bfloat16* qh = reinterpret_cast<__nv_bfloat16*>(asm_smem + AQ_HI);
        __nv_bfloat16* ql = reinterpret_cast<__nv_bfloat16*>(asm_smem + AQ_LO);
        for (int c = tid; c < 1024; c += 256) {
            int row = c >> 3, ch = c & 7;
            size_t g = (size_t)(b * 128 + row) * 1024 + h * 64 + ch * 8;
            *reinterpret_cast<uint4*>(qh + row * RP + ch * 8) =
                *reinterpret_cast<const uint4*>(g_qphi + g);
            *reinterpret_cast<uint4*>(ql + row * RP + ch * 8) =
                *reinterpret_cast<const uint4*>(g_qplo + g);
        }
    }

    auto load_kv = [&](int jt, int s) {
        uint32_t st = sbase + ASTG + s * AST_SZ;
        #pragma unroll
        for (int half = 0; half < 2; half++) {
            int c = tid + half * 256;        // 0..511
            int row = c >> 3, ch = c & 7;
            uint32_t so = (uint32_t)(row * RP * 2 + ch * 16);
            size_t kr = (size_t)(b * J_WIN + jt * 64 + row) * 2048 + h * 64 + ch * 8;
            cp16(st + AK_HI + so, g_kvphi + kr);
            cp16(st + AK_LO + so, g_kvplo + kr);
            cp16(st + AV_HI + so, g_kvphi + kr + 1024);
            cp16(st + AV_LO + so, g_kvplo + kr + 1024);
        }
    };

    load_kv(0, 0);
    CP_COMMIT();

    float oacc[8][4];
    #pragma unroll
    for (int d = 0; d < 8; d++)
        #pragma unroll
        for (int v = 0; v < 4; v++) oacc[d][v] = 0.f;
    float m0 = -INFINITY, m1 = -INFINITY, l0 = 0.f, l1 = 0.f;

    const int a_row = lane & 15;
    const int a_k8  = (lane >> 4) * 8;
    const int b_row = (lane & 7) + ((lane >> 4) << 3);
    const int b_k8  = ((lane >> 3) & 1) * 8;

    for (int jt = 0; jt < 8; jt++) {
        __syncthreads();
        if (jt + 1 < 8) {
            load_kv(jt + 1, (jt + 1) & 1);
            CP_COMMIT();
            CP_WAIT(1);
        } else {
            CP_WAIT(0);
        }
        __syncthreads();
        const uint32_t st = sbase + ASTG + (jt & 1) * AST_SZ;

        // ---- S = Q K^T (M16 x N64 x K64, 3-split) ----
        float sacc[8][4];
        #pragma unroll
        for (int p = 0; p < 8; p++)
            #pragma unroll
            for (int v = 0; v < 4; v++) sacc[p][v] = 0.f;

        uint32_t ah[4][4], al[4][4];
        #pragma unroll
        for (int kc = 0; kc < 4; kc++) {
            uint32_t off = (uint32_t)((wid * 16 + a_row) * RP * 2)
                         + (kc * 16 + a_k8) * 2;
            ldsm_x4(ah[kc], sbase + AQ_HI + off);
            ldsm_x4(al[kc], sbase + AQ_LO + off);
        }
        #pragma unroll
        for (int p = 0; p < 4; p++) {
            #pragma unroll
            for (int kc = 0; kc < 4; kc++) {
                uint32_t bh[4], bl[4];
                uint32_t off = (uint32_t)((p * 16 + b_row) * RP * 2)
                             + (kc * 16 + b_k8) * 2;
                ldsm_x4(bh, st + AK_HI + off);
                ldsm_x4(bl, st + AK_LO + off);
                mma_bf16(sacc[2 * p + 0], ah[kc], bh[0], bh[1]);
                mma_bf16(sacc[2 * p + 0], ah[kc], bl[0], bl[1]);
                mma_bf16(sacc[2 * p + 0], al[kc], bh[0], bh[1]);
                mma_bf16(sacc[2 * p + 1], ah[kc], bh[2], bh[3]);
                mma_bf16(sacc[2 * p + 1], ah[kc], bl[2], bl[3]);
                mma_bf16(sacc[2 * p + 1], al[kc], bh[2], bh[3]);
            }
        }

        // ---- online softmax (rows lane/4 and lane/4+8) ----
        float mx0 = -INFINITY, mx1 = -INFINITY;
        #pragma unroll
        for (int nt = 0; nt < 8; nt++) {
            mx0 = fmaxf(mx0, fmaxf(sacc[nt][0], sacc[nt][1]));
            mx1 = fmaxf(mx1, fmaxf(sacc[nt][2], sacc[nt][3]));
        }
        #pragma unroll
        for (int o = 1; o <= 2; o <<= 1) {
            mx0 = fmaxf(mx0, __shfl_xor_sync(0xffffffffu, mx0, o));
            mx1 = fmaxf(mx1, __shfl_xor_sync(0xffffffffu, mx1, o));
        }
        float m0n = fmaxf(m0, mx0 * scale);
        float m1n = fmaxf(m1, mx1 * scale);
        float f0 = __expf(m0 - m0n);
        float f1 = __expf(m1 - m1n);
        m0 = m0n; m1 = m1n;

        float s0 = 0.f, s1 = 0.f;
        #pragma unroll
        for (int nt = 0; nt < 8; nt++) {
            float p0 = __expf(sacc[nt][0] * scale - m0n);
            float p1 = __expf(sacc[nt][1] * scale - m0n);
            float p2 = __expf(sacc[nt][2] * scale - m1n);
            float p3 = __expf(sacc[nt][3] * scale - m1n);
            sacc[nt][0] = p0; sacc[nt][1] = p1;
            sacc[nt][2] = p2; sacc[nt][3] = p3;
            s0 += p0 + p1; s1 += p2 + p3;
        }
        #pragma unroll
        for (int o = 1; o <= 2; o <<= 1) {
            s0 += __shfl_xor_sync(0xffffffffu, s0, o);
            s1 += __shfl_xor_sync(0xffffffffu, s1, o);
        }
        l0 = l0 * f0 + s0;
        l1 = l1 * f1 + s1;
        #pragma unroll
        for (int d = 0; d < 8; d++) {
            oacc[d][0] *= f0; oacc[d][1] *= f0;
            oacc[d][2] *= f1; oacc[d][3] *= f1;
        }

        // ---- O += P V (M16 x N64 x K64, 3-split; P from S acc) ----
        #pragma unroll
        for (int kcp = 0; kcp < 4; kcp++) {
            uint32_t phi[4], plo[4];
            #pragma unroll
            for (int t = 0; t < 2; t++) {
                int nt = 2 * kcp + t;
                float v0 = sacc[nt][0], v1 = sacc[nt][1];
                float v2 = sacc[nt][2], v3 = sacc[nt][3];
                uint32_t hp0 = pack_bf16(v0, v1);
                uint32_t hp1 = pack_bf16(v2, v3);
                __nv_bfloat162 hb0 = *reinterpret_cast<__nv_bfloat162*>(&hp0);
                __nv_bfloat162 hb1 = *reinterpret_cast<__nv_bfloat162*>(&hp1);
                phi[2 * t + 0] = hp0;
                phi[2 * t + 1] = hp1;
                plo[2 * t + 0] = pack_bf16(v0 - __bfloat162float(hb0.x),
                                           v1 - __bfloat162float(hb0.y));
                plo[2 * t + 1] = pack_bf16(v2 - __bfloat162float(hb1.x),
                                           v3 - __bfloat162float(hb1.y));
            }
            // a-frag order: a0=(r, k2c), a1=(r+8, k2c), a2=(r, k2c+8), a3=(r+8,...)
            uint32_t pa_h[4] = { phi[0], phi[1], phi[2], phi[3] };
            uint32_t pa_l[4] = { plo[0], plo[1], plo[2], plo[3] };
            #pragma unroll
            for (int dp = 0; dp < 4; dp++) {
                uint32_t vh[4], vl[4];
                uint32_t off = (uint32_t)((kcp * 16 + (lane & 15)) * RP * 2)
                             + (dp * 16 + (lane >> 4) * 8) * 2;
                ldsm_x4t(vh, st + AV_HI + off);
                ldsm_x4t(vl, st + AV_LO + off);
                mma_bf16(oacc[2 * dp + 0], pa_h, vh[0], vh[1]);
                mma_bf16(oacc[2 * dp + 0], pa_l, vh[0], vh[1]);
                mma_bf16(oacc[2 * dp + 0], pa_h, vl[0], vl[1]);
                mma_bf16(oacc[2 * dp + 1], pa_h, vh[2], vh[3]);
                mma_bf16(oacc[2 * dp + 1], pa_l, vh[2], vh[3]);
                mma_bf16(oacc[2 * dp + 1], pa_h, vl[2], vl[3]);
            }
        }
    }

    // ---- write O / l as bf16 hi/lo split ----
    const float inv0 = 1.f / l0;
    const float inv1 = 1.f / l1;
    const int r0 = b * 128 + wid * 16 + (lane >> 2);
    const int cbase = h * 64 + (lane & 3) * 2;
    #pragma unroll
    for (int dt = 0; dt < 8; dt++) {
        int c = cbase + dt * 8;
        #pragma unroll
        for (int half = 0; half < 2; half++) {
            int r = r0 + half * 8;
            float inv = half ? inv1 : inv0;
            float v0 = oacc[dt][2 * half + 0] * inv;
            float v1 = oacc[dt][2 * half + 1] * inv;
            uint32_t hp = pack_bf16(v0, v1);
            __nv_bfloat162 hb = *reinterpret_cast<__nv_bfloat162*>(&hp);
            uint32_t lp = pack_bf16(v0 - __bfloat162float(hb.x),
                                    v1 - __bfloat162float(hb.y));
            *reinterpret_cast<uint32_t*>(g_athi + (size_t)r * 1024 + c) = hp;
            *reinterpret_cast<uint32_t*>(g_atlo + (size_t)r * 1024 + c) = lp;
        }
    }
}

// ---------------------------------------------------------------------------
// Launch
// ---------------------------------------------------------------------------
extern "C" void kernel_launch(void* const* d_in, const int* in_sizes, int n_in,
                              void* d_out, int out_size)
{
    const float* q   = (const float*)d_in[0];
    const float* kv  = (const float*)d_in[1];
    const float* Wq  = (const float*)d_in[2];
    const float* Wkv = (const float*)d_in[3];
    const float* Wo  = (const float*)d_in[4];
    const float* bo  = (const float*)d_in[5];
    float* out = (float*)d_out;

    __nv_bfloat16 *qhi, *qlo, *kvhi, *kvlo, *qphi, *qplo, *kvphi, *kvplo;
    __nv_bfloat16 *athi, *atlo, *wqthi, *wqtlo, *wkvthi, *wkvtlo, *wothi, *wotlo;
    cudaGetSymbolAddress((void**)&qhi,  g_qhi);     cudaGetSymbolAddress((void**)&qlo,  g_qlo);
    cudaGetSymbolAddress((void**)&kvhi, g_kvhi);    cudaGetSymbolAddress((void**)&kvlo, g_kvlo);
    cudaGetSymbolAddress((void**)&qphi, g_qphi);    cudaGetSymbolAddress((void**)&qplo, g_qplo);
    cudaGetSymbolAddress((void**)&kvphi, g_kvphi);  cudaGetSymbolAddress((void**)&kvplo, g_kvplo);
    cudaGetSymbolAddress((void**)&athi, g_athi);    cudaGetSymbolAddress((void**)&atlo, g_atlo);
    cudaGetSymbolAddress((void**)&wqthi, g_wqthi);  cudaGetSymbolAddress((void**)&wqtlo, g_wqtlo);
    cudaGetSymbolAddress((void**)&wkvthi, g_wkvthi);cudaGetSymbolAddress((void**)&wkvtlo, g_wkvtlo);
    cudaGetSymbolAddress((void**)&wothi, g_wothi);  cudaGetSymbolAddress((void**)&wotlo, g_wotlo);

    cudaFuncSetAttribute(mma_gemm_kernel,
                         cudaFuncAttributeMaxDynamicSharedMemorySize, GEMM_SMEM);
    cudaFuncSetAttribute(attn_mma_kernel,
                         cudaFuncAttributeMaxDynamicSharedMemorySize, ATT_SMEM);

    // 1) prep
    split_all_kernel<<<3145728 / 256, 256>>>(q, kv);
    tsplit_all_kernel<<<1572864 / 256, 256>>>(Wq, Wkv, Wo);

    // 2) query proj -> bf16 hi/lo
    mma_gemm_kernel<<<dim3(HID / BN, 8192 / BM), 256, GEMM_SMEM>>>(
        qhi, qlo, wqthi, wqtlo, nullptr, qphi, qplo, 8192, HID, QD, nullptr);

    // 3) kv proj -> bf16 hi/lo
    mma_gemm_kernel<<<dim3(2 * HID / BN, 32768 / BM), 256, GEMM_SMEM>>>(
        kvhi, kvlo, wkvthi, wkvtlo, nullptr, kvphi, kvplo, 32768, 2 * HID, KVD, nullptr);

    // 4) flash attention (HMMA) -> bf16 hi/lo
    attn_mma_kernel<<<B_ASSETS * NH, 256, ATT_SMEM>>>();

    // 5) out = attn @ Wo + bo (fp32)
    mma_gemm_kernel<<<dim3(QD / BN, 8192 / BM), 256, GEMM_SMEM>>>(
        athi, atlo, wothi, wotlo, out, nullptr, nullptr, 8192, QD, HID, bo);
}

// round 5
// speedup vs baseline: 3.2037x; 1.0798x over previous
#include <cuda_runtime.h>
#include <cuda_bf16.h>
#include <cstdint>
#include <math.h>

// ---------------------------------------------------------------------------
//   q (64,128,512)  kv (64,512,256)  Wq (512,1024)  Wkv (256,2048)
//   Wo (1024,512)  bo (512)  out (64,128,512)
// All heavy math on HMMA (mma.sync m16n8k16 bf16), fp32 emulated via
// bf16 hi/lo 3-split. 3-stage cp.async pipelines, XOR-swizzled smem.
// ---------------------------------------------------------------------------

#define B_ASSETS 64
#define I_LAT    128
#define J_WIN    512
#define QD       512
#define KVD      256
#define HID      1024
#define NH       16
#define HD       64

// ------------------------- scratch (no cudaMalloc) -------------------------
__device__ __nv_bfloat16  g_qhi  [8192u  * 512u],  g_qlo  [8192u  * 512u];
__device__ __nv_bfloat16  g_kvhi [32768u * 256u],  g_kvlo [32768u * 256u];
__device__ __nv_bfloat16  g_qphi [8192u  * 1024u], g_qplo [8192u  * 1024u];
__device__ __nv_bfloat16  g_kvphi[32768u * 2048u], g_kvplo[32768u * 2048u];
__device__ __nv_bfloat16  g_athi [8192u  * 1024u], g_atlo [8192u  * 1024u];
__device__ __nv_bfloat16  g_wqthi [1024u * 512u],  g_wqtlo [1024u * 512u];
__device__ __nv_bfloat16  g_wkvthi[2048u * 256u],  g_wkvtlo[2048u * 256u];
__device__ __nv_bfloat16  g_wothi [512u * 1024u],  g_wotlo [512u * 1024u];

// ------------------------------ PTX helpers --------------------------------
__device__ __forceinline__ uint32_t smem_u32(const void* p) {
    uint32_t a;
    asm("{ .reg .u64 t; cvta.to.shared.u64 t, %1; cvt.u32.u64 %0, t; }"
        : "=r"(a) : "l"(p));
    return a;
}
__device__ __forceinline__ void cp16(uint32_t dst, const void* src) {
    asm volatile("cp.async.cg.shared.global [%0], [%1], 16;"
                 :: "r"(dst), "l"(src));
}
#define CP_COMMIT() asm volatile("cp.async.commit_group;" ::: "memory")
#define CP_WAIT(n)  asm volatile("cp.async.wait_group %0;" :: "n"(n) : "memory")

__device__ __forceinline__ void ldsm_x4(uint32_t (&r)[4], uint32_t addr) {
    asm volatile("ldmatrix.sync.aligned.m8n8.x4.shared.b16 {%0,%1,%2,%3}, [%4];"
                 : "=r"(r[0]), "=r"(r[1]), "=r"(r[2]), "=r"(r[3]) : "r"(addr));
}
__device__ __forceinline__ void ldsm_x4t(uint32_t (&r)[4], uint32_t addr) {
    asm volatile("ldmatrix.sync.aligned.m8n8.x4.trans.shared.b16 {%0,%1,%2,%3}, [%4];"
                 : "=r"(r[0]), "=r"(r[1]), "=r"(r[2]), "=r"(r[3]) : "r"(addr));
}
__device__ __forceinline__ void mma_bf16(float (&d)[4],
                                         const uint32_t (&a)[4],
                                         uint32_t b0, uint32_t b1) {
    asm volatile(
        "mma.sync.aligned.m16n8k16.row.col.f32.bf16.bf16.f32 "
        "{%0,%1,%2,%3}, {%4,%5,%6,%7}, {%8,%9}, {%0,%1,%2,%3};"
        : "+f"(d[0]), "+f"(d[1]), "+f"(d[2]), "+f"(d[3])
        : "r"(a[0]), "r"(a[1]), "r"(a[2]), "r"(a[3]), "r"(b0), "r"(b1));
}
__device__ __forceinline__ uint32_t pack_bf16(float lo, float hi) {
    __nv_bfloat162 h = __floats2bfloat162_rn(lo, hi);
    return *reinterpret_cast<uint32_t*>(&h);
}
__device__ __forceinline__ uint32_t swz(uint32_t b) {   // SW128 xor swizzle
    return b ^ ((b >> 3) & 0x70);
}

// ---------------------------------------------------------------------------
// HMMA GEMM: (Ahi+Alo)(MxK) * (Bthi+Btlo)^T ; out fp32 C (+bias) or bf16
// hi/lo split. CTA 128x128, BK=32, 8 warps, 3-stage cp.async, swizzled smem.
// ---------------------------------------------------------------------------
#define BM 128
#define BN 128
#define BK 32
#define ARR_B 8192u               // 128 rows x 64 B
#define STG_B 32768u              // 4 arrays per stage
#define GEMM_SMEM (3 * 32768)

__global__ __launch_bounds__(256, 2) void mma_gemm_kernel(
    const __nv_bfloat16* __restrict__ Ahi, const __nv_bfloat16* __restrict__ Alo,
    const __nv_bfloat16* __restrict__ Bthi, const __nv_bfloat16* __restrict__ Btlo,
    float* __restrict__ C,
    __nv_bfloat16* __restrict__ Chi, __nv_bfloat16* __restrict__ Clo,
    int M, int N, int K, const float* __restrict__ bias)
{
    extern __shared__ __nv_bfloat16 smem[];
    const uint32_t sbase = smem_u32(smem);
    const int tid  = threadIdx.x;
    const int wid  = tid >> 5;
    const int lane = tid & 31;
    const int m0 = blockIdx.y * BM;
    const int n0 = blockIdx.x * BN;
    const int wm = (wid >> 1) * 32;
    const int wn = (wid & 1) * 64;

    auto load_stage = [&](int s, int kbase) {
        uint32_t st = sbase + (uint32_t)s * STG_B;
        #pragma unroll
        for (int half = 0; half < 2; half++) {
            int c   = tid + half * 256;     // 0..511
            int row = c >> 2;
            int ch  = c & 3;
            uint32_t so = st + swz((uint32_t)(row * 64 + ch * 16));
            size_t goa = (size_t)(m0 + row) * K + kbase + ch * 8;
            size_t gob = (size_t)(n0 + row) * K + kbase + ch * 8;
            cp16(so + 0 * ARR_B, Ahi  + goa);
            cp16(so + 1 * ARR_B, Alo  + goa);
            cp16(so + 2 * ARR_B, Bthi + gob);
            cp16(so + 3 * ARR_B, Btlo + gob);
        }
    };

    float acc[2][8][4];
    #pragma unroll
    for (int i = 0; i < 2; i++)
        #pragma unroll
        for (int j = 0; j < 8; j++)
            #pragma unroll
            for (int v = 0; v < 4; v++) acc[i][j][v] = 0.f;

    const int nk = K / BK;
    load_stage(0, 0);
    CP_COMMIT();
    load_stage(1, BK);
    CP_COMMIT();

    const int a_row = lane & 15;
    const int a_k8  = (lane >> 4) * 8;
    const int b_row = (lane & 7) + ((lane >> 4) << 3);
    const int b_k8  = ((lane >> 3) & 1) * 8;

    int s_cur = 0, s_nxt = 2;
    for (int kc = 0; kc < nk; kc++) {
        if (kc + 2 < nk) {
            load_stage(s_nxt, (kc + 2) * BK);
            CP_COMMIT();
            CP_WAIT(2);
        } else if (kc + 1 < nk) {
            CP_WAIT(1);
        } else {
            CP_WAIT(0);
        }
        __syncthreads();

        const uint32_t stg = sbase + (uint32_t)s_cur * STG_B;

        #pragma unroll
        for (int k16 = 0; k16 < BK; k16 += 16) {
            uint32_t ah[2][4], al[2][4];
            #pragma unroll
            for (int mt = 0; mt < 2; mt++) {
                uint32_t off = swz((uint32_t)((wm + mt * 16 + a_row) * 64)
                                   + (k16 + a_k8) * 2);
                ldsm_x4(ah[mt], stg + off);
                ldsm_x4(al[mt], stg + 1 * ARR_B + off);
            }
            #pragma unroll
            for (int p = 0; p < 4; p++) {
                uint32_t bh[4], bl[4];
                uint32_t off = swz((uint32_t)((wn + p * 16 + b_row) * 64)
                                   + (k16 + b_k8) * 2);
                ldsm_x4(bh, stg + 2 * ARR_B + off);
                ldsm_x4(bl, stg + 3 * ARR_B + off);
                // term-outer, mt-inner: same-acc MMAs spaced by 4
                #pragma unroll
                for (int mt = 0; mt < 2; mt++) {
                    mma_bf16(acc[mt][2 * p + 0], ah[mt], bh[0], bh[1]);
                    mma_bf16(acc[mt][2 * p + 1], ah[mt], bh[2], bh[3]);
                }
                #pragma unroll
                for (int mt = 0; mt < 2; mt++) {
                    mma_bf16(acc[mt][2 * p + 0], ah[mt], bl[0], bl[1]);
                    mma_bf16(acc[mt][2 * p + 1], ah[mt], bl[2], bl[3]);
                }
                #pragma unroll
                for (int mt = 0; mt < 2; mt++) {
                    mma_bf16(acc[mt][2 * p + 0], al[mt], bh[0], bh[1]);
                    mma_bf16(acc[mt][2 * p + 1], al[mt], bh[2], bh[3]);
                }
            }
        }
        __syncthreads();
        int t = s_cur; s_cur = (s_cur + 1 == 3) ? 0 : s_cur + 1;
        s_nxt = (s_nxt + 1 == 3) ? 0 : s_nxt + 1; (void)t;
    }

    const int er = lane >> 2;
    const int ec = (lane & 3) * 2;
    #pragma unroll
    for (int mt = 0; mt < 2; mt++) {
        int r0 = m0 + wm + mt * 16 + er;
        #pragma unroll
        for (int nt = 0; nt < 8; nt++) {
            int c = n0 + wn + nt * 8 + ec;
            if (Chi != nullptr) {
                #pragma unroll
                for (int half = 0; half < 2; half++) {
                    int r = r0 + half * 8;
                    float v0 = acc[mt][nt][2 * half + 0];
                    float v1 = acc[mt][nt][2 * half + 1];
                    uint32_t hp = pack_bf16(v0, v1);
                    __nv_bfloat162 hb = *reinterpret_cast<__nv_bfloat162*>(&hp);
                    uint32_t lp = pack_bf16(v0 - __bfloat162float(hb.x),
                                            v1 - __bfloat162float(hb.y));
                    *reinterpret_cast<uint32_t*>(Chi + (size_t)r * N + c) = hp;
                    *reinterpret_cast<uint32_t*>(Clo + (size_t)r * N + c) = lp;
                }
            } else {
                float bx = 0.f, by = 0.f;
                if (bias != nullptr) { bx = bias[c]; by = bias[c + 1]; }
                float2 v0 = make_float2(acc[mt][nt][0] + bx, acc[mt][nt][1] + by);
                float2 v1 = make_float2(acc[mt][nt][2] + bx, acc[mt][nt][3] + by);
                *reinterpret_cast<float2*>(C + (size_t)r0 * N + c) = v0;
                *reinterpret_cast<float2*>(C + (size_t)(r0 + 8) * N + c) = v1;
            }
        }
    }
}

// ---------------------------------------------------------------------------
// Prep kernels
// ---------------------------------------------------------------------------
__global__ void split_all_kernel(const float* __restrict__ q,
                                 const float* __restrict__ kv)
{
    int i = blockIdx.x * blockDim.x + threadIdx.x;
    const float* src; __nv_bfloat16 *hi, *lo; int base;
    if (i < 1048576) { src = q;  hi = g_qhi;  lo = g_qlo;  base = i; }
    else             { src = kv; hi = g_kvhi; lo = g_kvlo; base = i - 1048576; }
    float4 v = reinterpret_cast<const float4*>(src)[base];
    __nv_bfloat162 hp0 = __floats2bfloat162_rn(v.x, v.y);
    __nv_bfloat162 hp1 = __floats2bfloat162_rn(v.z, v.w);
    __nv_bfloat162 lp0 = __floats2bfloat162_rn(v.x - __bfloat162float(hp0.x),
                                               v.y - __bfloat162float(hp0.y));
    __nv_bfloat162 lp1 = __floats2bfloat162_rn(v.z - __bfloat162float(hp1.x),
                                               v.w - __bfloat162float(hp1.y));
    reinterpret_cast<__nv_bfloat162*>(hi)[2 * base + 0] = hp0;
    reinterpret_cast<__nv_bfloat162*>(hi)[2 * base + 1] = hp1;
    reinterpret_cast<__nv_bfloat162*>(lo)[2 * base + 0] = lp0;
    reinterpret_cast<__nv_bfloat162*>(lo)[2 * base + 1] = lp1;
}

__global__ void tsplit_all_kernel(const float* __restrict__ Wq,
                                  const float* __restrict__ Wkv,
                                  const float* __restrict__ Wo)
{
    int i = blockIdx.x * blockDim.x + threadIdx.x;
    const float* W; __nv_bfloat16 *Whi, *Wlo; int K, N, idx;
    if (i < 524288)       { W = Wq;  Whi = g_wqthi;  Wlo = g_wqtlo;  K = 512;  N = 1024; idx = i; }
    else if (i < 1048576) { W = Wkv; Whi = g_wkvthi; Wlo = g_wkvtlo; K = 256;  N = 2048; idx = i - 524288; }
    else                  { W = Wo;  Whi = g_wothi;  Wlo = g_wotlo;  K = 1024; N = 512;  idx = i - 1048576; }
    int k = idx / N, n = idx - k * N;
    float v = W[idx];
    __nv_bfloat16 h = __float2bfloat16_rn(v);
    Whi[(size_t)n * K + k] = h;
    Wlo[(size_t)n * K + k] = __float2bfloat16_rn(v - __bfloat162float(h));
}

// ---------------------------------------------------------------------------
// HMMA flash attention: CTA = (b, h), 8 warps x 16 q-rows, swizzled smem,
// Q fragments hoisted, K/V double-buffered.
// ---------------------------------------------------------------------------
#define AQ_HI 0u
#define AQ_LO 16384u
#define ASTG  32768u
#define AST_SZ 32768u
#define AK_HI 0u
#define AK_LO 8192u
#define AV_HI 16384u
#define AV_LO 24576u
#define ATT_SMEM (32768 + 2 * 32768)

__global__ __launch_bounds__(256, 2) void attn_mma_kernel()
{
    extern __shared__ char asmem[];
    const uint32_t sbase = smem_u32(asmem);
    const int b = blockIdx.x >> 4;
    const int h = blockIdx.x & 15;
    const int tid  = threadIdx.x;
    const int wid  = tid >> 5;
    const int lane = tid & 31;
    const float scale = 0.125f;

    // ---- stage Q tile (128 x 64 hi/lo), swizzled 128B rows ----
    for (int c = tid; c < 1024; c += 256) {
        int row = c >> 3, ch = c & 7;
        uint32_t so = swz((uint32_t)(row * 128 + ch * 16));
        size_t g = (size_t)(b * 128 + row) * 1024 + h * 64 + ch * 8;
        *reinterpret_cast<uint4*>(asmem + AQ_HI + so) =
            *reinterpret_cast<const uint4*>(g_qphi + g);
        *reinterpret_cast<uint4*>(asmem + AQ_LO + so) =
            *reinterpret_cast<const uint4*>(g_qplo + g);
    }

    auto load_kv = [&](int jt, int s) {
        uint32_t st = sbase + ASTG + (uint32_t)s * AST_SZ;
        #pragma unroll
        for (int half = 0; half < 2; half++) {
            int c = tid + half * 256;
            int row = c >> 3, ch = c & 7;
            uint32_t so = swz((uint32_t)(row * 128 + ch * 16));
            size_t kr = (size_t)(b * J_WIN + jt * 64 + row) * 2048 + h * 64 + ch * 8;
            cp16(st + AK_HI + so, g_kvphi + kr);
            cp16(st + AK_LO + so, g_kvplo + kr);
            cp16(st + AV_HI + so, g_kvphi + kr + 1024);
            cp16(st + AV_LO + so, g_kvplo + kr + 1024);
        }
    };

    load_kv(0, 0);
    CP_COMMIT();

    const int a_row = lane & 15;
    const int a_k8  = (lane >> 4) * 8;
    const int b_row = (lane & 7) + ((lane >> 4) << 3);
    const int b_k8  = ((lane >> 3) & 1) * 8;

    // ---- hoisted Q fragments ----
    __syncthreads();
    uint32_t qah[4][4], qal[4][4];
    #pragma unroll
    for (int kc = 0; kc < 4; kc++) {
        uint32_t off = swz((uint32_t)((wid * 16 + a_row) * 128)
                           + (kc * 16 + a_k8) * 2);
        ldsm_x4(qah[kc], sbase + AQ_HI + off);
        ldsm_x4(qal[kc], sbase + AQ_LO + off);
    }

    float oacc[8][4];
    #pragma unroll
    for (int d = 0; d < 8; d++)
        #pragma unroll
        for (int v = 0; v < 4; v++) oacc[d][v] = 0.f;
    float m0 = -INFINITY, m1 = -INFINITY, l0 = 0.f, l1 = 0.f;

    for (int jt = 0; jt < 8; jt++) {
        __syncthreads();
        if (jt + 1 < 8) {
            load_kv(jt + 1, (jt + 1) & 1);
            CP_COMMIT();
            CP_WAIT(1);
        } else {
            CP_WAIT(0);
        }
        __syncthreads();
        const uint32_t st = sbase + ASTG + (uint32_t)(jt & 1) * AST_SZ;

        // ---- S = Q K^T, kc-outer for acc spacing ----
        float sacc[8][4];
        #pragma unroll
        for (int p = 0; p < 8; p++)
            #pragma unroll
            for (int v = 0; v < 4; v++) sacc[p][v] = 0.f;

        #pragma unroll
        for (int kc = 0; kc < 4; kc++) {
            #pragma unroll
            for (int p = 0; p < 4; p++) {
                uint32_t bh[4], bl[4];
                uint32_t off = swz((uint32_t)((p * 16 + b_row) * 128)
                                   + (kc * 16 + b_k8) * 2);
                ldsm_x4(bh, st + AK_HI + off);
                ldsm_x4(bl, st + AK_LO + off);
                mma_bf16(sacc[2 * p + 0], qah[kc], bh[0], bh[1]);
                mma_bf16(sacc[2 * p + 1], qah[kc], bh[2], bh[3]);
                mma_bf16(sacc[2 * p + 0], qah[kc], bl[0], bl[1]);
                mma_bf16(sacc[2 * p + 1], qah[kc], bl[2], bl[3]);
                mma_bf16(sacc[2 * p + 0], qal[kc], bh[0], bh[1]);
                mma_bf16(sacc[2 * p + 1], qal[kc], bh[2], bh[3]);
            }
        }

        // ---- online softmax ----
        float mx0 = -INFINITY, mx1 = -INFINITY;
        #pragma unroll
        for (int nt = 0; nt < 8; nt++) {
            mx0 = fmaxf(mx0, fmaxf(sacc[nt][0], sacc[nt][1]));
            mx1 = fmaxf(mx1, fmaxf(sacc[nt][2], sacc[nt][3]));
        }
        #pragma unroll
        for (int o = 1; o <= 2; o <<= 1) {
            mx0 = fmaxf(mx0, __shfl_xor_sync(0xffffffffu, mx0, o));
            mx1 = fmaxf(mx1, __shfl_xor_sync(0xffffffffu, mx1, o));
        }
        float m0n = fmaxf(m0, mx0 * scale);
        float m1n = fmaxf(m1, mx1 * scale);
        float f0 = __expf(m0 - m0n);
        float f1 = __expf(m1 - m1n);
        m0 = m0n; m1 = m1n;

        float s0 = 0.f, s1 = 0.f;
        #pragma unroll
        for (int nt = 0; nt < 8; nt++) {
            float p0 = __expf(sacc[nt][0] * scale - m0n);
            float p1 = __expf(sacc[nt][1] * scale - m0n);
            float p2 = __expf(sacc[nt][2] * scale - m1n);
            float p3 = __expf(sacc[nt][3] * scale - m1n);
            sacc[nt][0] = p0; sacc[nt][1] = p1;
            sacc[nt][2] = p2; sacc[nt][3] = p3;
            s0 += p0 + p1; s1 += p2 + p3;
        }
        #pragma unroll
        for (int o = 1; o <= 2; o <<= 1) {
            s0 += __shfl_xor_sync(0xffffffffu, s0, o);
            s1 += __shfl_xor_sync(0xffffffffu, s1, o);
        }
        l0 = l0 * f0 + s0;
        l1 = l1 * f1 + s1;
        #pragma unroll
        for (int d = 0; d < 8; d++) {
            oacc[d][0] *= f0; oacc[d][1] *= f0;
            oacc[d][2] *= f1; oacc[d][3] *= f1;
        }

        // ---- O += P V ----
        #pragma unroll
        for (int kcp = 0; kcp < 4; kcp++) {
            uint32_t pa_h[4], pa_l[4];
            #pragma unroll
            for (int t = 0; t < 2; t++) {
                int nt = 2 * kcp + t;
                float v0 = sacc[nt][0], v1 = sacc[nt][1];
                float v2 = sacc[nt][2], v3 = sacc[nt][3];
                uint32_t hp0 = pack_bf16(v0, v1);
                uint32_t hp1 = pack_bf16(v2, v3);
                __nv_bfloat162 hb0 = *reinterpret_cast<__nv_bfloat162*>(&hp0);
                __nv_bfloat162 hb1 = *reinterpret_cast<__nv_bfloat162*>(&hp1);
                pa_h[2 * t + 0] = hp0;
                pa_h[2 * t + 1] = hp1;
                pa_l[2 * t + 0] = pack_bf16(v0 - __bfloat162float(hb0.x),
                                            v1 - __bfloat162float(hb0.y));
                pa_l[2 * t + 1] = pack_bf16(v2 - __bfloat162float(hb1.x),
                                            v3 - __bfloat162float(hb1.y));
            }
            #pragma unroll
            for (int dp = 0; dp < 4; dp++) {
                uint32_t vh[4], vl[4];
                uint32_t off = swz((uint32_t)((kcp * 16 + (lane & 15)) * 128)
                                   + (dp * 16 + (lane >> 4) * 8) * 2);
                ldsm_x4t(vh, st + AV_HI + off);
                ldsm_x4t(vl, st + AV_LO + off);
                mma_bf16(oacc[2 * dp + 0], pa_h, vh[0], vh[1]);
                mma_bf16(oacc[2 * dp + 1], pa_h, vh[2], vh[3]);
                mma_bf16(oacc[2 * dp + 0], pa_l, vh[0], vh[1]);
                mma_bf16(oacc[2 * dp + 1], pa_l, vh[2], vh[3]);
                mma_bf16(oacc[2 * dp + 0], pa_h, vl[0], vl[1]);
                mma_bf16(oacc[2 * dp + 1], pa_h, vl[2], vl[3]);
            }
        }
    }

    // ---- epilogue: O / l -> bf16 hi/lo split ----
    const float inv0 = 1.f / l0;
    const float inv1 = 1.f / l1;
    const int r0 = b * 128 + wid * 16 + (lane >> 2);
    const int cbase = h * 64 + (lane & 3) * 2;
    #pragma unroll
    for (int dt = 0; dt < 8; dt++) {
        int c = cbase + dt * 8;
        #pragma unroll
        for (int half = 0; half < 2; half++) {
            int r = r0 + half * 8;
            float inv = half ? inv1 : inv0;
            float v0 = oacc[dt][2 * half + 0] * inv;
            float v1 = oacc[dt][2 * half + 1] * inv;
            uint32_t hp = pack_bf16(v0, v1);
            __nv_bfloat162 hb = *reinterpret_cast<__nv_bfloat162*>(&hp);
            uint32_t lp = pack_bf16(v0 - __bfloat162float(hb.x),
                                    v1 - __bfloat162float(hb.y));
            *reinterpret_cast<uint32_t*>(g_athi + (size_t)r * 1024 + c) = hp;
            *reinterpret_cast<uint32_t*>(g_atlo + (size_t)r * 1024 + c) = lp;
        }
    }
}

// ---------------------------------------------------------------------------
// Launch
// ---------------------------------------------------------------------------
extern "C" void kernel_launch(void* const* d_in, const int* in_sizes, int n_in,
                              void* d_out, int out_size)
{
    const float* q   = (const float*)d_in[0];
    const float* kv  = (const float*)d_in[1];
    const float* Wq  = (const float*)d_in[2];
    const float* Wkv = (const float*)d_in[3];
    const float* Wo  = (const float*)d_in[4];
    const float* bo  = (const float*)d_in[5];
    float* out = (float*)d_out;

    __nv_bfloat16 *qhi, *qlo, *kvhi, *kvlo;
    __nv_bfloat16 *qphi, *qplo, *kvphi, *kvplo, *athi, *atlo;
    __nv_bfloat16 *wqthi, *wqtlo, *wkvthi, *wkvtlo, *wothi, *wotlo;
    cudaGetSymbolAddress((void**)&qhi,  g_qhi);     cudaGetSymbolAddress((void**)&qlo,  g_qlo);
    cudaGetSymbolAddress((void**)&kvhi, g_kvhi);    cudaGetSymbolAddress((void**)&kvlo, g_kvlo);
    cudaGetSymbolAddress((void**)&qphi, g_qphi);    cudaGetSymbolAddress((void**)&qplo, g_qplo);
    cudaGetSymbolAddress((void**)&kvphi, g_kvphi);  cudaGetSymbolAddress((void**)&kvplo, g_kvplo);
    cudaGetSymbolAddress((void**)&athi, g_athi);    cudaGetSymbolAddress((void**)&atlo, g_atlo);
    cudaGetSymbolAddress((void**)&wqthi, g_wqthi);  cudaGetSymbolAddress((void**)&wqtlo, g_wqtlo);
    cudaGetSymbolAddress((void**)&wkvthi, g_wkvthi);cudaGetSymbolAddress((void**)&wkvtlo, g_wkvtlo);
    cudaGetSymbolAddress((void**)&wothi, g_wothi);  cudaGetSymbolAddress((void**)&wotlo, g_wotlo);

    cudaFuncSetAttribute(mma_gemm_kernel,
                         cudaFuncAttributeMaxDynamicSharedMemorySize, GEMM_SMEM);
    cudaFuncSetAttribute(attn_mma_kernel,
                         cudaFuncAttributeMaxDynamicSharedMemorySize, ATT_SMEM);

    // 1) prep
    split_all_kernel<<<3145728 / 256, 256>>>(q, kv);
    tsplit_all_kernel<<<1572864 / 256, 256>>>(Wq, Wkv, Wo);

    // 2) query proj -> bf16 hi/lo
    mma_gemm_kernel<<<dim3(HID / BN, 8192 / BM), 256, GEMM_SMEM>>>(
        qhi, qlo, wqthi, wqtlo, nullptr, qphi, qplo, 8192, HID, QD, nullptr);

    // 3) kv proj -> bf16 hi/lo
    mma_gemm_kernel<<<dim3(2 * HID / BN, 32768 / BM), 256, GEMM_SMEM>>>(
        kvhi, kvlo, wkvthi, wkvtlo, nullptr, kvphi, kvplo, 32768, 2 * HID, KVD, nullptr);

    // 4) flash attention (HMMA) -> bf16 hi/lo
    attn_mma_kernel<<<B_ASSETS * NH, 256, ATT_SMEM>>>();

    // 5) out = attn @ Wo + bo (fp32)
    mma_gemm_kernel<<<dim3(QD / BN, 8192 / BM), 256, GEMM_SMEM>>>(
        athi, atlo, wothi, wotlo, out, nullptr, nullptr, 8192, QD, HID, bo);
}

// round 6
// speedup vs baseline: 3.3690x; 1.0516x over previous
#include <cuda_runtime.h>
#include <cuda_bf16.h>
#include <cstdint>
#include <math.h>

// ---------------------------------------------------------------------------
//   q (64,128,512)  kv (64,512,256)  Wq (512,1024)  Wkv (256,2048)
//   Wo (1024,512)  bo (512)  out (64,128,512)
// All heavy math on HMMA (mma.sync m16n8k16 bf16), fp32 emulated via
// bf16 hi/lo 3-split. 3-stage cp.async pipelines, XOR-swizzled smem,
// smem-staged vectorized epilogues.
// ---------------------------------------------------------------------------

#define B_ASSETS 64
#define I_LAT    128
#define J_WIN    512
#define QD       512
#define KVD      256
#define HID      1024
#define NH       16
#define HD       64

// ------------------------- scratch (no cudaMalloc) -------------------------
__device__ __nv_bfloat16  g_qhi  [8192u  * 512u],  g_qlo  [8192u  * 512u];
__device__ __nv_bfloat16  g_kvhi [32768u * 256u],  g_kvlo [32768u * 256u];
__device__ __nv_bfloat16  g_qphi [8192u  * 1024u], g_qplo [8192u  * 1024u];
__device__ __nv_bfloat16  g_kvphi[32768u * 2048u], g_kvplo[32768u * 2048u];
__device__ __nv_bfloat16  g_athi [8192u  * 1024u], g_atlo [8192u  * 1024u];
__device__ __nv_bfloat16  g_wqthi [1024u * 512u],  g_wqtlo [1024u * 512u];
__device__ __nv_bfloat16  g_wkvthi[2048u * 256u],  g_wkvtlo[2048u * 256u];
__device__ __nv_bfloat16  g_wothi [512u * 1024u],  g_wotlo [512u * 1024u];

// ------------------------------ PTX helpers --------------------------------
__device__ __forceinline__ uint32_t smem_u32(const void* p) {
    uint32_t a;
    asm("{ .reg .u64 t; cvta.to.shared.u64 t, %1; cvt.u32.u64 %0, t; }"
        : "=r"(a) : "l"(p));
    return a;
}
__device__ __forceinline__ void cp16(uint32_t dst, const void* src) {
    asm volatile("cp.async.cg.shared.global [%0], [%1], 16;"
                 :: "r"(dst), "l"(src));
}
#define CP_COMMIT() asm volatile("cp.async.commit_group;" ::: "memory")
#define CP_WAIT(n)  asm volatile("cp.async.wait_group %0;" :: "n"(n) : "memory")

__device__ __forceinline__ void ldsm_x4(uint32_t (&r)[4], uint32_t addr) {
    asm volatile("ldmatrix.sync.aligned.m8n8.x4.shared.b16 {%0,%1,%2,%3}, [%4];"
                 : "=r"(r[0]), "=r"(r[1]), "=r"(r[2]), "=r"(r[3]) : "r"(addr));
}
__device__ __forceinline__ void ldsm_x4t(uint32_t (&r)[4], uint32_t addr) {
    asm volatile("ldmatrix.sync.aligned.m8n8.x4.trans.shared.b16 {%0,%1,%2,%3}, [%4];"
                 : "=r"(r[0]), "=r"(r[1]), "=r"(r[2]), "=r"(r[3]) : "r"(addr));
}
__device__ __forceinline__ void mma_bf16(float (&d)[4],
                                         const uint32_t (&a)[4],
                                         uint32_t b0, uint32_t b1) {
    asm volatile(
        "mma.sync.aligned.m16n8k16.row.col.f32.bf16.bf16.f32 "
        "{%0,%1,%2,%3}, {%4,%5,%6,%7}, {%8,%9}, {%0,%1,%2,%3};"
        : "+f"(d[0]), "+f"(d[1]), "+f"(d[2]), "+f"(d[3])
        : "r"(a[0]), "r"(a[1]), "r"(a[2]), "r"(a[3]), "r"(b0), "r"(b1));
}
__device__ __forceinline__ uint32_t pack_bf16(float lo, float hi) {
    __nv_bfloat162 h = __floats2bfloat162_rn(lo, hi);
    return *reinterpret_cast<uint32_t*>(&h);
}
__device__ __forceinline__ uint32_t swz(uint32_t b) {   // SW128 xor swizzle
    return b ^ ((b >> 3) & 0x70);
}

// ---------------------------------------------------------------------------
// HMMA GEMM: (Ahi+Alo)(MxK) * (Bthi+Btlo)^T ; out fp32 C (+bias) or bf16
// hi/lo split. CTA 128x128, BK=32, 8 warps, 3-stage cp.async, swizzled smem.
// bf16 output goes through smem staging for coalesced STG.128.
// ---------------------------------------------------------------------------
#define BM 128
#define BN 128
#define BK 32
#define ARR_B 8192u
#define STG_B 32768u
#define GEMM_SMEM (3 * 32768)
#define EPIT 272u                 // epilogue smem row pitch (bytes)
#define EARR 34816u               // 128 * 272

__global__ __launch_bounds__(256, 2) void mma_gemm_kernel(
    const __nv_bfloat16* __restrict__ Ahi, const __nv_bfloat16* __restrict__ Alo,
    const __nv_bfloat16* __restrict__ Bthi, const __nv_bfloat16* __restrict__ Btlo,
    float* __restrict__ C,
    __nv_bfloat16* __restrict__ Chi, __nv_bfloat16* __restrict__ Clo,
    int M, int N, int K, const float* __restrict__ bias)
{
    extern __shared__ __nv_bfloat16 smem[];
    char* smc = reinterpret_cast<char*>(smem);
    const uint32_t sbase = smem_u32(smem);
    const int tid  = threadIdx.x;
    const int wid  = tid >> 5;
    const int lane = tid & 31;
    const int m0 = blockIdx.y * BM;
    const int n0 = blockIdx.x * BN;
    const int wm = (wid >> 1) * 32;
    const int wn = (wid & 1) * 64;

    auto load_stage = [&](int s, int kbase) {
        uint32_t st = sbase + (uint32_t)s * STG_B;
        #pragma unroll
        for (int half = 0; half < 2; half++) {
            int c   = tid + half * 256;
            int row = c >> 2;
            int ch  = c & 3;
            uint32_t so = st + swz((uint32_t)(row * 64 + ch * 16));
            size_t goa = (size_t)(m0 + row) * K + kbase + ch * 8;
            size_t gob = (size_t)(n0 + row) * K + kbase + ch * 8;
            cp16(so + 0 * ARR_B, Ahi  + goa);
            cp16(so + 1 * ARR_B, Alo  + goa);
            cp16(so + 2 * ARR_B, Bthi + gob);
            cp16(so + 3 * ARR_B, Btlo + gob);
        }
    };

    float acc[2][8][4];
    #pragma unroll
    for (int i = 0; i < 2; i++)
        #pragma unroll
        for (int j = 0; j < 8; j++)
            #pragma unroll
            for (int v = 0; v < 4; v++) acc[i][j][v] = 0.f;

    const int nk = K / BK;
    load_stage(0, 0);
    CP_COMMIT();
    load_stage(1, BK);
    CP_COMMIT();

    const int a_row = lane & 15;
    const int a_k8  = (lane >> 4) * 8;
    const int b_row = (lane & 7) + ((lane >> 4) << 3);
    const int b_k8  = ((lane >> 3) & 1) * 8;

    int s_cur = 0, s_nxt = 2;
    for (int kc = 0; kc < nk; kc++) {
        if (kc < nk - 1) { CP_WAIT(1); } else { CP_WAIT(0); }
        __syncthreads();
        if (kc + 2 < nk) {
            load_stage(s_nxt, (kc + 2) * BK);
            CP_COMMIT();
        }

        const uint32_t stg = sbase + (uint32_t)s_cur * STG_B;

        #pragma unroll
        for (int k16 = 0; k16 < BK; k16 += 16) {
            uint32_t ah[2][4], al[2][4];
            #pragma unroll
            for (int mt = 0; mt < 2; mt++) {
                uint32_t off = swz((uint32_t)((wm + mt * 16 + a_row) * 64)
                                   + (k16 + a_k8) * 2);
                ldsm_x4(ah[mt], stg + off);
                ldsm_x4(al[mt], stg + 1 * ARR_B + off);
            }
            #pragma unroll
            for (int p = 0; p < 4; p++) {
                uint32_t bh[4], bl[4];
                uint32_t off = swz((uint32_t)((wn + p * 16 + b_row) * 64)
                                   + (k16 + b_k8) * 2);
                ldsm_x4(bh, stg + 2 * ARR_B + off);
                ldsm_x4(bl, stg + 3 * ARR_B + off);
                #pragma unroll
                for (int mt = 0; mt < 2; mt++) {
                    mma_bf16(acc[mt][2 * p + 0], ah[mt], bh[0], bh[1]);
                    mma_bf16(acc[mt][2 * p + 1], ah[mt], bh[2], bh[3]);
                }
                #pragma unroll
                for (int mt = 0; mt < 2; mt++) {
                    mma_bf16(acc[mt][2 * p + 0], ah[mt], bl[0], bl[1]);
                    mma_bf16(acc[mt][2 * p + 1], ah[mt], bl[2], bl[3]);
                }
                #pragma unroll
                for (int mt = 0; mt < 2; mt++) {
                    mma_bf16(acc[mt][2 * p + 0], al[mt], bh[0], bh[1]);
                    mma_bf16(acc[mt][2 * p + 1], al[mt], bh[2], bh[3]);
                }
            }
        }
        s_cur = (s_cur + 1 == 3) ? 0 : s_cur + 1;
        s_nxt = (s_nxt + 1 == 3) ? 0 : s_nxt + 1;
    }

    const int er = lane >> 2;
    const int ec = (lane & 3) * 2;

    if (Chi != nullptr) {
        // ---- smem-staged epilogue: conflict-free STS, coalesced STG.128 ----
        __syncthreads();
        #pragma unroll
        for (int mt = 0; mt < 2; mt++) {
            #pragma unroll
            for (int nt = 0; nt < 8; nt++) {
                #pragma unroll
                for (int half = 0; half < 2; half++) {
                    int r = wm + mt * 16 + er + half * 8;
                    int c = wn + nt * 8 + ec;
                    float v0 = acc[mt][nt][2 * half + 0];
                    float v1 = acc[mt][nt][2 * half + 1];
                    uint32_t hp = pack_bf16(v0, v1);
                    __nv_bfloat162 hb = *reinterpret_cast<__nv_bfloat162*>(&hp);
                    uint32_t lp = pack_bf16(v0 - __bfloat162float(hb.x),
                                            v1 - __bfloat162float(hb.y));
                    *reinterpret_cast<uint32_t*>(smc + r * EPIT + c * 2) = hp;
                    *reinterpret_cast<uint32_t*>(smc + EARR + r * EPIT + c * 2) = lp;
                }
            }
        }
        __syncthreads();
        #pragma unroll
        for (int it = 0; it < 8; it++) {
            int idx = tid + it * 256;
            int r = idx >> 4, ch = idx & 15;
            uint4 v = *reinterpret_cast<const uint4*>(smc + r * EPIT + ch * 16);
            uint4 w = *reinterpret_cast<const uint4*>(smc + EARR + r * EPIT + ch * 16);
            size_t g = (size_t)(m0 + r) * N + n0 + ch * 8;
            *reinterpret_cast<uint4*>(Chi + g) = v;
            *reinterpret_cast<uint4*>(Clo + g) = w;
        }
    } else {
        #pragma unroll
        for (int mt = 0; mt < 2; mt++) {
            int r0 = m0 + wm + mt * 16 + er;
            #pragma unroll
            for (int nt = 0; nt < 8; nt++) {
                int c = n0 + wn + nt * 8 + ec;
                float bx = 0.f, by = 0.f;
                if (bias != nullptr) { bx = bias[c]; by = bias[c + 1]; }
                float2 v0 = make_float2(acc[mt][nt][0] + bx, acc[mt][nt][1] + by);
                float2 v1 = make_float2(acc[mt][nt][2] + bx, acc[mt][nt][3] + by);
                *reinterpret_cast<float2*>(C + (size_t)r0 * N + c) = v0;
                *reinterpret_cast<float2*>(C + (size_t)(r0 + 8) * N + c) = v1;
            }
        }
    }
}

// ---------------------------------------------------------------------------
// Prep kernels
// ---------------------------------------------------------------------------
__global__ void split_all_kernel(const float* __restrict__ q,
                                 const float* __restrict__ kv)
{
    int i = blockIdx.x * blockDim.x + threadIdx.x;
    const float* src; __nv_bfloat16 *hi, *lo; int base;
    if (i < 1048576) { src = q;  hi = g_qhi;  lo = g_qlo;  base = i; }
    else             { src = kv; hi = g_kvhi; lo = g_kvlo; base = i - 1048576; }
    float4 v = reinterpret_cast<const float4*>(src)[base];
    __nv_bfloat162 hp0 = __floats2bfloat162_rn(v.x, v.y);
    __nv_bfloat162 hp1 = __floats2bfloat162_rn(v.z, v.w);
    __nv_bfloat162 lp0 = __floats2bfloat162_rn(v.x - __bfloat162float(hp0.x),
                                               v.y - __bfloat162float(hp0.y));
    __nv_bfloat162 lp1 = __floats2bfloat162_rn(v.z - __bfloat162float(hp1.x),
                                               v.w - __bfloat162float(hp1.y));
    reinterpret_cast<__nv_bfloat162*>(hi)[2 * base + 0] = hp0;
    reinterpret_cast<__nv_bfloat162*>(hi)[2 * base + 1] = hp1;
    reinterpret_cast<__nv_bfloat162*>(lo)[2 * base + 0] = lp0;
    reinterpret_cast<__nv_bfloat162*>(lo)[2 * base + 1] = lp1;
}

__global__ void tsplit_all_kernel(const float* __restrict__ Wq,
                                  const float* __restrict__ Wkv,
                                  const float* __restrict__ Wo)
{
    int i = blockIdx.x * blockDim.x + threadIdx.x;
    const float* W; __nv_bfloat16 *Whi, *Wlo; int K, N, idx;
    if (i < 524288)       { W = Wq;  Whi = g_wqthi;  Wlo = g_wqtlo;  K = 512;  N = 1024; idx = i; }
    else if (i < 1048576) { W = Wkv; Whi = g_wkvthi; Wlo = g_wkvtlo; K = 256;  N = 2048; idx = i - 524288; }
    else                  { W = Wo;  Whi = g_wothi;  Wlo = g_wotlo;  K = 1024; N = 512;  idx = i - 1048576; }
    int k = idx / N, n = idx - k * N;
    float v = W[idx];
    __nv_bfloat16 h = __float2bfloat16_rn(v);
    Whi[(size_t)n * K + k] = h;
    Wlo[(size_t)n * K + k] = __float2bfloat16_rn(v - __bfloat162float(h));
}

// ---------------------------------------------------------------------------
// HMMA flash attention: CTA = (b, h), 8 warps x 16 q-rows, swizzled smem,
// Q fragments hoisted, K/V double-buffered, smem-staged epilogue.
// ---------------------------------------------------------------------------
#define AQ_HI 0u
#define AQ_LO 16384u
#define ASTG  32768u
#define AST_SZ 32768u
#define AK_HI 0u
#define AK_LO 8192u
#define AV_HI 16384u
#define AV_LO 24576u
#define ATT_SMEM (32768 + 2 * 32768)
#define AEPIT 144u
#define AEARR 18432u

__global__ __launch_bounds__(256, 2) void attn_mma_kernel()
{
    extern __shared__ char asmem[];
    const uint32_t sbase = smem_u32(asmem);
    const int b = blockIdx.x >> 4;
    const int h = blockIdx.x & 15;
    const int tid  = threadIdx.x;
    const int wid  = tid >> 5;
    const int lane = tid & 31;
    const float scale = 0.125f;

    // ---- stage Q tile (128 x 64 hi/lo), swizzled 128B rows ----
    for (int c = tid; c < 1024; c += 256) {
        int row = c >> 3, ch = c & 7;
        uint32_t so = swz((uint32_t)(row * 128 + ch * 16));
        size_t g = (size_t)(b * 128 + row) * 1024 + h * 64 + ch * 8;
        *reinterpret_cast<uint4*>(asmem + AQ_HI + so) =
            *reinterpret_cast<const uint4*>(g_qphi + g);
        *reinterpret_cast<uint4*>(asmem + AQ_LO + so) =
            *reinterpret_cast<const uint4*>(g_qplo + g);
    }

    auto load_kv = [&](int jt, int s) {
        uint32_t st = sbase + ASTG + (uint32_t)s * AST_SZ;
        #pragma unroll
        for (int half = 0; half < 2; half++) {
            int c = tid + half * 256;
            int row = c >> 3, ch = c & 7;
            uint32_t so = swz((uint32_t)(row * 128 + ch * 16));
            size_t kr = (size_t)(b * J_WIN + jt * 64 + row) * 2048 + h * 64 + ch * 8;
            cp16(st + AK_HI + so, g_kvphi + kr);
            cp16(st + AK_LO + so, g_kvplo + kr);
            cp16(st + AV_HI + so, g_kvphi + kr + 1024);
            cp16(st + AV_LO + so, g_kvplo + kr + 1024);
        }
    };

    load_kv(0, 0);
    CP_COMMIT();

    const int a_row = lane & 15;
    const int a_k8  = (lane >> 4) * 8;
    const int b_row = (lane & 7) + ((lane >> 4) << 3);
    const int b_k8  = ((lane >> 3) & 1) * 8;

    __syncthreads();
    uint32_t qah[4][4], qal[4][4];
    #pragma unroll
    for (int kc = 0; kc < 4; kc++) {
        uint32_t off = swz((uint32_t)((wid * 16 + a_row) * 128)
                           + (kc * 16 + a_k8) * 2);
        ldsm_x4(qah[kc], sbase + AQ_HI + off);
        ldsm_x4(qal[kc], sbase + AQ_LO + off);
    }

    float oacc[8][4];
    #pragma unroll
    for (int d = 0; d < 8; d++)
        #pragma unroll
        for (int v = 0; v < 4; v++) oacc[d][v] = 0.f;
    float m0 = -INFINITY, m1 = -INFINITY, l0 = 0.f, l1 = 0.f;

    for (int jt = 0; jt < 8; jt++) {
        __syncthreads();
        if (jt + 1 < 8) {
            load_kv(jt + 1, (jt + 1) & 1);
            CP_COMMIT();
            CP_WAIT(1);
        } else {
            CP_WAIT(0);
        }
        __syncthreads();
        const uint32_t st = sbase + ASTG + (uint32_t)(jt & 1) * AST_SZ;

        // ---- S = Q K^T ----
        float sacc[8][4];
        #pragma unroll
        for (int p = 0; p < 8; p++)
            #pragma unroll
            for (int v = 0; v < 4; v++) sacc[p][v] = 0.f;

        #pragma unroll
        for (int kc = 0; kc < 4; kc++) {
            #pragma unroll
            for (int p = 0; p < 4; p++) {
                uint32_t bh[4], bl[4];
                uint32_t off = swz((uint32_t)((p * 16 + b_row) * 128)
                                   + (kc * 16 + b_k8) * 2);
                ldsm_x4(bh, st + AK_HI + off);
                ldsm_x4(bl, st + AK_LO + off);
                mma_bf16(sacc[2 * p + 0], qah[kc], bh[0], bh[1]);
                mma_bf16(sacc[2 * p + 1], qah[kc], bh[2], bh[3]);
                mma_bf16(sacc[2 * p + 0], qah[kc], bl[0], bl[1]);
                mma_bf16(sacc[2 * p + 1], qah[kc], bl[2], bl[3]);
                mma_bf16(sacc[2 * p + 0], qal[kc], bh[0], bh[1]);
                mma_bf16(sacc[2 * p + 1], qal[kc], bh[2], bh[3]);
            }
        }

        // ---- online softmax ----
        float mx0 = -INFINITY, mx1 = -INFINITY;
        #pragma unroll
        for (int nt = 0; nt < 8; nt++) {
            mx0 = fmaxf(mx0, fmaxf(sacc[nt][0], sacc[nt][1]));
            mx1 = fmaxf(mx1, fmaxf(sacc[nt][2], sacc[nt][3]));
        }
        #pragma unroll
        for (int o = 1; o <= 2; o <<= 1) {
            mx0 = fmaxf(mx0, __shfl_xor_sync(0xffffffffu, mx0, o));
            mx1 = fmaxf(mx1, __shfl_xor_sync(0xffffffffu, mx1, o));
        }
        float m0n = fmaxf(m0, mx0 * scale);
        float m1n = fmaxf(m1, mx1 * scale);
        float f0 = __expf(m0 - m0n);
        float f1 = __expf(m1 - m1n);
        m0 = m0n; m1 = m1n;

        float s0 = 0.f, s1 = 0.f;
        #pragma unroll
        for (int nt = 0; nt < 8; nt++) {
            float p0 = __expf(sacc[nt][0] * scale - m0n);
            float p1 = __expf(sacc[nt][1] * scale - m0n);
            float p2 = __expf(sacc[nt][2] * scale - m1n);
            float p3 = __expf(sacc[nt][3] * scale - m1n);
            sacc[nt][0] = p0; sacc[nt][1] = p1;
            sacc[nt][2] = p2; sacc[nt][3] = p3;
            s0 += p0 + p1; s1 += p2 + p3;
        }
        #pragma unroll
        for (int o = 1; o <= 2; o <<= 1) {
            s0 += __shfl_xor_sync(0xffffffffu, s0, o);
            s1 += __shfl_xor_sync(0xffffffffu, s1, o);
        }
        l0 = l0 * f0 + s0;
        l1 = l1 * f1 + s1;
        #pragma unroll
        for (int d = 0; d < 8; d++) {
            oacc[d][0] *= f0; oacc[d][1] *= f0;
            oacc[d][2] *= f1; oacc[d][3] *= f1;
        }

        // ---- O += P V ----
        #pragma unroll
        for (int kcp = 0; kcp < 4; kcp++) {
            uint32_t pa_h[4], pa_l[4];
            #pragma unroll
            for (int t = 0; t < 2; t++) {
                int nt = 2 * kcp + t;
                float v0 = sacc[nt][0], v1 = sacc[nt][1];
                float v2 = sacc[nt][2], v3 = sacc[nt][3];
                uint32_t hp0 = pack_bf16(v0, v1);
                uint32_t hp1 = pack_bf16(v2, v3);
                __nv_bfloat162 hb0 = *reinterpret_cast<__nv_bfloat162*>(&hp0);
                __nv_bfloat162 hb1 = *reinterpret_cast<__nv_bfloat162*>(&hp1);
                pa_h[2 * t + 0] = hp0;
                pa_h[2 * t + 1] = hp1;
                pa_l[2 * t + 0] = pack_bf16(v0 - __bfloat162float(hb0.x),
                                            v1 - __bfloat162float(hb0.y));
                pa_l[2 * t + 1] = pack_bf16(v2 - __bfloat162float(hb1.x),
                                            v3 - __bfloat162float(hb1.y));
            }
            #pragma unroll
            for (int dp = 0; dp < 4; dp++) {
                uint32_t vh[4], vl[4];
                uint32_t off = swz((uint32_t)((kcp * 16 + (lane & 15)) * 128)
                                   + (dp * 16 + (lane >> 4) * 8) * 2);
                ldsm_x4t(vh, st + AV_HI + off);
                ldsm_x4t(vl, st + AV_LO + off);
                mma_bf16(oacc[2 * dp + 0], pa_h, vh[0], vh[1]);
                mma_bf16(oacc[2 * dp + 1], pa_h, vh[2], vh[3]);
                mma_bf16(oacc[2 * dp + 0], pa_l, vh[0], vh[1]);
                mma_bf16(oacc[2 * dp + 1], pa_l, vh[2], vh[3]);
                mma_bf16(oacc[2 * dp + 0], pa_h, vl[0], vl[1]);
                mma_bf16(oacc[2 * dp + 1], pa_h, vl[2], vl[3]);
            }
        }
    }

    // ---- smem-staged epilogue: O / l -> bf16 hi/lo, coalesced STG.128 ----
    const float inv0 = 1.f / l0;
    const float inv1 = 1.f / l1;
    #pragma unroll
    for (int dt = 0; dt < 8; dt++) {
        #pragma unroll
        for (int half = 0; half < 2; half++) {
            int r = wid * 16 + (lane >> 2) + half * 8;
            int c = (lane & 3) * 2 + dt * 8;
            float inv = half ? inv1 : inv0;
            float v0 = oacc[dt][2 * half + 0] * inv;
            float v1 = oacc[dt][2 * half + 1] * inv;
            uint32_t hp = pack_bf16(v0, v1);
            __nv_bfloat162 hb = *reinterpret_cast<__nv_bfloat162*>(&hp);
            uint32_t lp = pack_bf16(v0 - __bfloat162float(hb.x),
                                    v1 - __bfloat162float(hb.y));
            *reinterpret_cast<uint32_t*>(asmem + r * AEPIT + c * 2) = hp;
            *reinterpret_cast<uint32_t*>(asmem + AEARR + r * AEPIT + c * 2) = lp;
        }
    }
    __syncthreads();
    #pragma unroll
    for (int it = 0; it < 4; it++) {
        int idx = tid + it * 256;
        int r = idx >> 3, ch = idx & 7;
        uint4 v = *reinterpret_cast<const uint4*>(asmem + r * AEPIT + ch * 16);
        uint4 w = *reinterpret_cast<const uint4*>(asmem + AEARR + r * AEPIT + ch * 16);
        size_t g = (size_t)(b * 128 + r) * 1024 + h * 64 + ch * 8;
        *reinterpret_cast<uint4*>(g_athi + g) = v;
        *reinterpret_cast<uint4*>(g_atlo + g) = w;
    }
}

// ---------------------------------------------------------------------------
// Launch
// ---------------------------------------------------------------------------
extern "C" void kernel_launch(void* const* d_in, const int* in_sizes, int n_in,
                              void* d_out, int out_size)
{
    const float* q   = (const float*)d_in[0];
    const float* kv  = (const float*)d_in[1];
    const float* Wq  = (const float*)d_in[2];
    const float* Wkv = (const float*)d_in[3];
    const float* Wo  = (const float*)d_in[4];
    const float* bo  = (const float*)d_in[5];
    float* out = (float*)d_out;

    __nv_bfloat16 *qhi, *qlo, *kvhi, *kvlo;
    __nv_bfloat16 *qphi, *qplo, *kvphi, *kvplo, *athi, *atlo;
    __nv_bfloat16 *wqthi, *wqtlo, *wkvthi, *wkvtlo, *wothi, *wotlo;
    cudaGetSymbolAddress((void**)&qhi,  g_qhi);     cudaGetSymbolAddress((void**)&qlo,  g_qlo);
    cudaGetSymbolAddress((void**)&kvhi, g_kvhi);    cudaGetSymbolAddress((void**)&kvlo, g_kvlo);
    cudaGetSymbolAddress((void**)&qphi, g_qphi);    cudaGetSymbolAddress((void**)&qplo, g_qplo);
    cudaGetSymbolAddress((void**)&kvphi, g_kvphi);  cudaGetSymbolAddress((void**)&kvplo, g_kvplo);
    cudaGetSymbolAddress((void**)&athi, g_athi);    cudaGetSymbolAddress((void**)&atlo, g_atlo);
    cudaGetSymbolAddress((void**)&wqthi, g_wqthi);  cudaGetSymbolAddress((void**)&wqtlo, g_wqtlo);
    cudaGetSymbolAddress((void**)&wkvthi, g_wkvthi);cudaGetSymbolAddress((void**)&wkvtlo, g_wkvtlo);
    cudaGetSymbolAddress((void**)&wothi, g_wothi);  cudaGetSymbolAddress((void**)&wotlo, g_wotlo);

    cudaFuncSetAttribute(mma_gemm_kernel,
                         cudaFuncAttributeMaxDynamicSharedMemorySize, GEMM_SMEM);
    cudaFuncSetAttribute(attn_mma_kernel,
                         cudaFuncAttributeMaxDynamicSharedMemorySize, ATT_SMEM);

    // 1) prep
    split_all_kernel<<<3145728 / 256, 256>>>(q, kv);
    tsplit_all_kernel<<<1572864 / 256, 256>>>(Wq, Wkv, Wo);

    // 2) query proj -> bf16 hi/lo
    mma_gemm_kernel<<<dim3(HID / BN, 8192 / BM), 256, GEMM_SMEM>>>(
        qhi, qlo, wqthi, wqtlo, nullptr, qphi, qplo, 8192, HID, QD, nullptr);

    // 3) kv proj -> bf16 hi/lo
    mma_gemm_kernel<<<dim3(2 * HID / BN, 32768 / BM), 256, GEMM_SMEM>>>(
        kvhi, kvlo, wkvthi, wkvtlo, nullptr, kvphi, kvplo, 32768, 2 * HID, KVD, nullptr);

    // 4) flash attention (HMMA) -> bf16 hi/lo
    attn_mma_kernel<<<B_ASSETS * NH, 256, ATT_SMEM>>>();

    // 5) out = attn @ Wo + bo (fp32)
    mma_gemm_kernel<<<dim3(QD / BN, 8192 / BM), 256, GEMM_SMEM>>>(
        athi, atlo, wothi, wotlo, out, nullptr, nullptr, 8192, QD, HID, bo);
}

// round 7
// speedup vs baseline: 3.4407x; 1.0213x over previous
#include <cuda_runtime.h>
#include <cuda_bf16.h>
#include <cstdint>
#include <math.h>

// ---------------------------------------------------------------------------
//   q (64,128,512)  kv (64,512,256)  Wq (512,1024)  Wkv (256,2048)
//   Wo (1024,512)  bo (512)  out (64,128,512)
// HMMA everywhere (mma.sync m16n8k16 bf16), fp32 via bf16 hi/lo 3-split.
// GEMM1+GEMM2 fused into one launch; smem-staged epilogues everywhere.
// ---------------------------------------------------------------------------

#define B_ASSETS 64
#define I_LAT    128
#define J_WIN    512
#define QD       512
#define KVD      256
#define HID      1024
#define NH       16
#define HD       64

// ------------------------- scratch (no cudaMalloc) -------------------------
__device__ __nv_bfloat16  g_qhi  [8192u  * 512u],  g_qlo  [8192u  * 512u];
__device__ __nv_bfloat16  g_kvhi [32768u * 256u],  g_kvlo [32768u * 256u];
__device__ __nv_bfloat16  g_qphi [8192u  * 1024u], g_qplo [8192u  * 1024u];
__device__ __nv_bfloat16  g_kvphi[32768u * 2048u], g_kvplo[32768u * 2048u];
__device__ __nv_bfloat16  g_athi [8192u  * 1024u], g_atlo [8192u  * 1024u];
__device__ __nv_bfloat16  g_wqthi [1024u * 512u],  g_wqtlo [1024u * 512u];
__device__ __nv_bfloat16  g_wkvthi[2048u * 256u],  g_wkvtlo[2048u * 256u];
__device__ __nv_bfloat16  g_wothi [512u * 1024u],  g_wotlo [512u * 1024u];

// ------------------------------ PTX helpers --------------------------------
__device__ __forceinline__ uint32_t smem_u32(const void* p) {
    uint32_t a;
    asm("{ .reg .u64 t; cvta.to.shared.u64 t, %1; cvt.u32.u64 %0, t; }"
        : "=r"(a) : "l"(p));
    return a;
}
__device__ __forceinline__ void cp16(uint32_t dst, const void* src) {
    asm volatile("cp.async.cg.shared.global [%0], [%1], 16;"
                 :: "r"(dst), "l"(src));
}
#define CP_COMMIT() asm volatile("cp.async.commit_group;" ::: "memory")
#define CP_WAIT(n)  asm volatile("cp.async.wait_group %0;" :: "n"(n) : "memory")

__device__ __forceinline__ void ldsm_x4(uint32_t (&r)[4], uint32_t addr) {
    asm volatile("ldmatrix.sync.aligned.m8n8.x4.shared.b16 {%0,%1,%2,%3}, [%4];"
                 : "=r"(r[0]), "=r"(r[1]), "=r"(r[2]), "=r"(r[3]) : "r"(addr));
}
__device__ __forceinline__ void ldsm_x4t(uint32_t (&r)[4], uint32_t addr) {
    asm volatile("ldmatrix.sync.aligned.m8n8.x4.trans.shared.b16 {%0,%1,%2,%3}, [%4];"
                 : "=r"(r[0]), "=r"(r[1]), "=r"(r[2]), "=r"(r[3]) : "r"(addr));
}
__device__ __forceinline__ void mma_bf16(float (&d)[4],
                                         const uint32_t (&a)[4],
                                         uint32_t b0, uint32_t b1) {
    asm volatile(
        "mma.sync.aligned.m16n8k16.row.col.f32.bf16.bf16.f32 "
        "{%0,%1,%2,%3}, {%4,%5,%6,%7}, {%8,%9}, {%0,%1,%2,%3};"
        : "+f"(d[0]), "+f"(d[1]), "+f"(d[2]), "+f"(d[3])
        : "r"(a[0]), "r"(a[1]), "r"(a[2]), "r"(a[3]), "r"(b0), "r"(b1));
}
__device__ __forceinline__ uint32_t pack_bf16(float lo, float hi) {
    __nv_bfloat162 h = __floats2bfloat162_rn(lo, hi);
    return *reinterpret_cast<uint32_t*>(&h);
}
__device__ __forceinline__ uint32_t swz(uint32_t b) {
    return b ^ ((b >> 3) & 0x70);
}

// ---------------------------------------------------------------------------
// Shared GEMM machinery: CTA 128x128, BK=32, 8 warps (4x2), 3-stage cp.async.
// ---------------------------------------------------------------------------
#define BM 128
#define BN 128
#define BK 32
#define ARR_B 8192u
#define STG_B 32768u
#define GEMM_SMEM (3 * 32768)
#define EPIT  272u                 // bf16 epilogue pitch
#define EARR  34816u
#define EPIT32 528u                // fp32 epilogue pitch (128*4 + 16)

struct GemmAcc { float a[2][8][4]; };

__device__ __forceinline__ void gemm_mainloop(
    const __nv_bfloat16* __restrict__ Ahi, const __nv_bfloat16* __restrict__ Alo,
    const __nv_bfloat16* __restrict__ Bthi, const __nv_bfloat16* __restrict__ Btlo,
    int K, int m0, int n0, uint32_t sbase, GemmAcc& A)
{
    const int tid  = threadIdx.x;
    const int wid  = tid >> 5;
    const int lane = tid & 31;
    const int wm = (wid >> 1) * 32;
    const int wn = (wid & 1) * 64;

    auto load_stage = [&](int s, int kbase) {
        uint32_t st = sbase + (uint32_t)s * STG_B;
        #pragma unroll
        for (int half = 0; half < 2; half++) {
            int c   = tid + half * 256;
            int row = c >> 2;
            int ch  = c & 3;
            uint32_t so = st + swz((uint32_t)(row * 64 + ch * 16));
            size_t goa = (size_t)(m0 + row) * K + kbase + ch * 8;
            size_t gob = (size_t)(n0 + row) * K + kbase + ch * 8;
            cp16(so + 0 * ARR_B, Ahi  + goa);
            cp16(so + 1 * ARR_B, Alo  + goa);
            cp16(so + 2 * ARR_B, Bthi + gob);
            cp16(so + 3 * ARR_B, Btlo + gob);
        }
    };

    #pragma unroll
    for (int i = 0; i < 2; i++)
        #pragma unroll
        for (int j = 0; j < 8; j++)
            #pragma unroll
            for (int v = 0; v < 4; v++) A.a[i][j][v] = 0.f;

    const int nk = K / BK;
    load_stage(0, 0);
    CP_COMMIT();
    load_stage(1, BK);
    CP_COMMIT();

    const int a_row = lane & 15;
    const int a_k8  = (lane >> 4) * 8;
    const int b_row = (lane & 7) + ((lane >> 4) << 3);
    const int b_k8  = ((lane >> 3) & 1) * 8;

    int s_cur = 0, s_nxt = 2;
    for (int kc = 0; kc < nk; kc++) {
        if (kc < nk - 1) { CP_WAIT(1); } else { CP_WAIT(0); }
        __syncthreads();
        if (kc + 2 < nk) {
            load_stage(s_nxt, (kc + 2) * BK);
            CP_COMMIT();
        }
        const uint32_t stg = sbase + (uint32_t)s_cur * STG_B;

        #pragma unroll
        for (int k16 = 0; k16 < BK; k16 += 16) {
            uint32_t ah[2][4], al[2][4];
            #pragma unroll
            for (int mt = 0; mt < 2; mt++) {
                uint32_t off = swz((uint32_t)((wm + mt * 16 + a_row) * 64)
                                   + (k16 + a_k8) * 2);
                ldsm_x4(ah[mt], stg + off);
                ldsm_x4(al[mt], stg + 1 * ARR_B + off);
            }
            #pragma unroll
            for (int p = 0; p < 4; p++) {
                uint32_t bh[4], bl[4];
                uint32_t off = swz((uint32_t)((wn + p * 16 + b_row) * 64)
                                   + (k16 + b_k8) * 2);
                ldsm_x4(bh, stg + 2 * ARR_B + off);
                ldsm_x4(bl, stg + 3 * ARR_B + off);
                #pragma unroll
                for (int mt = 0; mt < 2; mt++) {
                    mma_bf16(A.a[mt][2 * p + 0], ah[mt], bh[0], bh[1]);
                    mma_bf16(A.a[mt][2 * p + 1], ah[mt], bh[2], bh[3]);
                }
                #pragma unroll
                for (int mt = 0; mt < 2; mt++) {
                    mma_bf16(A.a[mt][2 * p + 0], ah[mt], bl[0], bl[1]);
                    mma_bf16(A.a[mt][2 * p + 1], ah[mt], bl[2], bl[3]);
                }
                #pragma unroll
                for (int mt = 0; mt < 2; mt++) {
                    mma_bf16(A.a[mt][2 * p + 0], al[mt], bh[0], bh[1]);
                    mma_bf16(A.a[mt][2 * p + 1], al[mt], bh[2], bh[3]);
                }
            }
        }
        s_cur = (s_cur + 1 == 3) ? 0 : s_cur + 1;
        s_nxt = (s_nxt + 1 == 3) ? 0 : s_nxt + 1;
    }
}

// ---------------------------------------------------------------------------
// Fused GEMM1 + GEMM2 (independent projections): one launch.
// blocks [0, 512)   : query proj  (8192 x 1024, K=512)  -> g_qphi/g_qplo
// blocks [512, 4608): kv proj    (32768 x 2048, K=256)  -> g_kvphi/g_kvplo
// GEMM1 CTAs (2x work) scheduled first.
// ---------------------------------------------------------------------------
__global__ __launch_bounds__(256, 2) void gemm12_kernel()
{
    extern __shared__ __nv_bfloat16 smem[];
    char* smc = reinterpret_cast<char*>(smem);
    const uint32_t sbase = smem_u32(smem);
    const int tid  = threadIdx.x;
    const int wid  = tid >> 5;
    const int lane = tid & 31;

    const int bid = blockIdx.x;
    const bool g1 = bid < 512;
    const __nv_bfloat16* Ahi  = g1 ? g_qhi   : g_kvhi;
    const __nv_bfloat16* Alo  = g1 ? g_qlo   : g_kvlo;
    const __nv_bfloat16* Bthi = g1 ? g_wqthi : g_wkvthi;
    const __nv_bfloat16* Btlo = g1 ? g_wqtlo : g_wkvtlo;
    __nv_bfloat16* Chi = g1 ? g_qphi : g_kvphi;
    __nv_bfloat16* Clo = g1 ? g_qplo : g_kvplo;
    const int K = g1 ? QD : KVD;
    const int N = g1 ? HID : 2 * HID;
    const int nbx = g1 ? 8 : 16;
    const int lb  = g1 ? bid : bid - 512;
    const int m0 = (lb / nbx) * BM;
    const int n0 = (lb % nbx) * BN;

    GemmAcc acc;
    gemm_mainloop(Ahi, Alo, Bthi, Btlo, K, m0, n0, sbase, acc);

    // ---- smem-staged bf16 hi/lo epilogue ----
    const int wm = (wid >> 1) * 32;
    const int wn = (wid & 1) * 64;
    const int er = lane >> 2;
    const int ec = (lane & 3) * 2;
    __syncthreads();
    #pragma unroll
    for (int mt = 0; mt < 2; mt++) {
        #pragma unroll
        for (int nt = 0; nt < 8; nt++) {
            #pragma unroll
            for (int half = 0; half < 2; half++) {
                int r = wm + mt * 16 + er + half * 8;
                int c = wn + nt * 8 + ec;
                float v0 = acc.a[mt][nt][2 * half + 0];
                float v1 = acc.a[mt][nt][2 * half + 1];
                uint32_t hp = pack_bf16(v0, v1);
                __nv_bfloat162 hb = *reinterpret_cast<__nv_bfloat162*>(&hp);
                uint32_t lp = pack_bf16(v0 - __bfloat162float(hb.x),
                                        v1 - __bfloat162float(hb.y));
                *reinterpret_cast<uint32_t*>(smc + r * EPIT + c * 2) = hp;
                *reinterpret_cast<uint32_t*>(smc + EARR + r * EPIT + c * 2) = lp;
            }
        }
    }
    __syncthreads();
    #pragma unroll
    for (int it = 0; it < 8; it++) {
        int idx = tid + it * 256;
        int r = idx >> 4, ch = idx & 15;
        uint4 v = *reinterpret_cast<const uint4*>(smc + r * EPIT + ch * 16);
        uint4 w = *reinterpret_cast<const uint4*>(smc + EARR + r * EPIT + ch * 16);
        size_t g = (size_t)(m0 + r) * N + n0 + ch * 8;
        *reinterpret_cast<uint4*>(Chi + g) = v;
        *reinterpret_cast<uint4*>(Clo + g) = w;
    }
}

// ---------------------------------------------------------------------------
// GEMM3: out = attn @ Wo + bo (fp32, smem-staged epilogue)
// ---------------------------------------------------------------------------
__global__ __launch_bounds__(256, 2) void gemm3_kernel(
    float* __restrict__ C, const float* __restrict__ bias)
{
    extern __shared__ __nv_bfloat16 smem[];
    char* smc = reinterpret_cast<char*>(smem);
    const uint32_t sbase = smem_u32(smem);
    const int tid  = threadIdx.x;
    const int wid  = tid >> 5;
    const int lane = tid & 31;
    const int m0 = blockIdx.y * BM;
    const int n0 = blockIdx.x * BN;
    const int N = QD;

    GemmAcc acc;
    gemm_mainloop(g_athi, g_atlo, g_wothi, g_wotlo, HID, m0, n0, sbase, acc);

    const int wm = (wid >> 1) * 32;
    const int wn = (wid & 1) * 64;
    const int er = lane >> 2;
    const int ec = (lane & 3) * 2;
    __syncthreads();
    #pragma unroll
    for (int mt = 0; mt < 2; mt++) {
        #pragma unroll
        for (int nt = 0; nt < 8; nt++) {
            #pragma unroll
            for (int half = 0; half < 2; half++) {
                int r = wm + mt * 16 + er + half * 8;
                int c = wn + nt * 8 + ec;
                float2 v = make_float2(acc.a[mt][nt][2 * half + 0],
                                       acc.a[mt][nt][2 * half + 1]);
                *reinterpret_cast<float2*>(smc + r * EPIT32 + c * 4) = v;
            }
        }
    }
    __syncthreads();
    #pragma unroll
    for (int it = 0; it < 16; it++) {
        int idx = tid + it * 256;
        int r = idx >> 5, ch = idx & 31;
        float4 v = *reinterpret_cast<const float4*>(smc + r * EPIT32 + ch * 16);
        float4 bv = *reinterpret_cast<const float4*>(bias + n0 + ch * 4);
        v.x += bv.x; v.y += bv.y; v.z += bv.z; v.w += bv.w;
        *reinterpret_cast<float4*>(C + (size_t)(m0 + r) * N + n0 + ch * 4) = v;
    }
}

// ---------------------------------------------------------------------------
// Prep (single launch): input splits + weight transpose-splits
// ---------------------------------------------------------------------------
__global__ void prep_kernel(const float* __restrict__ q,
                            const float* __restrict__ kv,
                            const float* __restrict__ Wq,
                            const float* __restrict__ Wkv,
                            const float* __restrict__ Wo)
{
    int i = blockIdx.x * blockDim.x + threadIdx.x;
    if (i < 3145728) {
        // vectorized hi/lo split of q then kv (float4 granules)
        const float* src; __nv_bfloat16 *hi, *lo; int base;
        if (i < 1048576) { src = q;  hi = g_qhi;  lo = g_qlo;  base = i; }
        else             { src = kv; hi = g_kvhi; lo = g_kvlo; base = i - 1048576; }
        float4 v = reinterpret_cast<const float4*>(src)[base];
        __nv_bfloat162 hp0 = __floats2bfloat162_rn(v.x, v.y);
        __nv_bfloat162 hp1 = __floats2bfloat162_rn(v.z, v.w);
        __nv_bfloat162 lp0 = __floats2bfloat162_rn(v.x - __bfloat162float(hp0.x),
                                                   v.y - __bfloat162float(hp0.y));
        __nv_bfloat162 lp1 = __floats2bfloat162_rn(v.z - __bfloat162float(hp1.x),
                                                   v.w - __bfloat162float(hp1.y));
        reinterpret_cast<__nv_bfloat162*>(hi)[2 * base + 0] = hp0;
        reinterpret_cast<__nv_bfloat162*>(hi)[2 * base + 1] = hp1;
        reinterpret_cast<__nv_bfloat162*>(lo)[2 * base + 0] = lp0;
        reinterpret_cast<__nv_bfloat162*>(lo)[2 * base + 1] = lp1;
    } else {
        int j = i - 3145728;
        const float* W; __nv_bfloat16 *Whi, *Wlo; int K, N, idx;
        if (j < 524288)       { W = Wq;  Whi = g_wqthi;  Wlo = g_wqtlo;  K = 512;  N = 1024; idx = j; }
        else if (j < 1048576) { W = Wkv; Whi = g_wkvthi; Wlo = g_wkvtlo; K = 256;  N = 2048; idx = j - 524288; }
        else                  { W = Wo;  Whi = g_wothi;  Wlo = g_wotlo;  K = 1024; N = 512;  idx = j - 1048576; }
        int k = idx / N, n = idx - k * N;
        float v = W[idx];
        __nv_bfloat16 h = __float2bfloat16_rn(v);
        Whi[(size_t)n * K + k] = h;
        Wlo[(size_t)n * K + k] = __float2bfloat16_rn(v - __bfloat162float(h));
    }
}

// ---------------------------------------------------------------------------
// HMMA flash attention: CTA = (b, h), 8 warps x 16 q-rows, swizzled smem,
// Q fragments hoisted, K/V double-buffered, smem-staged epilogue.
// ---------------------------------------------------------------------------
#define AQ_HI 0u
#define AQ_LO 16384u
#define ASTG  32768u
#define AST_SZ 32768u
#define AK_HI 0u
#define AK_LO 8192u
#define AV_HI 16384u
#define AV_LO 24576u
#define ATT_SMEM (32768 + 2 * 32768)
#define AEPIT 144u
#define AEARR 18432u

__global__ __launch_bounds__(256, 2) void attn_mma_kernel()
{
    extern __shared__ char asmem[];
    const uint32_t sbase = smem_u32(asmem);
    const int b = blockIdx.x >> 4;
    const int h = blockIdx.x & 15;
    const int tid  = threadIdx.x;
    const int wid  = tid >> 5;
    const int lane = tid & 31;
    const float scale = 0.125f;

    for (int c = tid; c < 1024; c += 256) {
        int row = c >> 3, ch = c & 7;
        uint32_t so = swz((uint32_t)(row * 128 + ch * 16));
        size_t g = (size_t)(b * 128 + row) * 1024 + h * 64 + ch * 8;
        *reinterpret_cast<uint4*>(asmem + AQ_HI + so) =
            *reinterpret_cast<const uint4*>(g_qphi + g);
        *reinterpret_cast<uint4*>(asmem + AQ_LO + so) =
            *reinterpret_cast<const uint4*>(g_qplo + g);
    }

    auto load_kv = [&](int jt, int s) {
        uint32_t st = sbase + ASTG + (uint32_t)s * AST_SZ;
        #pragma unroll
        for (int half = 0; half < 2; half++) {
            int c = tid + half * 256;
            int row = c >> 3, ch = c & 7;
            uint32_t so = swz((uint32_t)(row * 128 + ch * 16));
            size_t kr = (size_t)(b * J_WIN + jt * 64 + row) * 2048 + h * 64 + ch * 8;
            cp16(st + AK_HI + so, g_kvphi + kr);
            cp16(st + AK_LO + so, g_kvplo + kr);
            cp16(st + AV_HI + so, g_kvphi + kr + 1024);
            cp16(st + AV_LO + so, g_kvplo + kr + 1024);
        }
    };

    load_kv(0, 0);
    CP_COMMIT();

    const int a_row = lane & 15;
    const int a_k8  = (lane >> 4) * 8;
    const int b_row = (lane & 7) + ((lane >> 4) << 3);
    const int b_k8  = ((lane >> 3) & 1) * 8;

    __syncthreads();
    uint32_t qah[4][4], qal[4][4];
    #pragma unroll
    for (int kc = 0; kc < 4; kc++) {
        uint32_t off = swz((uint32_t)((wid * 16 + a_row) * 128)
                           + (kc * 16 + a_k8) * 2);
        ldsm_x4(qah[kc], sbase + AQ_HI + off);
        ldsm_x4(qal[kc], sbase + AQ_LO + off);
    }

    float oacc[8][4];
    #pragma unroll
    for (int d = 0; d < 8; d++)
        #pragma unroll
        for (int v = 0; v < 4; v++) oacc[d][v] = 0.f;
    float m0 = -INFINITY, m1 = -INFINITY, l0 = 0.f, l1 = 0.f;

    for (int jt = 0; jt < 8; jt++) {
        __syncthreads();
        if (jt + 1 < 8) {
            load_kv(jt + 1, (jt + 1) & 1);
            CP_COMMIT();
            CP_WAIT(1);
        } else {
            CP_WAIT(0);
        }
        __syncthreads();
        const uint32_t st = sbase + ASTG + (uint32_t)(jt & 1) * AST_SZ;

        float sacc[8][4];
        #pragma unroll
        for (int p = 0; p < 8; p++)
            #pragma unroll
            for (int v = 0; v < 4; v++) sacc[p][v] = 0.f;

        #pragma unroll
        for (int kc = 0; kc < 4; kc++) {
            #pragma unroll
            for (int p = 0; p < 4; p++) {
                uint32_t bh[4], bl[4];
                uint32_t off = swz((uint32_t)((p * 16 + b_row) * 128)
                                   + (kc * 16 + b_k8) * 2);
                ldsm_x4(bh, st + AK_HI + off);
                ldsm_x4(bl, st + AK_LO + off);
                mma_bf16(sacc[2 * p + 0], qah[kc], bh[0], bh[1]);
                mma_bf16(sacc[2 * p + 1], qah[kc], bh[2], bh[3]);
                mma_bf16(sacc[2 * p + 0], qah[kc], bl[0], bl[1]);
                mma_bf16(sacc[2 * p + 1], qah[kc], bl[2], bl[3]);
                mma_bf16(sacc[2 * p + 0], qal[kc], bh[0], bh[1]);
                mma_bf16(sacc[2 * p + 1], qal[kc], bh[2], bh[3]);
            }
        }

        float mx0 = -INFINITY, mx1 = -INFINITY;
        #pragma unroll
        for (int nt = 0; nt < 8; nt++) {
            mx0 = fmaxf(mx0, fmaxf(sacc[nt][0], sacc[nt][1]));
            mx1 = fmaxf(mx1, fmaxf(sacc[nt][2], sacc[nt][3]));
        }
        #pragma unroll
        for (int o = 1; o <= 2; o <<= 1) {
            mx0 = fmaxf(mx0, __shfl_xor_sync(0xffffffffu, mx0, o));
            mx1 = fmaxf(mx1, __shfl_xor_sync(0xffffffffu, mx1, o));
        }
        float m0n = fmaxf(m0, mx0 * scale);
        float m1n = fmaxf(m1, mx1 * scale);
        float f0 = __expf(m0 - m0n);
        float f1 = __expf(m1 - m1n);
        m0 = m0n; m1 = m1n;

        float s0 = 0.f, s1 = 0.f;
        #pragma unroll
        for (int nt = 0; nt < 8; nt++) {
            float p0 = __expf(sacc[nt][0] * scale - m0n);
            float p1 = __expf(sacc[nt][1] * scale - m0n);
            float p2 = __expf(sacc[nt][2] * scale - m1n);
            float p3 = __expf(sacc[nt][3] * scale - m1n);
            sacc[nt][0] = p0; sacc[nt][1] = p1;
            sacc[nt][2] = p2; sacc[nt][3] = p3;
            s0 += p0 + p1; s1 += p2 + p3;
        }
        #pragma unroll
        for (int o = 1; o <= 2; o <<= 1) {
            s0 += __shfl_xor_sync(0xffffffffu, s0, o);
            s1 += __shfl_xor_sync(0xffffffffu, s1, o);
        }
        l0 = l0 * f0 + s0;
        l1 = l1 * f1 + s1;
        #pragma unroll
        for (int d = 0; d < 8; d++) {
            oacc[d][0] *= f0; oacc[d][1] *= f0;
            oacc[d][2] *= f1; oacc[d][3] *= f1;
        }

        #pragma unroll
        for (int kcp = 0; kcp < 4; kcp++) {
            uint32_t pa_h[4], pa_l[4];
            #pragma unroll
            for (int t = 0; t < 2; t++) {
                int nt = 2 * kcp + t;
                float v0 = sacc[nt][0], v1 = sacc[nt][1];
                float v2 = sacc[nt][2], v3 = sacc[nt][3];
                uint32_t hp0 = pack_bf16(v0, v1);
                uint32_t hp1 = pack_bf16(v2, v3);
                __nv_bfloat162 hb0 = *reinterpret_cast<__nv_bfloat162*>(&hp0);
                __nv_bfloat162 hb1 = *reinterpret_cast<__nv_bfloat162*>(&hp1);
                pa_h[2 * t + 0] = hp0;
                pa_h[2 * t + 1] = hp1;
                pa_l[2 * t + 0] = pack_bf16(v0 - __bfloat162float(hb0.x),
                                            v1 - __bfloat162float(hb0.y));
                pa_l[2 * t + 1] = pack_bf16(v2 - __bfloat162float(hb1.x),
                                            v3 - __bfloat162float(hb1.y));
            }
            #pragma unroll
            for (int dp = 0; dp < 4; dp++) {
                uint32_t vh[4], vl[4];
                uint32_t off = swz((uint32_t)((kcp * 16 + (lane & 15)) * 128)
                                   + (dp * 16 + (lane >> 4) * 8) * 2);
                ldsm_x4t(vh, st + AV_HI + off);
                ldsm_x4t(vl, st + AV_LO + off);
                mma_bf16(oacc[2 * dp + 0], pa_h, vh[0], vh[1]);
                mma_bf16(oacc[2 * dp + 1], pa_h, vh[2], vh[3]);
                mma_bf16(oacc[2 * dp + 0], pa_l, vh[0], vh[1]);
                mma_bf16(oacc[2 * dp + 1], pa_l, vh[2], vh[3]);
                mma_bf16(oacc[2 * dp + 0], pa_h, vl[0], vl[1]);
                mma_bf16(oacc[2 * dp + 1], pa_h, vl[2], vl[3]);
            }
        }
    }

    const float inv0 = 1.f / l0;
    const float inv1 = 1.f / l1;
    #pragma unroll
    for (int dt = 0; dt < 8; dt++) {
        #pragma unroll
        for (int half = 0; half < 2; half++) {
            int r = wid * 16 + (lane >> 2) + half * 8;
            int c = (lane & 3) * 2 + dt * 8;
            float inv = half ? inv1 : inv0;
            float v0 = oacc[dt][2 * half + 0] * inv;
            float v1 = oacc[dt][2 * half + 1] * inv;
            uint32_t hp = pack_bf16(v0, v1);
            __nv_bfloat162 hb = *reinterpret_cast<__nv_bfloat162*>(&hp);
            uint32_t lp = pack_bf16(v0 - __bfloat162float(hb.x),
                                    v1 - __bfloat162float(hb.y));
            *reinterpret_cast<uint32_t*>(asmem + r * AEPIT + c * 2) = hp;
            *reinterpret_cast<uint32_t*>(asmem + AEARR + r * AEPIT + c * 2) = lp;
        }
    }
    __syncthreads();
    #pragma unroll
    for (int it = 0; it < 4; it++) {
        int idx = tid + it * 256;
        int r = idx >> 3, ch = idx & 7;
        uint4 v = *reinterpret_cast<const uint4*>(asmem + r * AEPIT + ch * 16);
        uint4 w = *reinterpret_cast<const uint4*>(asmem + AEARR + r * AEPIT + ch * 16);
        size_t g = (size_t)(b * 128 + r) * 1024 + h * 64 + ch * 8;
        *reinterpret_cast<uint4*>(g_athi + g) = v;
        *reinterpret_cast<uint4*>(g_atlo + g) = w;
    }
}

// ---------------------------------------------------------------------------
// Launch
// ---------------------------------------------------------------------------
extern "C" void kernel_launch(void* const* d_in, const int* in_sizes, int n_in,
                              void* d_out, int out_size)
{
    const float* q   = (const float*)d_in[0];
    const float* kv  = (const float*)d_in[1];
    const float* Wq  = (const float*)d_in[2];
    const float* Wkv = (const float*)d_in[3];
    const float* Wo  = (const float*)d_in[4];
    const float* bo  = (const float*)d_in[5];
    float* out = (float*)d_out;

    cudaFuncSetAttribute(gemm12_kernel,
                         cudaFuncAttributeMaxDynamicSharedMemorySize, GEMM_SMEM);
    cudaFuncSetAttribute(gemm3_kernel,
                         cudaFuncAttributeMaxDynamicSharedMemorySize, GEMM_SMEM);
    cudaFuncSetAttribute(attn_mma_kernel,
                         cudaFuncAttributeMaxDynamicSharedMemorySize, ATT_SMEM);

    // 1) prep: input splits + weight transpose-splits (one launch)
    prep_kernel<<<(3145728 + 1572864) / 256, 256>>>(q, kv, Wq, Wkv, Wo);

    // 2) fused query+kv projections -> bf16 hi/lo
    gemm12_kernel<<<4608, 256, GEMM_SMEM>>>();

    // 3) flash attention (HMMA) -> bf16 hi/lo
    attn_mma_kernel<<<B_ASSETS * NH, 256, ATT_SMEM>>>();

    // 4) out = attn @ Wo + bo (fp32, staged epilogue)
    gemm3_kernel<<<dim3(QD / BN, 8192 / BM), 256, GEMM_SMEM>>>(out, bo);
}

// round 8
// speedup vs baseline: 3.4880x; 1.0137x over previous
#include <cuda_runtime.h>
#include <cuda_bf16.h>
#include <cstdint>
#include <math.h>

// ---------------------------------------------------------------------------
//   q (64,128,512)  kv (64,512,256)  Wq (512,1024)  Wkv (256,2048)
//   Wo (1024,512)  bo (512)  out (64,128,512)
// HMMA everywhere, fp32 via bf16 hi/lo 3-split. GEMMs: 128x128 CTA tile,
// 4 warps x (64x64) warp tiles for 85B-LDSM/MMA, 3-stage cp.async.
// ---------------------------------------------------------------------------

#define B_ASSETS 64
#define I_LAT    128
#define J_WIN    512
#define QD       512
#define KVD      256
#define HID      1024
#define NH       16
#define HD       64

// ------------------------- scratch (no cudaMalloc) -------------------------
__device__ __nv_bfloat16  g_qhi  [8192u  * 512u],  g_qlo  [8192u  * 512u];
__device__ __nv_bfloat16  g_kvhi [32768u * 256u],  g_kvlo [32768u * 256u];
__device__ __nv_bfloat16  g_qphi [8192u  * 1024u], g_qplo [8192u  * 1024u];
__device__ __nv_bfloat16  g_kvphi[32768u * 2048u], g_kvplo[32768u * 2048u];
__device__ __nv_bfloat16  g_athi [8192u  * 1024u], g_atlo [8192u  * 1024u];
__device__ __nv_bfloat16  g_wqthi [1024u * 512u],  g_wqtlo [1024u * 512u];
__device__ __nv_bfloat16  g_wkvthi[2048u * 256u],  g_wkvtlo[2048u * 256u];
__device__ __nv_bfloat16  g_wothi [512u * 1024u],  g_wotlo [512u * 1024u];

// ------------------------------ PTX helpers --------------------------------
__device__ __forceinline__ uint32_t smem_u32(const void* p) {
    uint32_t a;
    asm("{ .reg .u64 t; cvta.to.shared.u64 t, %1; cvt.u32.u64 %0, t; }"
        : "=r"(a) : "l"(p));
    return a;
}
__device__ __forceinline__ void cp16(uint32_t dst, const void* src) {
    asm volatile("cp.async.cg.shared.global [%0], [%1], 16;"
                 :: "r"(dst), "l"(src));
}
#define CP_COMMIT() asm volatile("cp.async.commit_group;" ::: "memory")
#define CP_WAIT(n)  asm volatile("cp.async.wait_group %0;" :: "n"(n) : "memory")

__device__ __forceinline__ void ldsm_x4(uint32_t (&r)[4], uint32_t addr) {
    asm volatile("ldmatrix.sync.aligned.m8n8.x4.shared.b16 {%0,%1,%2,%3}, [%4];"
                 : "=r"(r[0]), "=r"(r[1]), "=r"(r[2]), "=r"(r[3]) : "r"(addr));
}
__device__ __forceinline__ void ldsm_x4t(uint32_t (&r)[4], uint32_t addr) {
    asm volatile("ldmatrix.sync.aligned.m8n8.x4.trans.shared.b16 {%0,%1,%2,%3}, [%4];"
                 : "=r"(r[0]), "=r"(r[1]), "=r"(r[2]), "=r"(r[3]) : "r"(addr));
}
__device__ __forceinline__ void mma_bf16(float (&d)[4],
                                         const uint32_t (&a)[4],
                                         uint32_t b0, uint32_t b1) {
    asm volatile(
        "mma.sync.aligned.m16n8k16.row.col.f32.bf16.bf16.f32 "
        "{%0,%1,%2,%3}, {%4,%5,%6,%7}, {%8,%9}, {%0,%1,%2,%3};"
        : "+f"(d[0]), "+f"(d[1]), "+f"(d[2]), "+f"(d[3])
        : "r"(a[0]), "r"(a[1]), "r"(a[2]), "r"(a[3]), "r"(b0), "r"(b1));
}
__device__ __forceinline__ uint32_t pack_bf16(float lo, float hi) {
    __nv_bfloat162 h = __floats2bfloat162_rn(lo, hi);
    return *reinterpret_cast<uint32_t*>(&h);
}
__device__ __forceinline__ uint32_t swz(uint32_t b) {
    return b ^ ((b >> 3) & 0x70);
}

// ---------------------------------------------------------------------------
// GEMM machinery: CTA 128x128 (128 threads, 4 warps, 2x2 grid of 64x64
// warp tiles), BK=32, 3-stage cp.async, swizzled smem.
// ---------------------------------------------------------------------------
#define BM 128
#define BN 128
#define BK 32
#define ARR_B 8192u
#define STG_B 32768u
#define GEMM_SMEM (3 * 32768)
#define EPIT   272u
#define EARR   34816u
#define EPIT32 528u

__device__ __forceinline__ void gemm_mainloop(
    const __nv_bfloat16* __restrict__ Ahi, const __nv_bfloat16* __restrict__ Alo,
    const __nv_bfloat16* __restrict__ Bthi, const __nv_bfloat16* __restrict__ Btlo,
    int K, int m0, int n0, uint32_t sbase, float (&acc)[4][8][4])
{
    const int tid  = threadIdx.x;
    const int wid  = tid >> 5;
    const int lane = tid & 31;
    const int wm = (wid >> 1) * 64;
    const int wn = (wid & 1) * 64;

    auto load_stage = [&](int s, int kbase) {
        uint32_t st = sbase + (uint32_t)s * STG_B;
        #pragma unroll
        for (int it = 0; it < 4; it++) {
            int c   = tid + it * 128;      // 0..511
            int row = c >> 2;
            int ch  = c & 3;
            uint32_t so = st + swz((uint32_t)(row * 64 + ch * 16));
            size_t goa = (size_t)(m0 + row) * K + kbase + ch * 8;
            size_t gob = (size_t)(n0 + row) * K + kbase + ch * 8;
            cp16(so + 0 * ARR_B, Ahi  + goa);
            cp16(so + 1 * ARR_B, Alo  + goa);
            cp16(so + 2 * ARR_B, Bthi + gob);
            cp16(so + 3 * ARR_B, Btlo + gob);
        }
    };

    #pragma unroll
    for (int i = 0; i < 4; i++)
        #pragma unroll
        for (int j = 0; j < 8; j++)
            #pragma unroll
            for (int v = 0; v < 4; v++) acc[i][j][v] = 0.f;

    const int nk = K / BK;
    load_stage(0, 0);
    CP_COMMIT();
    load_stage(1, BK);
    CP_COMMIT();

    const int a_row = lane & 15;
    const int a_k8  = (lane >> 4) * 8;
    const int b_row = (lane & 7) + ((lane >> 4) << 3);
    const int b_k8  = ((lane >> 3) & 1) * 8;

    int s_cur = 0, s_nxt = 2;
    for (int kc = 0; kc < nk; kc++) {
        if (kc < nk - 1) { CP_WAIT(1); } else { CP_WAIT(0); }
        __syncthreads();
        if (kc + 2 < nk) {
            load_stage(s_nxt, (kc + 2) * BK);
            CP_COMMIT();
        }
        const uint32_t stg = sbase + (uint32_t)s_cur * STG_B;

        #pragma unroll
        for (int k16 = 0; k16 < BK; k16 += 16) {
            uint32_t ah[4][4], al[4][4];
            #pragma unroll
            for (int mt = 0; mt < 4; mt++) {
                uint32_t off = swz((uint32_t)((wm + mt * 16 + a_row) * 64)
                                   + (k16 + a_k8) * 2);
                ldsm_x4(ah[mt], stg + off);
                ldsm_x4(al[mt], stg + 1 * ARR_B + off);
            }
            #pragma unroll
            for (int p = 0; p < 4; p++) {
                uint32_t bh[4], bl[4];
                uint32_t off = swz((uint32_t)((wn + p * 16 + b_row) * 64)
                                   + (k16 + b_k8) * 2);
                ldsm_x4(bh, stg + 2 * ARR_B + off);
                ldsm_x4(bl, stg + 3 * ARR_B + off);
                #pragma unroll
                for (int mt = 0; mt < 4; mt++) {
                    mma_bf16(acc[mt][2 * p + 0], ah[mt], bh[0], bh[1]);
                    mma_bf16(acc[mt][2 * p + 1], ah[mt], bh[2], bh[3]);
                }
                #pragma unroll
                for (int mt = 0; mt < 4; mt++) {
                    mma_bf16(acc[mt][2 * p + 0], ah[mt], bl[0], bl[1]);
                    mma_bf16(acc[mt][2 * p + 1], ah[mt], bl[2], bl[3]);
                }
                #pragma unroll
                for (int mt = 0; mt < 4; mt++) {
                    mma_bf16(acc[mt][2 * p + 0], al[mt], bh[0], bh[1]);
                    mma_bf16(acc[mt][2 * p + 1], al[mt], bh[2], bh[3]);
                }
            }
        }
        s_cur = (s_cur + 1 == 3) ? 0 : s_cur + 1;
        s_nxt = (s_nxt + 1 == 3) ? 0 : s_nxt + 1;
    }
}

// ---------------------------------------------------------------------------
// Fused GEMM1 + GEMM2: blocks [0,512) query proj, [512,4608) kv proj.
// ---------------------------------------------------------------------------
__global__ __launch_bounds__(128, 2) void gemm12_kernel()
{
    extern __shared__ __nv_bfloat16 smem[];
    char* smc = reinterpret_cast<char*>(smem);
    const uint32_t sbase = smem_u32(smem);
    const int tid  = threadIdx.x;
    const int wid  = tid >> 5;
    const int lane = tid & 31;

    const int bid = blockIdx.x;
    const bool g1 = bid < 512;
    const __nv_bfloat16* Ahi  = g1 ? g_qhi   : g_kvhi;
    const __nv_bfloat16* Alo  = g1 ? g_qlo   : g_kvlo;
    const __nv_bfloat16* Bthi = g1 ? g_wqthi : g_wkvthi;
    const __nv_bfloat16* Btlo = g1 ? g_wqtlo : g_wkvtlo;
    __nv_bfloat16* Chi = g1 ? g_qphi : g_kvphi;
    __nv_bfloat16* Clo = g1 ? g_qplo : g_kvplo;
    const int K = g1 ? QD : KVD;
    const int N = g1 ? HID : 2 * HID;
    const int nbx = g1 ? 8 : 16;
    const int lb  = g1 ? bid : bid - 512;
    const int m0 = (lb / nbx) * BM;
    const int n0 = (lb % nbx) * BN;

    float acc[4][8][4];
    gemm_mainloop(Ahi, Alo, Bthi, Btlo, K, m0, n0, sbase, acc);

    // ---- smem-staged bf16 hi/lo epilogue ----
    const int wm = (wid >> 1) * 64;
    const int wn = (wid & 1) * 64;
    const int er = lane >> 2;
    const int ec = (lane & 3) * 2;
    __syncthreads();
    #pragma unroll
    for (int mt = 0; mt < 4; mt++) {
        #pragma unroll
        for (int nt = 0; nt < 8; nt++) {
            #pragma unroll
            for (int half = 0; half < 2; half++) {
                int r = wm + mt * 16 + er + half * 8;
                int c = wn + nt * 8 + ec;
                float v0 = acc[mt][nt][2 * half + 0];
                float v1 = acc[mt][nt][2 * half + 1];
                uint32_t hp = pack_bf16(v0, v1);
                __nv_bfloat162 hb = *reinterpret_cast<__nv_bfloat162*>(&hp);
                uint32_t lp = pack_bf16(v0 - __bfloat162float(hb.x),
                                        v1 - __bfloat162float(hb.y));
                *reinterpret_cast<uint32_t*>(smc + r * EPIT + c * 2) = hp;
                *reinterpret_cast<uint32_t*>(smc + EARR + r * EPIT + c * 2) = lp;
            }
        }
    }
    __syncthreads();
    #pragma unroll
    for (int it = 0; it < 16; it++) {
        int idx = tid + it * 128;
        int r = idx >> 4, ch = idx & 15;
        uint4 v = *reinterpret_cast<const uint4*>(smc + r * EPIT + ch * 16);
        uint4 w = *reinterpret_cast<const uint4*>(smc + EARR + r * EPIT + ch * 16);
        size_t g = (size_t)(m0 + r) * N + n0 + ch * 8;
        *reinterpret_cast<uint4*>(Chi + g) = v;
        *reinterpret_cast<uint4*>(Clo + g) = w;
    }
}

// ---------------------------------------------------------------------------
// GEMM3: out = attn @ Wo + bo (fp32, smem-staged epilogue)
// ---------------------------------------------------------------------------
__global__ __launch_bounds__(128, 2) void gemm3_kernel(
    float* __restrict__ C, const float* __restrict__ bias)
{
    extern __shared__ __nv_bfloat16 smem[];
    char* smc = reinterpret_cast<char*>(smem);
    const uint32_t sbase = smem_u32(smem);
    const int tid  = threadIdx.x;
    const int wid  = tid >> 5;
    const int lane = tid & 31;
    const int m0 = blockIdx.y * BM;
    const int n0 = blockIdx.x * BN;
    const int N = QD;

    float acc[4][8][4];
    gemm_mainloop(g_athi, g_atlo, g_wothi, g_wotlo, HID, m0, n0, sbase, acc);

    const int wm = (wid >> 1) * 64;
    const int wn = (wid & 1) * 64;
    const int er = lane >> 2;
    const int ec = (lane & 3) * 2;
    __syncthreads();
    #pragma unroll
    for (int mt = 0; mt < 4; mt++) {
        #pragma unroll
        for (int nt = 0; nt < 8; nt++) {
            #pragma unroll
            for (int half = 0; half < 2; half++) {
                int r = wm + mt * 16 + er + half * 8;
                int c = wn + nt * 8 + ec;
                float2 v = make_float2(acc[mt][nt][2 * half + 0],
                                       acc[mt][nt][2 * half + 1]);
                *reinterpret_cast<float2*>(smc + r * EPIT32 + c * 4) = v;
            }
        }
    }
    __syncthreads();
    #pragma unroll
    for (int it = 0; it < 32; it++) {
        int idx = tid + it * 128;
        int r = idx >> 5, ch = idx & 31;
        float4 v = *reinterpret_cast<const float4*>(smc + r * EPIT32 + ch * 16);
        float4 bv = *reinterpret_cast<const float4*>(bias + n0 + ch * 4);
        v.x += bv.x; v.y += bv.y; v.z += bv.z; v.w += bv.w;
        *reinterpret_cast<float4*>(C + (size_t)(m0 + r) * N + n0 + ch * 4) = v;
    }
}

// ---------------------------------------------------------------------------
// Prep (single launch): input splits + weight transpose-splits
// ---------------------------------------------------------------------------
__global__ void prep_kernel(const float* __restrict__ q,
                            const float* __restrict__ kv,
                            const float* __restrict__ Wq,
                            const float* __restrict__ Wkv,
                            const float* __restrict__ Wo)
{
    int i = blockIdx.x * blockDim.x + threadIdx.x;
    if (i < 3145728) {
        const float* src; __nv_bfloat16 *hi, *lo; int base;
        if (i < 1048576) { src = q;  hi = g_qhi;  lo = g_qlo;  base = i; }
        else             { src = kv; hi = g_kvhi; lo = g_kvlo; base = i - 1048576; }
        float4 v = reinterpret_cast<const float4*>(src)[base];
        __nv_bfloat162 hp0 = __floats2bfloat162_rn(v.x, v.y);
        __nv_bfloat162 hp1 = __floats2bfloat162_rn(v.z, v.w);
        __nv_bfloat162 lp0 = __floats2bfloat162_rn(v.x - __bfloat162float(hp0.x),
                                                   v.y - __bfloat162float(hp0.y));
        __nv_bfloat162 lp1 = __floats2bfloat162_rn(v.z - __bfloat162float(hp1.x),
                                                   v.w - __bfloat162float(hp1.y));
        reinterpret_cast<__nv_bfloat162*>(hi)[2 * base + 0] = hp0;
        reinterpret_cast<__nv_bfloat162*>(hi)[2 * base + 1] = hp1;
        reinterpret_cast<__nv_bfloat162*>(lo)[2 * base + 0] = lp0;
        reinterpret_cast<__nv_bfloat162*>(lo)[2 * base + 1] = lp1;
    } else {
        int j = i - 3145728;
        const float* W; __nv_bfloat16 *Whi, *Wlo; int K, N, idx;
        if (j < 524288)       { W = Wq;  Whi = g_wqthi;  Wlo = g_wqtlo;  K = 512;  N = 1024; idx = j; }
        else if (j < 1048576) { W = Wkv; Whi = g_wkvthi; Wlo = g_wkvtlo; K = 256;  N = 2048; idx = j - 524288; }
        else                  { W = Wo;  Whi = g_wothi;  Wlo = g_wotlo;  K = 1024; N = 512;  idx = j - 1048576; }
        int k = idx / N, n = idx - k * N;
        float v = W[idx];
        __nv_bfloat16 h = __float2bfloat16_rn(v);
        Whi[(size_t)n * K + k] = h;
        Wlo[(size_t)n * K + k] = __float2bfloat16_rn(v - __bfloat162float(h));
    }
}

// ---------------------------------------------------------------------------
// HMMA flash attention (unchanged from R7): CTA = (b, h), 8 warps x 16 rows.
// ---------------------------------------------------------------------------
#define AQ_HI 0u
#define AQ_LO 16384u
#define ASTG  32768u
#define AST_SZ 32768u
#define AK_HI 0u
#define AK_LO 8192u
#define AV_HI 16384u
#define AV_LO 24576u
#define ATT_SMEM (32768 + 2 * 32768)
#define AEPIT 144u
#define AEARR 18432u

__global__ __launch_bounds__(256, 2) void attn_mma_kernel()
{
    extern __shared__ char asmem[];
    const uint32_t sbase = smem_u32(asmem);
    const int b = blockIdx.x >> 4;
    const int h = blockIdx.x & 15;
    const int tid  = threadIdx.x;
    const int wid  = tid >> 5;
    const int lane = tid & 31;
    const float scale = 0.125f;

    for (int c = tid; c < 1024; c += 256) {
        int row = c >> 3, ch = c & 7;
        uint32_t so = swz((uint32_t)(row * 128 + ch * 16));
        size_t g = (size_t)(b * 128 + row) * 1024 + h * 64 + ch * 8;
        *reinterpret_cast<uint4*>(asmem + AQ_HI + so) =
            *reinterpret_cast<const uint4*>(g_qphi + g);
        *reinterpret_cast<uint4*>(asmem + AQ_LO + so) =
            *reinterpret_cast<const uint4*>(g_qplo + g);
    }

    auto load_kv = [&](int jt, int s) {
        uint32_t st = sbase + ASTG + (uint32_t)s * AST_SZ;
        #pragma unroll
        for (int half = 0; half < 2; half++) {
            int c = tid + half * 256;
            int row = c >> 3, ch = c & 7;
            uint32_t so = swz((uint32_t)(row * 128 + ch * 16));
            size_t kr = (size_t)(b * J_WIN + jt * 64 + row) * 2048 + h * 64 + ch * 8;
            cp16(st + AK_HI + so, g_kvphi + kr);
            cp16(st + AK_LO + so, g_kvplo + kr);
            cp16(st + AV_HI + so, g_kvphi + kr + 1024);
            cp16(st + AV_LO + so, g_kvplo + kr + 1024);
        }
    };

    load_kv(0, 0);
    CP_COMMIT();

    const int a_row = lane & 15;
    const int a_k8  = (lane >> 4) * 8;
    const int b_row = (lane & 7) + ((lane >> 4) << 3);
    const int b_k8  = ((lane >> 3) & 1) * 8;

    __syncthreads();
    uint32_t qah[4][4], qal[4][4];
    #pragma unroll
    for (int kc = 0; kc < 4; kc++) {
        uint32_t off = swz((uint32_t)((wid * 16 + a_row) * 128)
                           + (kc * 16 + a_k8) * 2);
        ldsm_x4(qah[kc], sbase + AQ_HI + off);
        ldsm_x4(qal[kc], sbase + AQ_LO + off);
    }

    float oacc[8][4];
    #pragma unroll
    for (int d = 0; d < 8; d++)
        #pragma unroll
        for (int v = 0; v < 4; v++) oacc[d][v] = 0.f;
    float m0 = -INFINITY, m1 = -INFINITY, l0 = 0.f, l1 = 0.f;

    for (int jt = 0; jt < 8; jt++) {
        __syncthreads();
        if (jt + 1 < 8) {
            load_kv(jt + 1, (jt + 1) & 1);
            CP_COMMIT();
            CP_WAIT(1);
        } else {
            CP_WAIT(0);
        }
        __syncthreads();
        const uint32_t st = sbase + ASTG + (uint32_t)(jt & 1) * AST_SZ;

        float sacc[8][4];
        #pragma unroll
        for (int p = 0; p < 8; p++)
            #pragma unroll
            for (int v = 0; v < 4; v++) sacc[p][v] = 0.f;

        #pragma unroll
        for (int kc = 0; kc < 4; kc++) {
            #pragma unroll
            for (int p = 0; p < 4; p++) {
                uint32_t bh[4], bl[4];
                uint32_t off = swz((uint32_t)((p * 16 + b_row) * 128)
                                   + (kc * 16 + b_k8) * 2);
                ldsm_x4(bh, st + AK_HI + off);
                ldsm_x4(bl, st + AK_LO + off);
                mma_bf16(sacc[2 * p + 0], qah[kc], bh[0], bh[1]);
                mma_bf16(sacc[2 * p + 1], qah[kc], bh[2], bh[3]);
                mma_bf16(sacc[2 * p + 0], qah[kc], bl[0], bl[1]);
                mma_bf16(sacc[2 * p + 1], qah[kc], bl[2], bl[3]);
                mma_bf16(sacc[2 * p + 0], qal[kc], bh[0], bh[1]);
                mma_bf16(sacc[2 * p + 1], qal[kc], bh[2], bh[3]);
            }
        }

        float mx0 = -INFINITY, mx1 = -INFINITY;
        #pragma unroll
        for (int nt = 0; nt < 8; nt++) {
            mx0 = fmaxf(mx0, fmaxf(sacc[nt][0], sacc[nt][1]));
            mx1 = fmaxf(mx1, fmaxf(sacc[nt][2], sacc[nt][3]));
        }
        #pragma unroll
        for (int o = 1; o <= 2; o <<= 1) {
            mx0 = fmaxf(mx0, __shfl_xor_sync(0xffffffffu, mx0, o));
            mx1 = fmaxf(mx1, __shfl_xor_sync(0xffffffffu, mx1, o));
        }
        float m0n = fmaxf(m0, mx0 * scale);
        float m1n = fmaxf(m1, mx1 * scale);
        float f0 = __expf(m0 - m0n);
        float f1 = __expf(m1 - m1n);
        m0 = m0n; m1 = m1n;

        float s0 = 0.f, s1 = 0.f;
        #pragma unroll
        for (int nt = 0; nt < 8; nt++) {
            float p0 = __expf(sacc[nt][0] * scale - m0n);
            float p1 = __expf(sacc[nt][1] * scale - m0n);
            float p2 = __expf(sacc[nt][2] * scale - m1n);
            float p3 = __expf(sacc[nt][3] * scale - m1n);
            sacc[nt][0] = p0; sacc[nt][1] = p1;
            sacc[nt][2] = p2; sacc[nt][3] = p3;
            s0 += p0 + p1; s1 += p2 + p3;
        }
        #pragma unroll
        for (int o = 1; o <= 2; o <<= 1) {
            s0 += __shfl_xor_sync(0xffffffffu, s0, o);
            s1 += __shfl_xor_sync(0xffffffffu, s1, o);
        }
        l0 = l0 * f0 + s0;
        l1 = l1 * f1 + s1;
        #pragma unroll
        for (int d = 0; d < 8; d++) {
            oacc[d][0] *= f0; oacc[d][1] *= f0;
            oacc[d][2] *= f1; oacc[d][3] *= f1;
        }

        #pragma unroll
        for (int kcp = 0; kcp < 4; kcp++) {
            uint32_t pa_h[4], pa_l[4];
            #pragma unroll
            for (int t = 0; t < 2; t++) {
                int nt = 2 * kcp + t;
                float v0 = sacc[nt][0], v1 = sacc[nt][1];
                float v2 = sacc[nt][2], v3 = sacc[nt][3];
                uint32_t hp0 = pack_bf16(v0, v1);
                uint32_t hp1 = pack_bf16(v2, v3);
                __nv_bfloat162 hb0 = *reinterpret_cast<__nv_bfloat162*>(&hp0);
                __nv_bfloat162 hb1 = *reinterpret_cast<__nv_bfloat162*>(&hp1);
                pa_h[2 * t + 0] = hp0;
                pa_h[2 * t + 1] = hp1;
                pa_l[2 * t + 0] = pack_bf16(v0 - __bfloat162float(hb0.x),
                                            v1 - __bfloat162float(hb0.y));
                pa_l[2 * t + 1] = pack_bf16(v2 - __bfloat162float(hb1.x),
                                            v3 - __bfloat162float(hb1.y));
            }
            #pragma unroll
            for (int dp = 0; dp < 4; dp++) {
                uint32_t vh[4], vl[4];
                uint32_t off = swz((uint32_t)((kcp * 16 + (lane & 15)) * 128)
                                   + (dp * 16 + (lane >> 4) * 8) * 2);
                ldsm_x4t(vh, st + AV_HI + off);
                ldsm_x4t(vl, st + AV_LO + off);
                mma_bf16(oacc[2 * dp + 0], pa_h, vh[0], vh[1]);
                mma_bf16(oacc[2 * dp + 1], pa_h, vh[2], vh[3]);
                mma_bf16(oacc[2 * dp + 0], pa_l, vh[0], vh[1]);
                mma_bf16(oacc[2 * dp + 1], pa_l, vh[2], vh[3]);
                mma_bf16(oacc[2 * dp + 0], pa_h, vl[0], vl[1]);
                mma_bf16(oacc[2 * dp + 1], pa_h, vl[2], vl[3]);
            }
        }
    }

    const float inv0 = 1.f / l0;
    const float inv1 = 1.f / l1;
    #pragma unroll
    for (int dt = 0; dt < 8; dt++) {
        #pragma unroll
        for (int half = 0; half < 2; half++) {
            int r = wid * 16 + (lane >> 2) + half * 8;
            int c = (lane & 3) * 2 + dt * 8;
            float inv = half ? inv1 : inv0;
            float v0 = oacc[dt][2 * half + 0] * inv;
            float v1 = oacc[dt][2 * half + 1] * inv;
            uint32_t hp = pack_bf16(v0, v1);
            __nv_bfloat162 hb = *reinterpret_cast<__nv_bfloat162*>(&hp);
            uint32_t lp = pack_bf16(v0 - __bfloat162float(hb.x),
                                    v1 - __bfloat162float(hb.y));
            *reinterpret_cast<uint32_t*>(asmem + r * AEPIT + c * 2) = hp;
            *reinterpret_cast<uint32_t*>(asmem + AEARR + r * AEPIT + c * 2) = lp;
        }
    }
    __syncthreads();
    #pragma unroll
    for (int it = 0; it < 4; it++) {
        int idx = tid + it * 256;
        int r = idx >> 3, ch = idx & 7;
        uint4 v = *reinterpret_cast<const uint4*>(asmem + r * AEPIT + ch * 16);
        uint4 w = *reinterpret_cast<const uint4*>(asmem + AEARR + r * AEPIT + ch * 16);
        size_t g = (size_t)(b * 128 + r) * 1024 + h * 64 + ch * 8;
        *reinterpret_cast<uint4*>(g_athi + g) = v;
        *reinterpret_cast<uint4*>(g_atlo + g) = w;
    }
}

// ---------------------------------------------------------------------------
// Launch
// ---------------------------------------------------------------------------
extern "C" void kernel_launch(void* const* d_in, const int* in_sizes, int n_in,
                              void* d_out, int out_size)
{
    const float* q   = (const float*)d_in[0];
    const float* kv  = (const float*)d_in[1];
    const float* Wq  = (const float*)d_in[2];
    const float* Wkv = (const float*)d_in[3];
    const float* Wo  = (const float*)d_in[4];
    const float* bo  = (const float*)d_in[5];
    float* out = (float*)d_out;

    cudaFuncSetAttribute(gemm12_kernel,
                         cudaFuncAttributeMaxDynamicSharedMemorySize, GEMM_SMEM);
    cudaFuncSetAttribute(gemm3_kernel,
                         cudaFuncAttributeMaxDynamicSharedMemorySize, GEMM_SMEM);
    cudaFuncSetAttribute(attn_mma_kernel,
                         cudaFuncAttributeMaxDynamicSharedMemorySize, ATT_SMEM);

    // 1) prep: input splits + weight transpose-splits (one launch)
    prep_kernel<<<(3145728 + 1572864) / 256, 256>>>(q, kv, Wq, Wkv, Wo);

    // 2) fused query+kv projections -> bf16 hi/lo
    gemm12_kernel<<<4608, 128, GEMM_SMEM>>>();

    // 3) flash attention (HMMA) -> bf16 hi/lo
    attn_mma_kernel<<<B_ASSETS * NH, 256, ATT_SMEM>>>();

    // 4) out = attn @ Wo + bo (fp32, staged epilogue)
    gemm3_kernel<<<dim3(QD / BN, 8192 / BM), 128, GEMM_SMEM>>>(out, bo);
}

// round 9
// speedup vs baseline: 3.6368x; 1.0427x over previous
#include <cuda_runtime.h>
#include <cuda_bf16.h>
#include <cstdint>
#include <math.h>

// ---------------------------------------------------------------------------
//   q (64,128,512)  kv (64,512,256)  Wq (512,1024)  Wkv (256,2048)
//   Wo (1024,512)  bo (512)  out (64,128,512)
// HMMA everywhere, fp32 via bf16 hi/lo 3-split. GEMMs: 128x128 CTA tile,
// 4 warps x (64x64), 3-stage cp.async. Prep uses smem-tiled transposes.
// ---------------------------------------------------------------------------

#define B_ASSETS 64
#define I_LAT    128
#define J_WIN    512
#define QD       512
#define KVD      256
#define HID      1024
#define NH       16
#define HD       64

// ------------------------- scratch (no cudaMalloc) -------------------------
__device__ __nv_bfloat16  g_qhi  [8192u  * 512u],  g_qlo  [8192u  * 512u];
__device__ __nv_bfloat16  g_kvhi [32768u * 256u],  g_kvlo [32768u * 256u];
__device__ __nv_bfloat16  g_qphi [8192u  * 1024u], g_qplo [8192u  * 1024u];
__device__ __nv_bfloat16  g_kvphi[32768u * 2048u], g_kvplo[32768u * 2048u];
__device__ __nv_bfloat16  g_athi [8192u  * 1024u], g_atlo [8192u  * 1024u];
__device__ __nv_bfloat16  g_wqthi [1024u * 512u],  g_wqtlo [1024u * 512u];
__device__ __nv_bfloat16  g_wkvthi[2048u * 256u],  g_wkvtlo[2048u * 256u];
__device__ __nv_bfloat16  g_wothi [512u * 1024u],  g_wotlo [512u * 1024u];

// ------------------------------ PTX helpers --------------------------------
__device__ __forceinline__ uint32_t smem_u32(const void* p) {
    uint32_t a;
    asm("{ .reg .u64 t; cvta.to.shared.u64 t, %1; cvt.u32.u64 %0, t; }"
        : "=r"(a) : "l"(p));
    return a;
}
__device__ __forceinline__ void cp16(uint32_t dst, const void* src) {
    asm volatile("cp.async.cg.shared.global [%0], [%1], 16;"
                 :: "r"(dst), "l"(src));
}
#define CP_COMMIT() asm volatile("cp.async.commit_group;" ::: "memory")
#define CP_WAIT(n)  asm volatile("cp.async.wait_group %0;" :: "n"(n) : "memory")

__device__ __forceinline__ void ldsm_x4(uint32_t (&r)[4], uint32_t addr) {
    asm volatile("ldmatrix.sync.aligned.m8n8.x4.shared.b16 {%0,%1,%2,%3}, [%4];"
                 : "=r"(r[0]), "=r"(r[1]), "=r"(r[2]), "=r"(r[3]) : "r"(addr));
}
__device__ __forceinline__ void ldsm_x4t(uint32_t (&r)[4], uint32_t addr) {
    asm volatile("ldmatrix.sync.aligned.m8n8.x4.trans.shared.b16 {%0,%1,%2,%3}, [%4];"
                 : "=r"(r[0]), "=r"(r[1]), "=r"(r[2]), "=r"(r[3]) : "r"(addr));
}
__device__ __forceinline__ void mma_bf16(float (&d)[4],
                                         const uint32_t (&a)[4],
                                         uint32_t b0, uint32_t b1) {
    asm volatile(
        "mma.sync.aligned.m16n8k16.row.col.f32.bf16.bf16.f32 "
        "{%0,%1,%2,%3}, {%4,%5,%6,%7}, {%8,%9}, {%0,%1,%2,%3};"
        : "+f"(d[0]), "+f"(d[1]), "+f"(d[2]), "+f"(d[3])
        : "r"(a[0]), "r"(a[1]), "r"(a[2]), "r"(a[3]), "r"(b0), "r"(b1));
}
__device__ __forceinline__ uint32_t pack_bf16(float lo, float hi) {
    __nv_bfloat162 h = __floats2bfloat162_rn(lo, hi);
    return *reinterpret_cast<uint32_t*>(&h);
}
__device__ __forceinline__ uint32_t swz(uint32_t b) {
    return b ^ ((b >> 3) & 0x70);
}

// ---------------------------------------------------------------------------
// GEMM machinery: CTA 128x128 (128 threads, 4 warps, 2x2 of 64x64 tiles),
// BK=32, 3-stage cp.async, swizzled smem.
// ---------------------------------------------------------------------------
#define BM 128
#define BN 128
#define BK 32
#define ARR_B 8192u
#define STG_B 32768u
#define GEMM_SMEM (3 * 32768)
#define EPIT   272u
#define EARR   34816u
#define EPIT32 528u

__device__ __forceinline__ void gemm_mainloop(
    const __nv_bfloat16* __restrict__ Ahi, const __nv_bfloat16* __restrict__ Alo,
    const __nv_bfloat16* __restrict__ Bthi, const __nv_bfloat16* __restrict__ Btlo,
    int K, int m0, int n0, uint32_t sbase, float (&acc)[4][8][4])
{
    const int tid  = threadIdx.x;
    const int wid  = tid >> 5;
    const int lane = tid & 31;
    const int wm = (wid >> 1) * 64;
    const int wn = (wid & 1) * 64;

    auto load_stage = [&](int s, int kbase) {
        uint32_t st = sbase + (uint32_t)s * STG_B;
        #pragma unroll
        for (int it = 0; it < 4; it++) {
            int c   = tid + it * 128;
            int row = c >> 2;
            int ch  = c & 3;
            uint32_t so = st + swz((uint32_t)(row * 64 + ch * 16));
            size_t goa = (size_t)(m0 + row) * K + kbase + ch * 8;
            size_t gob = (size_t)(n0 + row) * K + kbase + ch * 8;
            cp16(so + 0 * ARR_B, Ahi  + goa);
            cp16(so + 1 * ARR_B, Alo  + goa);
            cp16(so + 2 * ARR_B, Bthi + gob);
            cp16(so + 3 * ARR_B, Btlo + gob);
        }
    };

    #pragma unroll
    for (int i = 0; i < 4; i++)
        #pragma unroll
        for (int j = 0; j < 8; j++)
            #pragma unroll
            for (int v = 0; v < 4; v++) acc[i][j][v] = 0.f;

    const int nk = K / BK;
    load_stage(0, 0);
    CP_COMMIT();
    load_stage(1, BK);
    CP_COMMIT();

    const int a_row = lane & 15;
    const int a_k8  = (lane >> 4) * 8;
    const int b_row = (lane & 7) + ((lane >> 4) << 3);
    const int b_k8  = ((lane >> 3) & 1) * 8;

    int s_cur = 0, s_nxt = 2;
    for (int kc = 0; kc < nk; kc++) {
        if (kc < nk - 1) { CP_WAIT(1); } else { CP_WAIT(0); }
        __syncthreads();
        if (kc + 2 < nk) {
            load_stage(s_nxt, (kc + 2) * BK);
            CP_COMMIT();
        }
        const uint32_t stg = sbase + (uint32_t)s_cur * STG_B;

        #pragma unroll
        for (int k16 = 0; k16 < BK; k16 += 16) {
            uint32_t ah[4][4], al[4][4];
            #pragma unroll
            for (int mt = 0; mt < 4; mt++) {
                uint32_t off = swz((uint32_t)((wm + mt * 16 + a_row) * 64)
                                   + (k16 + a_k8) * 2);
                ldsm_x4(ah[mt], stg + off);
                ldsm_x4(al[mt], stg + 1 * ARR_B + off);
            }
            #pragma unroll
            for (int p = 0; p < 4; p++) {
                uint32_t bh[4], bl[4];
                uint32_t off = swz((uint32_t)((wn + p * 16 + b_row) * 64)
                                   + (k16 + b_k8) * 2);
                ldsm_x4(bh, stg + 2 * ARR_B + off);
                ldsm_x4(bl, stg + 3 * ARR_B + off);
                #pragma unroll
                for (int mt = 0; mt < 4; mt++) {
                    mma_bf16(acc[mt][2 * p + 0], ah[mt], bh[0], bh[1]);
                    mma_bf16(acc[mt][2 * p + 1], ah[mt], bh[2], bh[3]);
                }
                #pragma unroll
                for (int mt = 0; mt < 4; mt++) {
                    mma_bf16(acc[mt][2 * p + 0], ah[mt], bl[0], bl[1]);
                    mma_bf16(acc[mt][2 * p + 1], ah[mt], bl[2], bl[3]);
                }
                #pragma unroll
                for (int mt = 0; mt < 4; mt++) {
                    mma_bf16(acc[mt][2 * p + 0], al[mt], bh[0], bh[1]);
                    mma_bf16(acc[mt][2 * p + 1], al[mt], bh[2], bh[3]);
                }
            }
        }
        s_cur = (s_cur + 1 == 3) ? 0 : s_cur + 1;
        s_nxt = (s_nxt + 1 == 3) ? 0 : s_nxt + 1;
    }
}

// ---------------------------------------------------------------------------
// Fused GEMM1 + GEMM2: blocks [0,512) query proj, [512,4608) kv proj.
// ---------------------------------------------------------------------------
__global__ __launch_bounds__(128, 2) void gemm12_kernel()
{
    extern __shared__ __nv_bfloat16 smem[];
    char* smc = reinterpret_cast<char*>(smem);
    const uint32_t sbase = smem_u32(smem);
    const int tid  = threadIdx.x;
    const int wid  = tid >> 5;
    const int lane = tid & 31;

    const int bid = blockIdx.x;
    const bool g1 = bid < 512;
    const __nv_bfloat16* Ahi  = g1 ? g_qhi   : g_kvhi;
    const __nv_bfloat16* Alo  = g1 ? g_qlo   : g_kvlo;
    const __nv_bfloat16* Bthi = g1 ? g_wqthi : g_wkvthi;
    const __nv_bfloat16* Btlo = g1 ? g_wqtlo : g_wkvtlo;
    __nv_bfloat16* Chi = g1 ? g_qphi : g_kvphi;
    __nv_bfloat16* Clo = g1 ? g_qplo : g_kvplo;
    const int K = g1 ? QD : KVD;
    const int N = g1 ? HID : 2 * HID;
    const int nbx = g1 ? 8 : 16;
    const int lb  = g1 ? bid : bid - 512;
    const int m0 = (lb / nbx) * BM;
    const int n0 = (lb % nbx) * BN;

    float acc[4][8][4];
    gemm_mainloop(Ahi, Alo, Bthi, Btlo, K, m0, n0, sbase, acc);

    const int wm = (wid >> 1) * 64;
    const int wn = (wid & 1) * 64;
    const int er = lane >> 2;
    const int ec = (lane & 3) * 2;
    __syncthreads();
    #pragma unroll
    for (int mt = 0; mt < 4; mt++) {
        #pragma unroll
        for (int nt = 0; nt < 8; nt++) {
            #pragma unroll
            for (int half = 0; half < 2; half++) {
                int r = wm + mt * 16 + er + half * 8;
                int c = wn + nt * 8 + ec;
                float v0 = acc[mt][nt][2 * half + 0];
                float v1 = acc[mt][nt][2 * half + 1];
                uint32_t hp = pack_bf16(v0, v1);
                __nv_bfloat162 hb = *reinterpret_cast<__nv_bfloat162*>(&hp);
                uint32_t lp = pack_bf16(v0 - __bfloat162float(hb.x),
                                        v1 - __bfloat162float(hb.y));
                *reinterpret_cast<uint32_t*>(smc + r * EPIT + c * 2) = hp;
                *reinterpret_cast<uint32_t*>(smc + EARR + r * EPIT + c * 2) = lp;
            }
        }
    }
    __syncthreads();
    #pragma unroll
    for (int it = 0; it < 16; it++) {
        int idx = tid + it * 128;
        int r = idx >> 4, ch = idx & 15;
        uint4 v = *reinterpret_cast<const uint4*>(smc + r * EPIT + ch * 16);
        uint4 w = *reinterpret_cast<const uint4*>(smc + EARR + r * EPIT + ch * 16);
        size_t g = (size_t)(m0 + r) * N + n0 + ch * 8;
        *reinterpret_cast<uint4*>(Chi + g) = v;
        *reinterpret_cast<uint4*>(Clo + g) = w;
    }
}

// ---------------------------------------------------------------------------
// GEMM3: out = attn @ Wo + bo (fp32, smem-staged epilogue)
// ---------------------------------------------------------------------------
__global__ __launch_bounds__(128, 2) void gemm3_kernel(
    float* __restrict__ C, const float* __restrict__ bias)
{
    extern __shared__ __nv_bfloat16 smem[];
    char* smc = reinterpret_cast<char*>(smem);
    const uint32_t sbase = smem_u32(smem);
    const int tid  = threadIdx.x;
    const int wid  = tid >> 5;
    const int lane = tid & 31;
    const int m0 = blockIdx.y * BM;
    const int n0 = blockIdx.x * BN;
    const int N = QD;

    float acc[4][8][4];
    gemm_mainloop(g_athi, g_atlo, g_wothi, g_wotlo, HID, m0, n0, sbase, acc);

    const int wm = (wid >> 1) * 64;
    const int wn = (wid & 1) * 64;
    const int er = lane >> 2;
    const int ec = (lane & 3) * 2;
    __syncthreads();
    #pragma unroll
    for (int mt = 0; mt < 4; mt++) {
        #pragma unroll
        for (int nt = 0; nt < 8; nt++) {
            #pragma unroll
            for (int half = 0; half < 2; half++) {
                int r = wm + mt * 16 + er + half * 8;
                int c = wn + nt * 8 + ec;
                float2 v = make_float2(acc[mt][nt][2 * half + 0],
                                       acc[mt][nt][2 * half + 1]);
                *reinterpret_cast<float2*>(smc + r * EPIT32 + c * 4) = v;
            }
        }
    }
    __syncthreads();
    #pragma unroll
    for (int it = 0; it < 32; it++) {
        int idx = tid + it * 128;
        int r = idx >> 5, ch = idx & 31;
        float4 v = *reinterpret_cast<const float4*>(smc + r * EPIT32 + ch * 16);
        float4 bv = *reinterpret_cast<const float4*>(bias + n0 + ch * 4);
        v.x += bv.x; v.y += bv.y; v.z += bv.z; v.w += bv.w;
        *reinterpret_cast<float4*>(C + (size_t)(m0 + r) * N + n0 + ch * 4) = v;
    }
}

// ---------------------------------------------------------------------------
// Prep: blocks [0,12288) = vectorized hi/lo splits of q and kv;
//       blocks [12288,13824) = smem-tiled 32x32 transpose-splits of weights.
// ---------------------------------------------------------------------------
__global__ __launch_bounds__(256) void prep_kernel(
    const float* __restrict__ q,   const float* __restrict__ kv,
    const float* __restrict__ Wq,  const float* __restrict__ Wkv,
    const float* __restrict__ Wo)
{
    const int tid = threadIdx.x;
    if (blockIdx.x < 12288) {
        int i = blockIdx.x * 256 + tid;       // float4 granule id
        const float* src; __nv_bfloat16 *hi, *lo; int base;
        if (i < 1048576) { src = q;  hi = g_qhi;  lo = g_qlo;  base = i; }
        else             { src = kv; hi = g_kvhi; lo = g_kvlo; base = i - 1048576; }
        float4 v = reinterpret_cast<const float4*>(src)[base];
        __nv_bfloat162 hp0 = __floats2bfloat162_rn(v.x, v.y);
        __nv_bfloat162 hp1 = __floats2bfloat162_rn(v.z, v.w);
        __nv_bfloat162 lp0 = __floats2bfloat162_rn(v.x - __bfloat162float(hp0.x),
                                                   v.y - __bfloat162float(hp0.y));
        __nv_bfloat162 lp1 = __floats2bfloat162_rn(v.z - __bfloat162float(hp1.x),
                                                   v.w - __bfloat162float(hp1.y));
        reinterpret_cast<__nv_bfloat162*>(hi)[2 * base + 0] = hp0;
        reinterpret_cast<__nv_bfloat162*>(hi)[2 * base + 1] = hp1;
        reinterpret_cast<__nv_bfloat162*>(lo)[2 * base + 0] = lp0;
        reinterpret_cast<__nv_bfloat162*>(lo)[2 * base + 1] = lp1;
        return;
    }

    // ---- transpose-split: 32x32 tile per block ----
    __shared__ __nv_bfloat16 sh_hi[32][36];
    __shared__ __nv_bfloat16 sh_lo[32][36];

    int bt = blockIdx.x - 12288;              // 0..1535
    const float* W; __nv_bfloat16 *Whi, *Wlo; int K, N, tn_cnt;
    if (bt < 512)       { W = Wq;  Whi = g_wqthi;  Wlo = g_wqtlo;  K = 512;  N = 1024; tn_cnt = 32; }
    else if (bt < 1024) { W = Wkv; Whi = g_wkvthi; Wlo = g_wkvtlo; K = 256;  N = 2048; tn_cnt = 64; bt -= 512; }
    else                { W = Wo;  Whi = g_wothi;  Wlo = g_wotlo;  K = 1024; N = 512;  tn_cnt = 16; bt -= 1024; }
    const int k0 = (bt / tn_cnt) * 32;
    const int n0 = (bt % tn_cnt) * 32;

    // load 32x32 fp32 tile (coalesced float4), split, store transposed to smem
    {
        int r  = tid >> 3;                    // k row within tile
        int c4 = (tid & 7) << 2;              // n col group
        float4 v = *reinterpret_cast<const float4*>(
            W + (size_t)(k0 + r) * N + n0 + c4);
        float vv[4] = { v.x, v.y, v.z, v.w };
        #pragma unroll
        for (int i = 0; i < 4; i++) {
            __nv_bfloat16 h = __float2bfloat16_rn(vv[i]);
            sh_hi[c4 + i][r] = h;
            sh_lo[c4 + i][r] = __float2bfloat16_rn(vv[i] - __bfloat162float(h));
        }
    }
    __syncthreads();

    // write out coalesced: row n, 4 consecutive k per thread (8B stores)
    {
        int nl = tid >> 3;
        int k4 = (tid & 7) << 2;
        uint32_t h0 = pack_bf16(__bfloat162float(sh_hi[nl][k4 + 0]),
                                __bfloat162float(sh_hi[nl][k4 + 1]));
        uint32_t h1 = pack_bf16(__bfloat162float(sh_hi[nl][k4 + 2]),
                                __bfloat162float(sh_hi[nl][k4 + 3]));
        uint32_t l0 = pack_bf16(__bfloat162float(sh_lo[nl][k4 + 0]),
                                __bfloat162float(sh_lo[nl][k4 + 1]));
        uint32_t l1 = pack_bf16(__bfloat162float(sh_lo[nl][k4 + 2]),
                                __bfloat162float(sh_lo[nl][k4 + 3]));
        uint2 ho = make_uint2(h0, h1);
        uint2 lo2 = make_uint2(l0, l1);
        *reinterpret_cast<uint2*>(Whi + (size_t)(n0 + nl) * K + k0 + k4) = ho;
        *reinterpret_cast<uint2*>(Wlo + (size_t)(n0 + nl) * K + k0 + k4) = lo2;
    }
}

// ---------------------------------------------------------------------------
// HMMA flash attention: CTA = (b, h), 8 warps x 16 rows; single barrier
// per jt iteration (wait -> sync -> issue prefetch -> compute).
// ---------------------------------------------------------------------------
#define AQ_HI 0u
#define AQ_LO 16384u
#define ASTG  32768u
#define AST_SZ 32768u
#define AK_HI 0u
#define AK_LO 8192u
#define AV_HI 16384u
#define AV_LO 24576u
#define ATT_SMEM (32768 + 2 * 32768)
#define AEPIT 144u
#define AEARR 18432u

__global__ __launch_bounds__(256, 2) void attn_mma_kernel()
{
    extern __shared__ char asmem[];
    const uint32_t sbase = smem_u32(asmem);
    const int b = blockIdx.x >> 4;
    const int h = blockIdx.x & 15;
    const int tid  = threadIdx.x;
    const int wid  = tid >> 5;
    const int lane = tid & 31;
    const float scale = 0.125f;

    for (int c = tid; c < 1024; c += 256) {
        int row = c >> 3, ch = c & 7;
        uint32_t so = swz((uint32_t)(row * 128 + ch * 16));
        size_t g = (size_t)(b * 128 + row) * 1024 + h * 64 + ch * 8;
        *reinterpret_cast<uint4*>(asmem + AQ_HI + so) =
            *reinterpret_cast<const uint4*>(g_qphi + g);
        *reinterpret_cast<uint4*>(asmem + AQ_LO + so) =
            *reinterpret_cast<const uint4*>(g_qplo + g);
    }

    auto load_kv = [&](int jt, int s) {
        uint32_t st = sbase + ASTG + (uint32_t)s * AST_SZ;
        #pragma unroll
        for (int half = 0; half < 2; half++) {
            int c = tid + half * 256;
            int row = c >> 3, ch = c & 7;
            uint32_t so = swz((uint32_t)(row * 128 + ch * 16));
            size_t kr = (size_t)(b * J_WIN + jt * 64 + row) * 2048 + h * 64 + ch * 8;
            cp16(st + AK_HI + so, g_kvphi + kr);
            cp16(st + AK_LO + so, g_kvplo + kr);
            cp16(st + AV_HI + so, g_kvphi + kr + 1024);
            cp16(st + AV_LO + so, g_kvplo + kr + 1024);
        }
    };

    load_kv(0, 0);
    CP_COMMIT();

    const int a_row = lane & 15;
    const int a_k8  = (lane >> 4) * 8;
    const int b_row = (lane & 7) + ((lane >> 4) << 3);
    const int b_k8  = ((lane >> 3) & 1) * 8;

    __syncthreads();
    uint32_t qah[4][4], qal[4][4];
    #pragma unroll
    for (int kc = 0; kc < 4; kc++) {
        uint32_t off = swz((uint32_t)((wid * 16 + a_row) * 128)
                           + (kc * 16 + a_k8) * 2);
        ldsm_x4(qah[kc], sbase + AQ_HI + off);
        ldsm_x4(qal[kc], sbase + AQ_LO + off);
    }

    float oacc[8][4];
    #pragma unroll
    for (int d = 0; d < 8; d++)
        #pragma unroll
        for (int v = 0; v < 4; v++) oacc[d][v] = 0.f;
    float m0 = -INFINITY, m1 = -INFINITY, l0 = 0.f, l1 = 0.f;

    for (int jt = 0; jt < 8; jt++) {
        CP_WAIT(0);
        __syncthreads();
        if (jt + 1 < 8) {
            load_kv(jt + 1, (jt + 1) & 1);
            CP_COMMIT();
        }
        const uint32_t st = sbase + ASTG + (uint32_t)(jt & 1) * AST_SZ;

        float sacc[8][4];
        #pragma unroll
        for (int p = 0; p < 8; p++)
            #pragma unroll
            for (int v = 0; v < 4; v++) sacc[p][v] = 0.f;

        #pragma unroll
        for (int kc = 0; kc < 4; kc++) {
            #pragma unroll
            for (int p = 0; p < 4; p++) {
                uint32_t bh[4], bl[4];
                uint32_t off = swz((uint32_t)((p * 16 + b_row) * 128)
                                   + (kc * 16 + b_k8) * 2);
                ldsm_x4(bh, st + AK_HI + off);
                ldsm_x4(bl, st + AK_LO + off);
                mma_bf16(sacc[2 * p + 0], qah[kc], bh[0], bh[1]);
                mma_bf16(sacc[2 * p + 1], qah[kc], bh[2], bh[3]);
                mma_bf16(sacc[2 * p + 0], qah[kc], bl[0], bl[1]);
                mma_bf16(sacc[2 * p + 1], qah[kc], bl[2], bl[3]);
                mma_bf16(sacc[2 * p + 0], qal[kc], bh[0], bh[1]);
                mma_bf16(sacc[2 * p + 1], qal[kc], bh[2], bh[3]);
            }
        }

        float mx0 = -INFINITY, mx1 = -INFINITY;
        #pragma unroll
        for (int nt = 0; nt < 8; nt++) {
            mx0 = fmaxf(mx0, fmaxf(sacc[nt][0], sacc[nt][1]));
            mx1 = fmaxf(mx1, fmaxf(sacc[nt][2], sacc[nt][3]));
        }
        #pragma unroll
        for (int o = 1; o <= 2; o <<= 1) {
            mx0 = fmaxf(mx0, __shfl_xor_sync(0xffffffffu, mx0, o));
            mx1 = fmaxf(mx1, __shfl_xor_sync(0xffffffffu, mx1, o));
        }
        float m0n = fmaxf(m0, mx0 * scale);
        float m1n = fmaxf(m1, mx1 * scale);
        float f0 = __expf(m0 - m0n);
        float f1 = __expf(m1 - m1n);
        m0 = m0n; m1 = m1n;

        float s0 = 0.f, s1 = 0.f;
        #pragma unroll
        for (int nt = 0; nt < 8; nt++) {
            float p0 = __expf(sacc[nt][0] * scale - m0n);
            float p1 = __expf(sacc[nt][1] * scale - m0n);
            float p2 = __expf(sacc[nt][2] * scale - m1n);
            float p3 = __expf(sacc[nt][3] * scale - m1n);
            sacc[nt][0] = p0; sacc[nt][1] = p1;
            sacc[nt][2] = p2; sacc[nt][3] = p3;
            s0 += p0 + p1; s1 += p2 + p3;
        }
        #pragma unroll
        for (int o = 1; o <= 2; o <<= 1) {
            s0 += __shfl_xor_sync(0xffffffffu, s0, o);
            s1 += __shfl_xor_sync(0xffffffffu, s1, o);
        }
        l0 = l0 * f0 + s0;
        l1 = l1 * f1 + s1;
        #pragma unroll
        for (int d = 0; d < 8; d++) {
            oacc[d][0] *= f0; oacc[d][1] *= f0;
            oacc[d][2] *= f1; oacc[d][3] *= f1;
        }

        #pragma unroll
        for (int kcp = 0; kcp < 4; kcp++) {
            uint32_t pa_h[4], pa_l[4];
            #pragma unroll
            for (int t = 0; t < 2; t++) {
                int nt = 2 * kcp + t;
                float v0 = sacc[nt][0], v1 = sacc[nt][1];
                float v2 = sacc[nt][2], v3 = sacc[nt][3];
                uint32_t hp0 = pack_bf16(v0, v1);
                uint32_t hp1 = pack_bf16(v2, v3);
                __nv_bfloat162 hb0 = *reinterpret_cast<__nv_bfloat162*>(&hp0);
                __nv_bfloat162 hb1 = *reinterpret_cast<__nv_bfloat162*>(&hp1);
                pa_h[2 * t + 0] = hp0;
                pa_h[2 * t + 1] = hp1;
                pa_l[2 * t + 0] = pack_bf16(v0 - __bfloat162float(hb0.x),
                                            v1 - __bfloat162float(hb0.y));
                pa_l[2 * t + 1] = pack_bf16(v2 - __bfloat162float(hb1.x),
                                            v3 - __bfloat162float(hb1.y));
            }
            #pragma unroll
            for (int dp = 0; dp < 4; dp++) {
                uint32_t vh[4], vl[4];
                uint32_t off = swz((uint32_t)((kcp * 16 + (lane & 15)) * 128)
                                   + (dp * 16 + (lane >> 4) * 8) * 2);
                ldsm_x4t(vh, st + AV_HI + off);
                ldsm_x4t(vl, st + AV_LO + off);
                mma_bf16(oacc[2 * dp + 0], pa_h, vh[0], vh[1]);
                mma_bf16(oacc[2 * dp + 1], pa_h, vh[2], vh[3]);
                mma_bf16(oacc[2 * dp + 0], pa_l, vh[0], vh[1]);
                mma_bf16(oacc[2 * dp + 1], pa_l, vh[2], vh[3]);
                mma_bf16(oacc[2 * dp + 0], pa_h, vl[0], vl[1]);
                mma_bf16(oacc[2 * dp + 1], pa_h, vl[2], vl[3]);
            }
        }
    }

    const float inv0 = 1.f / l0;
    const float inv1 = 1.f / l1;
    __syncthreads();   // all warps done reading stage buffers before reuse
    #pragma unroll
    for (int dt = 0; dt < 8; dt++) {
        #pragma unroll
        for (int half = 0; half < 2; half++) {
            int r = wid * 16 + (lane >> 2) + half * 8;
            int c = (lane & 3) * 2 + dt * 8;
            float inv = half ? inv1 : inv0;
            float v0 = oacc[dt][2 * half + 0] * inv;
            float v1 = oacc[dt][2 * half + 1] * inv;
            uint32_t hp = pack_bf16(v0, v1);
            __nv_bfloat162 hb = *reinterpret_cast<__nv_bfloat162*>(&hp);
            uint32_t lp = pack_bf16(v0 - __bfloat162float(hb.x),
                                    v1 - __bfloat162float(hb.y));
            *reinterpret_cast<uint32_t*>(asmem + r * AEPIT + c * 2) = hp;
            *reinterpret_cast<uint32_t*>(asmem + AEARR + r * AEPIT + c * 2) = lp;
        }
    }
    __syncthreads();
    #pragma unroll
    for (int it = 0; it < 4; it++) {
        int idx = tid + it * 256;
        int r = idx >> 3, ch = idx & 7;
        uint4 v = *reinterpret_cast<const uint4*>(asmem + r * AEPIT + ch * 16);
        uint4 w = *reinterpret_cast<const uint4*>(asmem + AEARR + r * AEPIT + ch * 16);
        size_t g = (size_t)(b * 128 + r) * 1024 + h * 64 + ch * 8;
        *reinterpret_cast<uint4*>(g_athi + g) = v;
        *reinterpret_cast<uint4*>(g_atlo + g) = w;
    }
}

// ---------------------------------------------------------------------------
// Launch
// ---------------------------------------------------------------------------
extern "C" void kernel_launch(void* const* d_in, const int* in_sizes, int n_in,
                              void* d_out, int out_size)
{
    const float* q   = (const float*)d_in[0];
    const float* kv  = (const float*)d_in[1];
    const float* Wq  = (const float*)d_in[2];
    const float* Wkv = (const float*)d_in[3];
    const float* Wo  = (const float*)d_in[4];
    const float* bo  = (const float*)d_in[5];
    float* out = (float*)d_out;

    cudaFuncSetAttribute(gemm12_kernel,
                         cudaFuncAttributeMaxDynamicSharedMemorySize, GEMM_SMEM);
    cudaFuncSetAttribute(gemm3_kernel,
                         cudaFuncAttributeMaxDynamicSharedMemorySize, GEMM_SMEM);
    cudaFuncSetAttribute(attn_mma_kernel,
                         cudaFuncAttributeMaxDynamicSharedMemorySize, ATT_SMEM);

    // 1) prep: splits (12288 blocks) + tiled transpose-splits (1536 blocks)
    prep_kernel<<<13824, 256>>>(q, kv, Wq, Wkv, Wo);

    // 2) fused query+kv projections -> bf16 hi/lo
    gemm12_kernel<<<4608, 128, GEMM_SMEM>>>();

    // 3) flash attention (HMMA) -> bf16 hi/lo
    attn_mma_kernel<<<B_ASSETS * NH, 256, ATT_SMEM>>>();

    // 4) out = attn @ Wo + bo (fp32, staged epilogue)
    gemm3_kernel<<<dim3(QD / BN, 8192 / BM), 128, GEMM_SMEM>>>(out, bo);
}